// round 4
// baseline (speedup 1.0000x reference)
#include <cuda_runtime.h>
#include <math.h>
#include <stdint.h>

#define Bsz 32
#define Tlen 128
#define Hdim 1024
#define Vsz 32000
#define NB 128
#define NT 256

// ---------------- device scratch (no allocations allowed) ----------------
__device__ float g_XT[Tlen * Hdim * Bsz];        // [t][k][b] 16.8 MB
__device__ float g_h1a[Hdim * Bsz], g_h1b[Hdim * Bsz];
__device__ float g_h2a[Hdim * Bsz], g_h2b[Hdim * Bsz];
__device__ float g_c1[Hdim * Bsz],  g_c2[Hdim * Bsz];
__device__ float g_x2[Hdim * Bsz];
__device__ float g_P[4 * Hdim * Bsz];            // mogrify partials [ky][j][b]
__device__ int g_ticket[32];
__device__ unsigned g_bar_count;
__device__ volatile unsigned g_bar_sense;

// ---------------- grid-wide barrier (sense reversing, replay-safe) ----------------
__device__ __forceinline__ void grid_barrier(unsigned& sense) {
    __threadfence();          // release: prior stores visible gpu-wide (+L1 inval)
    __syncthreads();
    if (threadIdx.x == 0) {
        unsigned s = sense ^ 1u;
        if (atomicAdd(&g_bar_count, 1u) == NB - 1u) {
            g_bar_count = 0u;
            __threadfence();
            g_bar_sense = s;
        } else {
            while (g_bar_sense != s) __nanosleep(32);
        }
    }
    __syncthreads();
    __threadfence();          // acquire: invalidate L1 so post-barrier loads fresh
    sense ^= 1u;
}

// ---------------- inner MAC over a 256-k chunk ----------------
// warp layout: kh = half of 128 k within chunk half, bg = 8-batch group, lane = j row
__device__ __forceinline__ void chunk_mac(
    const float* __restrict__ S, int kbase, int kh, int bg, int lane,
    float (*WsT)[33], float acc[8])
{
    const float* Sb = S + (size_t)(kbase + kh * 128) * Bsz + bg * 8;
#pragma unroll 16
    for (int kk = 0; kk < 128; kk++) {
        float wv = WsT[kh * 128 + kk][lane];
        const float4* xp = (const float4*)(Sb + (size_t)kk * Bsz);
        float4 xa = xp[0];
        float4 xb = xp[1];
        acc[0] = fmaf(wv, xa.x, acc[0]);
        acc[1] = fmaf(wv, xa.y, acc[1]);
        acc[2] = fmaf(wv, xa.z, acc[2]);
        acc[3] = fmaf(wv, xa.w, acc[3]);
        acc[4] = fmaf(wv, xb.x, acc[4]);
        acc[5] = fmaf(wv, xb.y, acc[5]);
        acc[6] = fmaf(wv, xb.z, acc[6]);
        acc[7] = fmaf(wv, xb.w, acc[7]);
    }
}

// ---------------- one mogrify stage: dst *= 2*sigmoid(W @ src + bias) ----------------
__device__ void mog_stage(const float* __restrict__ Wm, const float* __restrict__ bias,
                          const float* __restrict__ src, float* __restrict__ dst,
                          int mog_epoch, float (*WsT)[33], float (*Red)[33],
                          unsigned& sense)
{
    int tid = threadIdx.x, lane = tid & 31, w = tid >> 5;
    int kh = w >> 2, bg = w & 3;
    int jg = blockIdx.x >> 2, ky = blockIdx.x & 3;
    int j0 = jg * 32, kb = ky * 256;

    float acc[8];
#pragma unroll
    for (int i = 0; i < 8; i++) acc[i] = 0.f;

    // stage W tile 32 rows x 256 k, transposed (coalesced loads)
#pragma unroll
    for (int it = 0; it < 32; it++) {
        int idx = tid + it * NT;
        int jl = idx >> 8, kl = idx & 255;
        WsT[kl][jl] = Wm[(size_t)(j0 + jl) * Hdim + kb + kl];
    }
    __syncthreads();
    chunk_mac(src, kb, kh, bg, lane, WsT, acc);

    // kh reduction
    __syncthreads();
    if (kh == 1) {
#pragma unroll
        for (int i = 0; i < 8; i++) Red[lane][bg * 8 + i] = acc[i];
    }
    __syncthreads();
    if (kh == 0) {
#pragma unroll
        for (int i = 0; i < 8; i++) acc[i] += Red[lane][bg * 8 + i];
        float4* pp = (float4*)(g_P + (size_t)ky * Hdim * Bsz +
                               (size_t)(j0 + lane) * Bsz + bg * 8);
        pp[0] = make_float4(acc[0], acc[1], acc[2], acc[3]);
        pp[1] = make_float4(acc[4], acc[5], acc[6], acc[7]);
    }

    // 4-block sub-barrier among the k-slices of this j-group (epoch ticket)
    __threadfence();
    __syncthreads();
    if (tid == 0) {
        atomicAdd(&g_ticket[jg], 1);
        int target = 4 * mog_epoch;
        while (*(volatile int*)&g_ticket[jg] < target) __nanosleep(32);
    }
    __syncthreads();
    __threadfence();

    // distributed finalize: this block owns rows e = ky*8 .. ky*8+7
    {
        int e = ky * 8 + (tid >> 5);
        int b = lane;
        int j = j0 + e;
        size_t o = (size_t)j * Bsz + b;
        const size_t S = (size_t)Hdim * Bsz;
        float s = g_P[o] + g_P[S + o] + g_P[2 * S + o] + g_P[3 * S + o] + bias[j];
        dst[o] *= 2.f / (1.f + expf(-s));
    }
    grid_barrier(sense);
}

// ---------------- one LSTM gate stage (full-K per block, fused pointwise) ----------------
// block owns 8 hidden units (all 4 gate rows each): rows r = gate*H + j0u + u
__device__ void gate_stage(const float* __restrict__ Wih, const float* __restrict__ Whh,
                           const float* __restrict__ bih, const float* __restrict__ bhh,
                           const float* __restrict__ xsrc, const float* __restrict__ hsrc,
                           float* __restrict__ cSt, float* __restrict__ hDst,
                           float* __restrict__ x2copy, float* __restrict__ hidOut, int t,
                           float (*WsT)[33], float (*Red)[33], unsigned& sense)
{
    int tid = threadIdx.x, lane = tid & 31, w = tid >> 5;
    int kh = w >> 2, bg = w & 3;
    int j0u = blockIdx.x * 8;

    float acc[8];
#pragma unroll
    for (int i = 0; i < 8; i++) acc[i] = 0.f;

    for (int mat = 0; mat < 2; mat++) {
        const float* Wm = mat ? Whh : Wih;
        const float* S  = mat ? hsrc : xsrc;
        for (int c = 0; c < 4; c++) {
            __syncthreads();
#pragma unroll
            for (int it = 0; it < 32; it++) {
                int idx = tid + it * NT;
                int jl = idx >> 8, kl = idx & 255;
                int row = (jl >> 3) * Hdim + j0u + (jl & 7);
                WsT[kl][jl] = Wm[(size_t)row * Hdim + c * 256 + kl];
            }
            __syncthreads();
            chunk_mac(S, c * 256, kh, bg, lane, WsT, acc);
        }
    }

    // kh reduction into Red[row 0..31][b 0..31]
    __syncthreads();
    if (kh == 1) {
#pragma unroll
        for (int i = 0; i < 8; i++) Red[lane][bg * 8 + i] = acc[i];
    }
    __syncthreads();
    if (kh == 0) {
#pragma unroll
        for (int i = 0; i < 8; i++) Red[lane][bg * 8 + i] += acc[i];
    }
    __syncthreads();

    // fused LSTM pointwise: thread -> (unit u, batch b)
    {
        int u = tid >> 5, b = lane;
        int j = j0u + u;
        float gi = Red[u][b]      + bih[j]            + bhh[j];
        float gf = Red[8 + u][b]  + bih[Hdim + j]     + bhh[Hdim + j];
        float gg = Red[16 + u][b] + bih[2 * Hdim + j] + bhh[2 * Hdim + j];
        float go = Red[24 + u][b] + bih[3 * Hdim + j] + bhh[3 * Hdim + j];

        float si = 1.f / (1.f + expf(-gi));
        float sf = 1.f / (1.f + expf(-gf));
        float tg = tanhf(gg);
        float so = 1.f / (1.f + expf(-go));

        size_t g = (size_t)j * Bsz + b;
        float c = sf * cSt[g] + si * tg;   // cSt owned by this block only
        float h = so * tanhf(c);
        cSt[g] = c;
        hDst[g] = h;                        // ping-pong buffer: no read race
        if (x2copy) x2copy[g] = h;
        if (hidOut) hidOut[(size_t)b * Tlen * Hdim + (size_t)t * Hdim + j] = h;
    }
    grid_barrier(sense);
}

// ---------------- the persistent recurrence kernel ----------------
__global__ __launch_bounds__(NT, 1) void mog_lstm_kernel(
    const int* __restrict__ seq, const float* __restrict__ emb,
    const float* __restrict__ m1w, const float* __restrict__ m1b,
    const float* __restrict__ w1ih, const float* __restrict__ w1hh,
    const float* __restrict__ b1ih, const float* __restrict__ b1hh,
    const float* __restrict__ m2w, const float* __restrict__ m2b,
    const float* __restrict__ w2ih, const float* __restrict__ w2hh,
    const float* __restrict__ b2ih, const float* __restrict__ b2hh,
    float* __restrict__ hidp)
{
    __shared__ float WsT[256][33];
    __shared__ float Red[32][33];

    int tid = threadIdx.x;
    int bid = blockIdx.x;
    unsigned sense = 0;

    // init: zero states (128*256 == 32768 == Hdim*Bsz)
    {
        int g = bid * NT + tid;
        g_h1a[g] = 0.f; g_h1b[g] = 0.f; g_h2a[g] = 0.f; g_h2b[g] = 0.f;
        g_c1[g] = 0.f;  g_c2[g] = 0.f;
    }
    // embedding gather: block handles t = bid; XT[t][k][b] = emb[seq[b][t]][k]
    {
        int t = bid;
        for (int idx = tid; idx < Hdim * Bsz; idx += NT) {
            int b = idx >> 10;
            int k = idx & 1023;
            int id = seq[b * Tlen + t];
            g_XT[(size_t)t * Hdim * Bsz + (size_t)k * Bsz + b] =
                emb[(size_t)id * Hdim + k];
        }
    }
    grid_barrier(sense);

    int mog_epoch = 0;
    for (int t = 0; t < Tlen; t++) {
        float* xt  = g_XT + (size_t)t * Hdim * Bsz;
        float* h1s = (t & 1) ? g_h1b : g_h1a;   // state in, mogrified in place
        float* h1d = (t & 1) ? g_h1a : g_h1b;   // gate output
        float* h2s = (t & 1) ? g_h2b : g_h2a;
        float* h2d = (t & 1) ? g_h2a : g_h2b;

        // cell 1 mogrify: i even -> x <- f(h)*x ; i odd -> h <- f(x)*h
        for (int i = 0; i < 5; i++) {
            mog_epoch++;
            const float* src = (i & 1) ? (const float*)xt : (const float*)h1s;
            float* dst = (i & 1) ? h1s : xt;
            mog_stage(m1w + (size_t)i * Hdim * Hdim, m1b + i * Hdim,
                      src, dst, mog_epoch, WsT, Red, sense);
        }
        gate_stage(w1ih, w1hh, b1ih, b1hh, xt, h1s, g_c1, h1d,
                   g_x2, nullptr, t, WsT, Red, sense);

        // cell 2 mogrify on x2 (copy of new h1) and h2
        for (int i = 0; i < 5; i++) {
            mog_epoch++;
            const float* src = (i & 1) ? (const float*)g_x2 : (const float*)h2s;
            float* dst = (i & 1) ? h2s : g_x2;
            mog_stage(m2w + (size_t)i * Hdim * Hdim, m2b + i * Hdim,
                      src, dst, mog_epoch, WsT, Red, sense);
        }
        gate_stage(w2ih, w2hh, b2ih, b2hh, g_x2, h2s, g_c2, h2d,
                   nullptr, hidp, t, WsT, Red, sense);
    }
    grid_barrier(sense);   // total barrier count = 1538 (even -> sense restored)

    // restore tickets for next graph replay
    if (bid < 32 && tid == 0) g_ticket[bid] = 0;
}

// ---------------- logits sgemm: C[m][n] = sum_k A[m][k]*Bm[n][k] + bias[n] ----------------
__global__ __launch_bounds__(256, 2) void sgemm_nt_bias(
    const float* __restrict__ A, const float* __restrict__ Bm,
    const float* __restrict__ bias, float* __restrict__ C)
{
    const int K = Hdim, N = Vsz;
    __shared__ float As[8][132];
    __shared__ float Bs[8][132];

    int m0 = blockIdx.x * 128;
    int n0 = blockIdx.y * 128;
    int tid = threadIdx.x;
    int tx = tid & 15;
    int ty = tid >> 4;

    float acc[8][8];
#pragma unroll
    for (int i = 0; i < 8; i++)
#pragma unroll
        for (int jn = 0; jn < 8; jn++) acc[i][jn] = 0.f;

    int lrow = tid >> 1;
    int lk4  = (tid & 1) * 4;
    const float* Ap = A  + (size_t)(m0 + lrow) * K + lk4;
    const float* Bp = Bm + (size_t)(n0 + lrow) * K + lk4;

    float4 a4 = *(const float4*)(Ap);
    float4 b4 = *(const float4*)(Bp);

    for (int k0 = 0; k0 < K; k0 += 8) {
        __syncthreads();
        As[lk4 + 0][lrow] = a4.x; As[lk4 + 1][lrow] = a4.y;
        As[lk4 + 2][lrow] = a4.z; As[lk4 + 3][lrow] = a4.w;
        Bs[lk4 + 0][lrow] = b4.x; Bs[lk4 + 1][lrow] = b4.y;
        Bs[lk4 + 2][lrow] = b4.z; Bs[lk4 + 3][lrow] = b4.w;
        __syncthreads();
        if (k0 + 8 < K) {
            a4 = *(const float4*)(Ap + k0 + 8);
            b4 = *(const float4*)(Bp + k0 + 8);
        }
#pragma unroll
        for (int kk = 0; kk < 8; kk++) {
            float4 a0  = *(const float4*)&As[kk][ty * 8];
            float4 a1  = *(const float4*)&As[kk][ty * 8 + 4];
            float4 bb0 = *(const float4*)&Bs[kk][tx * 8];
            float4 bb1 = *(const float4*)&Bs[kk][tx * 8 + 4];
            float av[8] = {a0.x, a0.y, a0.z, a0.w, a1.x, a1.y, a1.z, a1.w};
            float bv[8] = {bb0.x, bb0.y, bb0.z, bb0.w, bb1.x, bb1.y, bb1.z, bb1.w};
#pragma unroll
            for (int i = 0; i < 8; i++)
#pragma unroll
                for (int jn = 0; jn < 8; jn++)
                    acc[i][jn] = fmaf(av[i], bv[jn], acc[i][jn]);
        }
    }

    float bv[8];
#pragma unroll
    for (int jn = 0; jn < 8; jn++) bv[jn] = bias[n0 + tx * 8 + jn];
#pragma unroll
    for (int i = 0; i < 8; i++) {
        size_t m = (size_t)(m0 + ty * 8 + i);
        float* cp = C + m * N + n0 + tx * 8;
        *(float4*)(cp)     = make_float4(acc[i][0] + bv[0], acc[i][1] + bv[1],
                                         acc[i][2] + bv[2], acc[i][3] + bv[3]);
        *(float4*)(cp + 4) = make_float4(acc[i][4] + bv[4], acc[i][5] + bv[5],
                                         acc[i][6] + bv[6], acc[i][7] + bv[7]);
    }
}

// ---------------- host ----------------
extern "C" void kernel_launch(void* const* d_in, const int* in_sizes, int n_in,
                              void* d_out, int out_size) {
    (void)in_sizes; (void)out_size;
    const int* seq = (const int*)d_in[0];
    int o = n_in - 14;  // emb index (handles optional max_len scalar input)
    const float* emb  = (const float*)d_in[o + 0];
    const float* fc_b = (const float*)d_in[o + 1];
    const float* m1w  = (const float*)d_in[o + 2];
    const float* m1b  = (const float*)d_in[o + 3];
    const float* w1ih = (const float*)d_in[o + 4];
    const float* w1hh = (const float*)d_in[o + 5];
    const float* b1ih = (const float*)d_in[o + 6];
    const float* b1hh = (const float*)d_in[o + 7];
    const float* m2w  = (const float*)d_in[o + 8];
    const float* m2b  = (const float*)d_in[o + 9];
    const float* w2ih = (const float*)d_in[o + 10];
    const float* w2hh = (const float*)d_in[o + 11];
    const float* b2ih = (const float*)d_in[o + 12];
    const float* b2hh = (const float*)d_in[o + 13];

    float* outp = (float*)d_out;                          // [B][T][V]
    float* hidp = outp + (size_t)Bsz * Tlen * Vsz;        // [B][T][H]

    mog_lstm_kernel<<<NB, NT>>>(seq, emb,
                                m1w, m1b, w1ih, w1hh, b1ih, b1hh,
                                m2w, m2b, w2ih, w2hh, b2ih, b2hh,
                                hidp);

    sgemm_nt_bias<<<dim3((Bsz * Tlen) / 128, Vsz / 128), 256>>>(hidp, emb, fc_b, outp);
}

// round 5
// speedup vs baseline: 1.4438x; 1.4438x over previous
#include <cuda_runtime.h>
#include <math.h>
#include <stdint.h>

#define Bsz 32
#define Tlen 128
#define Hdim 1024
#define Vsz 32000
#define NB 128
#define NT 512

// dynamic smem layout (floats)
#define WS_STRIDE 36
#define OFF_WS 0
#define OFF_XS (256 * 36)                 // 9216
#define OFF_P  (OFF_XS + 256 * 32)        // 17408
#define OFF_RED (OFF_P + 16 * 32 * 32)    // 33792
#define SMEM_FLOATS (OFF_RED + 32 * 32)   // 34816
#define SMEM_BYTES (SMEM_FLOATS * 4)      // 139264

// ---------------- device scratch ----------------
__device__ float g_XT[Tlen * Hdim * Bsz];        // [t][k][b]
__device__ float g_h1a[Hdim * Bsz], g_h1b[Hdim * Bsz];
__device__ float g_h2a[Hdim * Bsz], g_h2b[Hdim * Bsz];
__device__ float g_c1[Hdim * Bsz],  g_c2[Hdim * Bsz];
__device__ float g_x2[Hdim * Bsz];
__device__ float g_P[4 * Hdim * Bsz];            // mogrify cross-block partials
__device__ int g_ticket[32];
__device__ unsigned g_bar_count;
__device__ volatile unsigned g_bar_sense;

// ---------------- grid-wide barrier (sense reversing, replay-safe) ----------------
__device__ __forceinline__ void grid_barrier(unsigned& sense) {
    __threadfence();
    __syncthreads();
    if (threadIdx.x == 0) {
        unsigned s = sense ^ 1u;
        if (atomicAdd(&g_bar_count, 1u) == NB - 1u) {
            g_bar_count = 0u;
            __threadfence();
            g_bar_sense = s;
        } else {
            while (g_bar_sense != s) __nanosleep(32);
        }
    }
    __syncthreads();
    __threadfence();
    sense ^= 1u;
}

// ---------------- 16-k MAC: thread computes 4j x 8b ----------------
__device__ __forceinline__ void mac16(const float* __restrict__ WsT,
                                      const float* __restrict__ Xs,
                                      int ks, int jq, int bg, float acc[4][8])
{
#pragma unroll 4
    for (int kk = 0; kk < 16; kk++) {
        int k = ks + kk;
        float4 w4 = *(const float4*)&WsT[k * WS_STRIDE + jq * 4];
        float4 xa = *(const float4*)&Xs[k * 32 + bg * 8];
        float4 xb = *(const float4*)&Xs[k * 32 + bg * 8 + 4];
        float wv[4] = {w4.x, w4.y, w4.z, w4.w};
        float xv[8] = {xa.x, xa.y, xa.z, xa.w, xb.x, xb.y, xb.z, xb.w};
#pragma unroll
        for (int a = 0; a < 4; a++)
#pragma unroll
            for (int b = 0; b < 8; b++)
                acc[a][b] = fmaf(wv[a], xv[b], acc[a][b]);
    }
}

// ---------------- one mogrify stage: dst *= 2*sigmoid(W @ src + bias) ----------------
// block = (j-group of 32 rows) x (k-slice of 256), 32x4 = 128 blocks
__device__ void mog_stage(const float* __restrict__ Wm, const float* __restrict__ bias,
                          const float* __restrict__ src, float* __restrict__ dst,
                          int mog_epoch, float* sm, unsigned& sense)
{
    float* WsT = sm + OFF_WS;
    float* Xs  = sm + OFF_XS;
    float* P   = sm + OFF_P;

    int tid = threadIdx.x, lane = tid & 31, wid = tid >> 5;
    int jq = lane >> 2, bg = lane & 3;
    int jgrp = blockIdx.x >> 2, ky = blockIdx.x & 3;
    int j0 = jgrp * 32, kb = ky * 256;

    // stage W tile 32j x 256k, transposed (STS.128 along j -> conflict-free)
#pragma unroll
    for (int i = 0; i < 4; i++) {
        int idx = tid + i * NT;           // 0..2047
        int k = idx & 255, j4 = idx >> 8; // j4: 0..7
        const float* wr = Wm + (size_t)(j0 + j4 * 4) * Hdim + kb + k;
        float4 v;
        v.x = wr[0];
        v.y = wr[Hdim];
        v.z = wr[2 * Hdim];
        v.w = wr[3 * Hdim];
        *(float4*)&WsT[k * WS_STRIDE + j4 * 4] = v;
    }
    // stage X chunk 256k x 32b
#pragma unroll
    for (int i = 0; i < 4; i++) {
        int idx = tid + i * NT;           // float4 cells
        int k = idx >> 3, b4 = idx & 7;
        *(float4*)&Xs[k * 32 + b4 * 4] =
            *(const float4*)&src[(size_t)(kb + k) * Bsz + b4 * 4];
    }
    __syncthreads();

    float acc[4][8];
#pragma unroll
    for (int a = 0; a < 4; a++)
#pragma unroll
        for (int b = 0; b < 8; b++) acc[a][b] = 0.f;

    mac16(WsT, Xs, wid * 16, jq, bg, acc);

    // write per-warp partials
#pragma unroll
    for (int jj = 0; jj < 4; jj++) {
        float* pp = &P[wid * 1024 + (jq * 4 + jj) * 32 + bg * 8];
        *(float4*)pp       = make_float4(acc[jj][0], acc[jj][1], acc[jj][2], acc[jj][3]);
        *(float4*)(pp + 4) = make_float4(acc[jj][4], acc[jj][5], acc[jj][6], acc[jj][7]);
    }
    __syncthreads();

    // 16-warp reduce -> g_P[ky]
#pragma unroll
    for (int i = 0; i < 2; i++) {
        int cell = tid + i * NT;          // 0..1023
        float s = 0.f;
#pragma unroll
        for (int w = 0; w < 16; w++) s += P[w * 1024 + cell];
        g_P[(size_t)ky * (Hdim * Bsz) + (size_t)(j0 + (cell >> 5)) * Bsz + (cell & 31)] = s;
    }

    // 4-block sub-barrier among the k-slices of this j-group
    __threadfence();
    __syncthreads();
    if (tid == 0) {
        atomicAdd(&g_ticket[jgrp], 1);
        int target = 4 * mog_epoch;
        while (*(volatile int*)&g_ticket[jgrp] < target) __nanosleep(32);
    }
    __syncthreads();
    __threadfence();

    // distributed finalize: this block owns rows e = ky*8 .. ky*8+7
    if (tid < 256) {
        int e = ky * 8 + (tid >> 5);
        int b = tid & 31;
        int j = j0 + e;
        size_t o = (size_t)j * Bsz + b;
        const size_t S = (size_t)Hdim * Bsz;
        float s = g_P[o] + g_P[S + o] + g_P[2 * S + o] + g_P[3 * S + o] + bias[j];
        dst[o] *= 2.f / (1.f + __expf(-s));
    }
    grid_barrier(sense);
}

// ---------------- LSTM gate stage: block owns 8 units x 4 gates, full K ----------------
__device__ void gate_stage(const float* __restrict__ Wih, const float* __restrict__ Whh,
                           const float* __restrict__ bih, const float* __restrict__ bhh,
                           const float* __restrict__ xsrc, const float* __restrict__ hsrc,
                           float* __restrict__ cSt, float* __restrict__ hDst,
                           float* __restrict__ x2copy, float* __restrict__ hidOut, int t,
                           float* sm, unsigned& sense)
{
    float* WsT = sm + OFF_WS;
    float* Xs  = sm + OFF_XS;
    float* P   = sm + OFF_P;
    float* Red = sm + OFF_RED;

    int tid = threadIdx.x, lane = tid & 31, wid = tid >> 5;
    int jq = lane >> 2, bg = lane & 3;
    int j0u = blockIdx.x * 8;

    float acc[4][8];
#pragma unroll
    for (int a = 0; a < 4; a++)
#pragma unroll
        for (int b = 0; b < 8; b++) acc[a][b] = 0.f;

    for (int c = 0; c < 8; c++) {
        const float* Wm = (c < 4) ? Wih : Whh;
        const float* S  = (c < 4) ? xsrc : hsrc;
        int cbase = (c & 3) * 256;
        __syncthreads();   // previous chunk reads done before restage
#pragma unroll
        for (int i = 0; i < 4; i++) {
            int idx = tid + i * NT;
            int k = idx & 255, j4 = idx >> 8;    // row' = j4*4+cc: gate=row'>>3, u=row'&7
            float4 v;
            {
                int r0 = j4 * 4;
                v.x = Wm[(size_t)((r0 >> 3) * Hdim + j0u + (r0 & 7)) * Hdim + cbase + k];
                int r1 = j4 * 4 + 1;
                v.y = Wm[(size_t)((r1 >> 3) * Hdim + j0u + (r1 & 7)) * Hdim + cbase + k];
                int r2 = j4 * 4 + 2;
                v.z = Wm[(size_t)((r2 >> 3) * Hdim + j0u + (r2 & 7)) * Hdim + cbase + k];
                int r3 = j4 * 4 + 3;
                v.w = Wm[(size_t)((r3 >> 3) * Hdim + j0u + (r3 & 7)) * Hdim + cbase + k];
            }
            *(float4*)&WsT[k * WS_STRIDE + j4 * 4] = v;
        }
#pragma unroll
        for (int i = 0; i < 4; i++) {
            int idx = tid + i * NT;
            int k = idx >> 3, b4 = idx & 7;
            *(float4*)&Xs[k * 32 + b4 * 4] =
                *(const float4*)&S[(size_t)(cbase + k) * Bsz + b4 * 4];
        }
        __syncthreads();
        mac16(WsT, Xs, wid * 16, jq, bg, acc);
    }

    // per-warp partials
#pragma unroll
    for (int jj = 0; jj < 4; jj++) {
        float* pp = &P[wid * 1024 + (jq * 4 + jj) * 32 + bg * 8];
        *(float4*)pp       = make_float4(acc[jj][0], acc[jj][1], acc[jj][2], acc[jj][3]);
        *(float4*)(pp + 4) = make_float4(acc[jj][4], acc[jj][5], acc[jj][6], acc[jj][7]);
    }
    __syncthreads();
#pragma unroll
    for (int i = 0; i < 2; i++) {
        int cell = tid + i * NT;
        float s = 0.f;
#pragma unroll
        for (int w = 0; w < 16; w++) s += P[w * 1024 + cell];
        Red[cell] = s;
    }
    __syncthreads();

    // fused LSTM pointwise: (u, b) for 8 units
    if (tid < 256) {
        int u = tid >> 5, b = tid & 31;
        int j = j0u + u;
        float gi = Red[(u) * 32 + b]      + bih[j]            + bhh[j];
        float gf = Red[(8 + u) * 32 + b]  + bih[Hdim + j]     + bhh[Hdim + j];
        float gg = Red[(16 + u) * 32 + b] + bih[2 * Hdim + j] + bhh[2 * Hdim + j];
        float go = Red[(24 + u) * 32 + b] + bih[3 * Hdim + j] + bhh[3 * Hdim + j];

        float si = 1.f / (1.f + __expf(-gi));
        float sf = 1.f / (1.f + __expf(-gf));
        float tg = tanhf(gg);
        float so = 1.f / (1.f + __expf(-go));

        size_t g = (size_t)j * Bsz + b;
        float cc = sf * cSt[g] + si * tg;
        float h = so * tanhf(cc);
        cSt[g] = cc;
        hDst[g] = h;
        if (x2copy) x2copy[g] = h;
        if (hidOut) hidOut[(size_t)b * Tlen * Hdim + (size_t)t * Hdim + j] = h;
    }
    grid_barrier(sense);
}

// ---------------- persistent recurrence kernel ----------------
__global__ __launch_bounds__(NT, 1) void mog_lstm_kernel(
    const int* __restrict__ seq, const float* __restrict__ emb,
    const float* __restrict__ m1w, const float* __restrict__ m1b,
    const float* __restrict__ w1ih, const float* __restrict__ w1hh,
    const float* __restrict__ b1ih, const float* __restrict__ b1hh,
    const float* __restrict__ m2w, const float* __restrict__ m2b,
    const float* __restrict__ w2ih, const float* __restrict__ w2hh,
    const float* __restrict__ b2ih, const float* __restrict__ b2hh,
    float* __restrict__ hidp)
{
    extern __shared__ float sm[];
    int tid = threadIdx.x;
    int bid = blockIdx.x;
    unsigned sense = 0;

    // zero states: 128 blocks x 512 = 65536 slots for 32768 elems -> stride
    for (int g = bid * NT + tid; g < Hdim * Bsz; g += NB * NT) {
        g_h1a[g] = 0.f; g_h1b[g] = 0.f; g_h2a[g] = 0.f; g_h2b[g] = 0.f;
        g_c1[g] = 0.f;  g_c2[g] = 0.f;
    }
    // embedding gather: block t = bid
    {
        int t = bid;
        for (int idx = tid; idx < Hdim * Bsz; idx += NT) {
            int b = idx & 31;
            int k = idx >> 5;
            int id = seq[b * Tlen + t];
            sm[0] = 0.f; // no-op touch to keep smem live (not required)
            g_XT[(size_t)t * Hdim * Bsz + (size_t)k * Bsz + b] =
                emb[(size_t)id * Hdim + k];
        }
    }
    grid_barrier(sense);

    int mog_epoch = 0;
    for (int t = 0; t < Tlen; t++) {
        float* xt  = g_XT + (size_t)t * Hdim * Bsz;
        float* h1s = (t & 1) ? g_h1b : g_h1a;
        float* h1d = (t & 1) ? g_h1a : g_h1b;
        float* h2s = (t & 1) ? g_h2b : g_h2a;
        float* h2d = (t & 1) ? g_h2a : g_h2b;

        for (int i = 0; i < 5; i++) {
            mog_epoch++;
            const float* src = (i & 1) ? (const float*)xt : (const float*)h1s;
            float* dst = (i & 1) ? h1s : xt;
            mog_stage(m1w + (size_t)i * Hdim * Hdim, m1b + i * Hdim,
                      src, dst, mog_epoch, sm, sense);
        }
        gate_stage(w1ih, w1hh, b1ih, b1hh, xt, h1s, g_c1, h1d,
                   g_x2, nullptr, t, sm, sense);

        for (int i = 0; i < 5; i++) {
            mog_epoch++;
            const float* src = (i & 1) ? (const float*)g_x2 : (const float*)h2s;
            float* dst = (i & 1) ? h2s : g_x2;
            mog_stage(m2w + (size_t)i * Hdim * Hdim, m2b + i * Hdim,
                      src, dst, mog_epoch, sm, sense);
        }
        gate_stage(w2ih, w2hh, b2ih, b2hh, g_x2, h2s, g_c2, h2d,
                   nullptr, hidp, t, sm, sense);
    }
    grid_barrier(sense);   // total barriers = 2 + 128*12 = 1538 (even: sense restored)

    if (bid < 32 && tid == 0) g_ticket[bid] = 0;   // replay-deterministic
}

// ---------------- logits sgemm (double-buffered smem) ----------------
__global__ __launch_bounds__(256, 2) void sgemm_nt_bias(
    const float* __restrict__ A, const float* __restrict__ Bm,
    const float* __restrict__ bias, float* __restrict__ C)
{
    const int K = Hdim, N = Vsz;
    __shared__ float As[2][8][132];
    __shared__ float Bs[2][8][132];

    int m0 = blockIdx.x * 128;
    int n0 = blockIdx.y * 128;
    int tid = threadIdx.x;
    int tx = tid & 15;
    int ty = tid >> 4;

    float acc[8][8];
#pragma unroll
    for (int i = 0; i < 8; i++)
#pragma unroll
        for (int jn = 0; jn < 8; jn++) acc[i][jn] = 0.f;

    int lrow = tid >> 1;
    int lk4  = (tid & 1) * 4;
    const float* Ap = A  + (size_t)(m0 + lrow) * K + lk4;
    const float* Bp = Bm + (size_t)(n0 + lrow) * K + lk4;

    float4 a4 = *(const float4*)(Ap);
    float4 b4 = *(const float4*)(Bp);
    As[0][lk4 + 0][lrow] = a4.x; As[0][lk4 + 1][lrow] = a4.y;
    As[0][lk4 + 2][lrow] = a4.z; As[0][lk4 + 3][lrow] = a4.w;
    Bs[0][lk4 + 0][lrow] = b4.x; Bs[0][lk4 + 1][lrow] = b4.y;
    Bs[0][lk4 + 2][lrow] = b4.z; Bs[0][lk4 + 3][lrow] = b4.w;
    __syncthreads();

    int buf = 0;
    for (int k0 = 0; k0 < K; k0 += 8) {
        bool more = (k0 + 8 < K);
        if (more) {
            a4 = *(const float4*)(Ap + k0 + 8);
            b4 = *(const float4*)(Bp + k0 + 8);
        }
#pragma unroll
        for (int kk = 0; kk < 8; kk++) {
            float4 a0  = *(const float4*)&As[buf][kk][ty * 8];
            float4 a1  = *(const float4*)&As[buf][kk][ty * 8 + 4];
            float4 bb0 = *(const float4*)&Bs[buf][kk][tx * 8];
            float4 bb1 = *(const float4*)&Bs[buf][kk][tx * 8 + 4];
            float av[8] = {a0.x, a0.y, a0.z, a0.w, a1.x, a1.y, a1.z, a1.w};
            float bv[8] = {bb0.x, bb0.y, bb0.z, bb0.w, bb1.x, bb1.y, bb1.z, bb1.w};
#pragma unroll
            for (int i = 0; i < 8; i++)
#pragma unroll
                for (int jn = 0; jn < 8; jn++)
                    acc[i][jn] = fmaf(av[i], bv[jn], acc[i][jn]);
        }
        if (more) {
            int nb = buf ^ 1;
            As[nb][lk4 + 0][lrow] = a4.x; As[nb][lk4 + 1][lrow] = a4.y;
            As[nb][lk4 + 2][lrow] = a4.z; As[nb][lk4 + 3][lrow] = a4.w;
            Bs[nb][lk4 + 0][lrow] = b4.x; Bs[nb][lk4 + 1][lrow] = b4.y;
            Bs[nb][lk4 + 2][lrow] = b4.z; Bs[nb][lk4 + 3][lrow] = b4.w;
            __syncthreads();
            buf = nb;
        }
    }

    float bv[8];
#pragma unroll
    for (int jn = 0; jn < 8; jn++) bv[jn] = bias[n0 + tx * 8 + jn];
#pragma unroll
    for (int i = 0; i < 8; i++) {
        size_t m = (size_t)(m0 + ty * 8 + i);
        float* cp = C + m * N + n0 + tx * 8;
        *(float4*)(cp)     = make_float4(acc[i][0] + bv[0], acc[i][1] + bv[1],
                                         acc[i][2] + bv[2], acc[i][3] + bv[3]);
        *(float4*)(cp + 4) = make_float4(acc[i][4] + bv[4], acc[i][5] + bv[5],
                                         acc[i][6] + bv[6], acc[i][7] + bv[7]);
    }
}

// ---------------- host ----------------
extern "C" void kernel_launch(void* const* d_in, const int* in_sizes, int n_in,
                              void* d_out, int out_size) {
    (void)in_sizes; (void)out_size;
    const int* seq = (const int*)d_in[0];
    int o = n_in - 14;
    const float* emb  = (const float*)d_in[o + 0];
    const float* fc_b = (const float*)d_in[o + 1];
    const float* m1w  = (const float*)d_in[o + 2];
    const float* m1b  = (const float*)d_in[o + 3];
    const float* w1ih = (const float*)d_in[o + 4];
    const float* w1hh = (const float*)d_in[o + 5];
    const float* b1ih = (const float*)d_in[o + 6];
    const float* b1hh = (const float*)d_in[o + 7];
    const float* m2w  = (const float*)d_in[o + 8];
    const float* m2b  = (const float*)d_in[o + 9];
    const float* w2ih = (const float*)d_in[o + 10];
    const float* w2hh = (const float*)d_in[o + 11];
    const float* b2ih = (const float*)d_in[o + 12];
    const float* b2hh = (const float*)d_in[o + 13];

    float* outp = (float*)d_out;                          // [B][T][V]
    float* hidp = outp + (size_t)Bsz * Tlen * Vsz;        // [B][T][H]

    cudaFuncSetAttribute(mog_lstm_kernel,
                         cudaFuncAttributeMaxDynamicSharedMemorySize, SMEM_BYTES);

    mog_lstm_kernel<<<NB, NT, SMEM_BYTES>>>(seq, emb,
                                m1w, m1b, w1ih, w1hh, b1ih, b1hh,
                                m2w, m2b, w2ih, w2hh, b2ih, b2hh,
                                hidp);

    sgemm_nt_bias<<<dim3((Bsz * Tlen) / 128, Vsz / 128), 256>>>(hidp, emb, fc_b, outp);
}

// round 6
// speedup vs baseline: 1.5812x; 1.0952x over previous
#include <cuda_runtime.h>
#include <math.h>
#include <stdint.h>

#define Bsz 32
#define Tlen 128
#define Hdim 1024
#define Vsz 32000
#define NB 128
#define NT 512

// dynamic smem layout for recurrence (floats)
#define WS_STRIDE 36
#define OFF_WS 0
#define OFF_XS (256 * 36)                 // 9216
#define OFF_P  (OFF_XS + 256 * 32)        // 17408
#define OFF_RED (OFF_P + 16 * 32 * 32)    // 33792
#define SMEM_FLOATS (OFF_RED + 32 * 32)   // 34816
#define SMEM_BYTES (SMEM_FLOATS * 4)      // 139264

// ---------------- device scratch ----------------
__device__ float g_XT[Tlen * Hdim * Bsz];        // [t][k][b]
__device__ float g_h1a[Hdim * Bsz], g_h1b[Hdim * Bsz];
__device__ float g_h2a[Hdim * Bsz], g_h2b[Hdim * Bsz];
__device__ float g_c1[Hdim * Bsz],  g_c2[Hdim * Bsz];
__device__ float g_x2[Hdim * Bsz];
__device__ float g_P[4 * Hdim * Bsz];            // mogrify cross-block partials
__device__ int g_ticket[32];
__device__ unsigned g_bar_count;
__device__ volatile unsigned g_bar_sense;

// ---------------- grid-wide barrier (sense reversing, replay-safe) ----------------
__device__ __forceinline__ void grid_barrier(unsigned& sense) {
    __threadfence();
    __syncthreads();
    if (threadIdx.x == 0) {
        unsigned s = sense ^ 1u;
        if (atomicAdd(&g_bar_count, 1u) == NB - 1u) {
            g_bar_count = 0u;
            __threadfence();
            g_bar_sense = s;
        } else {
            while (g_bar_sense != s) __nanosleep(32);
        }
    }
    __syncthreads();
    __threadfence();
    sense ^= 1u;
}

// ---------------- 16-k MAC: thread computes 4j x 8b ----------------
__device__ __forceinline__ void mac16(const float* __restrict__ WsT,
                                      const float* __restrict__ Xs,
                                      int ks, int jq, int bg, float acc[4][8])
{
#pragma unroll 4
    for (int kk = 0; kk < 16; kk++) {
        int k = ks + kk;
        float4 w4 = *(const float4*)&WsT[k * WS_STRIDE + jq * 4];
        float4 xa = *(const float4*)&Xs[k * 32 + bg * 8];
        float4 xb = *(const float4*)&Xs[k * 32 + bg * 8 + 4];
        float wv[4] = {w4.x, w4.y, w4.z, w4.w};
        float xv[8] = {xa.x, xa.y, xa.z, xa.w, xb.x, xb.y, xb.z, xb.w};
#pragma unroll
        for (int a = 0; a < 4; a++)
#pragma unroll
            for (int b = 0; b < 8; b++)
                acc[a][b] = fmaf(wv[a], xv[b], acc[a][b]);
    }
}

// ---------------- one mogrify stage: dst *= 2*sigmoid(W @ src + bias) ----------------
__device__ void mog_stage(const float* __restrict__ Wm, const float* __restrict__ bias,
                          const float* __restrict__ src, float* __restrict__ dst,
                          int mog_epoch, float* sm, unsigned& sense)
{
    float* WsT = sm + OFF_WS;
    float* Xs  = sm + OFF_XS;
    float* P   = sm + OFF_P;

    int tid = threadIdx.x, lane = tid & 31, wid = tid >> 5;
    int jq = lane >> 2, bg = lane & 3;
    int jgrp = blockIdx.x >> 2, ky = blockIdx.x & 3;
    int j0 = jgrp * 32, kb = ky * 256;

#pragma unroll
    for (int i = 0; i < 4; i++) {
        int idx = tid + i * NT;
        int k = idx & 255, j4 = idx >> 8;
        const float* wr = Wm + (size_t)(j0 + j4 * 4) * Hdim + kb + k;
        float4 v;
        v.x = wr[0];
        v.y = wr[Hdim];
        v.z = wr[2 * Hdim];
        v.w = wr[3 * Hdim];
        *(float4*)&WsT[k * WS_STRIDE + j4 * 4] = v;
    }
#pragma unroll
    for (int i = 0; i < 4; i++) {
        int idx = tid + i * NT;
        int k = idx >> 3, b4 = idx & 7;
        *(float4*)&Xs[k * 32 + b4 * 4] =
            *(const float4*)&src[(size_t)(kb + k) * Bsz + b4 * 4];
    }
    __syncthreads();

    float acc[4][8];
#pragma unroll
    for (int a = 0; a < 4; a++)
#pragma unroll
        for (int b = 0; b < 8; b++) acc[a][b] = 0.f;

    mac16(WsT, Xs, wid * 16, jq, bg, acc);

#pragma unroll
    for (int jj = 0; jj < 4; jj++) {
        float* pp = &P[wid * 1024 + (jq * 4 + jj) * 32 + bg * 8];
        *(float4*)pp       = make_float4(acc[jj][0], acc[jj][1], acc[jj][2], acc[jj][3]);
        *(float4*)(pp + 4) = make_float4(acc[jj][4], acc[jj][5], acc[jj][6], acc[jj][7]);
    }
    __syncthreads();

#pragma unroll
    for (int i = 0; i < 2; i++) {
        int cell = tid + i * NT;
        float s = 0.f;
#pragma unroll
        for (int w = 0; w < 16; w++) s += P[w * 1024 + cell];
        g_P[(size_t)ky * (Hdim * Bsz) + (size_t)(j0 + (cell >> 5)) * Bsz + (cell & 31)] = s;
    }

    __threadfence();
    __syncthreads();
    if (tid == 0) {
        atomicAdd(&g_ticket[jgrp], 1);
        int target = 4 * mog_epoch;
        while (*(volatile int*)&g_ticket[jgrp] < target) __nanosleep(32);
    }
    __syncthreads();
    __threadfence();

    if (tid < 256) {
        int e = ky * 8 + (tid >> 5);
        int b = tid & 31;
        int j = j0 + e;
        size_t o = (size_t)j * Bsz + b;
        const size_t S = (size_t)Hdim * Bsz;
        float s = g_P[o] + g_P[S + o] + g_P[2 * S + o] + g_P[3 * S + o] + bias[j];
        dst[o] *= 2.f / (1.f + __expf(-s));
    }
    grid_barrier(sense);
}

// ---------------- LSTM gate stage ----------------
__device__ void gate_stage(const float* __restrict__ Wih, const float* __restrict__ Whh,
                           const float* __restrict__ bih, const float* __restrict__ bhh,
                           const float* __restrict__ xsrc, const float* __restrict__ hsrc,
                           float* __restrict__ cSt, float* __restrict__ hDst,
                           float* __restrict__ x2copy, float* __restrict__ hidOut, int t,
                           float* sm, unsigned& sense)
{
    float* WsT = sm + OFF_WS;
    float* Xs  = sm + OFF_XS;
    float* P   = sm + OFF_P;
    float* Red = sm + OFF_RED;

    int tid = threadIdx.x, lane = tid & 31, wid = tid >> 5;
    int jq = lane >> 2, bg = lane & 3;
    int j0u = blockIdx.x * 8;

    float acc[4][8];
#pragma unroll
    for (int a = 0; a < 4; a++)
#pragma unroll
        for (int b = 0; b < 8; b++) acc[a][b] = 0.f;

    for (int c = 0; c < 8; c++) {
        const float* Wm = (c < 4) ? Wih : Whh;
        const float* S  = (c < 4) ? xsrc : hsrc;
        int cbase = (c & 3) * 256;
        __syncthreads();
#pragma unroll
        for (int i = 0; i < 4; i++) {
            int idx = tid + i * NT;
            int k = idx & 255, j4 = idx >> 8;
            float4 v;
            {
                int r0 = j4 * 4;
                v.x = Wm[(size_t)((r0 >> 3) * Hdim + j0u + (r0 & 7)) * Hdim + cbase + k];
                int r1 = j4 * 4 + 1;
                v.y = Wm[(size_t)((r1 >> 3) * Hdim + j0u + (r1 & 7)) * Hdim + cbase + k];
                int r2 = j4 * 4 + 2;
                v.z = Wm[(size_t)((r2 >> 3) * Hdim + j0u + (r2 & 7)) * Hdim + cbase + k];
                int r3 = j4 * 4 + 3;
                v.w = Wm[(size_t)((r3 >> 3) * Hdim + j0u + (r3 & 7)) * Hdim + cbase + k];
            }
            *(float4*)&WsT[k * WS_STRIDE + j4 * 4] = v;
        }
#pragma unroll
        for (int i = 0; i < 4; i++) {
            int idx = tid + i * NT;
            int k = idx >> 3, b4 = idx & 7;
            *(float4*)&Xs[k * 32 + b4 * 4] =
                *(const float4*)&S[(size_t)(cbase + k) * Bsz + b4 * 4];
        }
        __syncthreads();
        mac16(WsT, Xs, wid * 16, jq, bg, acc);
    }

#pragma unroll
    for (int jj = 0; jj < 4; jj++) {
        float* pp = &P[wid * 1024 + (jq * 4 + jj) * 32 + bg * 8];
        *(float4*)pp       = make_float4(acc[jj][0], acc[jj][1], acc[jj][2], acc[jj][3]);
        *(float4*)(pp + 4) = make_float4(acc[jj][4], acc[jj][5], acc[jj][6], acc[jj][7]);
    }
    __syncthreads();
#pragma unroll
    for (int i = 0; i < 2; i++) {
        int cell = tid + i * NT;
        float s = 0.f;
#pragma unroll
        for (int w = 0; w < 16; w++) s += P[w * 1024 + cell];
        Red[cell] = s;
    }
    __syncthreads();

    if (tid < 256) {
        int u = tid >> 5, b = tid & 31;
        int j = j0u + u;
        float gi = Red[(u) * 32 + b]      + bih[j]            + bhh[j];
        float gf = Red[(8 + u) * 32 + b]  + bih[Hdim + j]     + bhh[Hdim + j];
        float gg = Red[(16 + u) * 32 + b] + bih[2 * Hdim + j] + bhh[2 * Hdim + j];
        float go = Red[(24 + u) * 32 + b] + bih[3 * Hdim + j] + bhh[3 * Hdim + j];

        float si = 1.f / (1.f + __expf(-gi));
        float sf = 1.f / (1.f + __expf(-gf));
        float tg = tanhf(gg);
        float so = 1.f / (1.f + __expf(-go));

        size_t g = (size_t)j * Bsz + b;
        float cc = sf * cSt[g] + si * tg;
        float h = so * tanhf(cc);
        cSt[g] = cc;
        hDst[g] = h;
        if (x2copy) x2copy[g] = h;
        if (hidOut) hidOut[(size_t)b * Tlen * Hdim + (size_t)t * Hdim + j] = h;
    }
    grid_barrier(sense);
}

// ---------------- persistent recurrence kernel ----------------
__global__ __launch_bounds__(NT, 1) void mog_lstm_kernel(
    const int* __restrict__ seq, const float* __restrict__ emb,
    const float* __restrict__ m1w, const float* __restrict__ m1b,
    const float* __restrict__ w1ih, const float* __restrict__ w1hh,
    const float* __restrict__ b1ih, const float* __restrict__ b1hh,
    const float* __restrict__ m2w, const float* __restrict__ m2b,
    const float* __restrict__ w2ih, const float* __restrict__ w2hh,
    const float* __restrict__ b2ih, const float* __restrict__ b2hh,
    float* __restrict__ hidp)
{
    extern __shared__ float sm[];
    int tid = threadIdx.x;
    int bid = blockIdx.x;
    unsigned sense = 0;

    for (int g = bid * NT + tid; g < Hdim * Bsz; g += NB * NT) {
        g_h1a[g] = 0.f; g_h1b[g] = 0.f; g_h2a[g] = 0.f; g_h2b[g] = 0.f;
        g_c1[g] = 0.f;  g_c2[g] = 0.f;
    }
    {
        int t = bid;
        for (int idx = tid; idx < Hdim * Bsz; idx += NT) {
            int b = idx & 31;
            int k = idx >> 5;
            int id = seq[b * Tlen + t];
            g_XT[(size_t)t * Hdim * Bsz + (size_t)k * Bsz + b] =
                emb[(size_t)id * Hdim + k];
        }
    }
    grid_barrier(sense);

    int mog_epoch = 0;
    for (int t = 0; t < Tlen; t++) {
        float* xt  = g_XT + (size_t)t * Hdim * Bsz;
        float* h1s = (t & 1) ? g_h1b : g_h1a;
        float* h1d = (t & 1) ? g_h1a : g_h1b;
        float* h2s = (t & 1) ? g_h2b : g_h2a;
        float* h2d = (t & 1) ? g_h2a : g_h2b;

        for (int i = 0; i < 5; i++) {
            mog_epoch++;
            const float* src = (i & 1) ? (const float*)xt : (const float*)h1s;
            float* dst = (i & 1) ? h1s : xt;
            mog_stage(m1w + (size_t)i * Hdim * Hdim, m1b + i * Hdim,
                      src, dst, mog_epoch, sm, sense);
        }
        gate_stage(w1ih, w1hh, b1ih, b1hh, xt, h1s, g_c1, h1d,
                   g_x2, nullptr, t, sm, sense);

        for (int i = 0; i < 5; i++) {
            mog_epoch++;
            const float* src = (i & 1) ? (const float*)g_x2 : (const float*)h2s;
            float* dst = (i & 1) ? h2s : g_x2;
            mog_stage(m2w + (size_t)i * Hdim * Hdim, m2b + i * Hdim,
                      src, dst, mog_epoch, sm, sense);
        }
        gate_stage(w2ih, w2hh, b2ih, b2hh, g_x2, h2s, g_c2, h2d,
                   nullptr, hidp, t, sm, sense);
    }
    grid_barrier(sense);

    if (bid < 32 && tid == 0) g_ticket[bid] = 0;
}

// ================= tf32x3 tensor-core logits GEMM =================
// C[m][n] = sum_k A[m][k]*B[n][k] + bias[n]
// A row-major (.row), B rows are k-contiguous (.col). mma m16n8k8 tf32.
// Error compensation: x = hi + lo (both tf32); acc += Ah*Bh + Al*Bh + Ah*Bl.

#define TS 36                      // smem k-stride (conflict-free frags)
#define SG_SMEM_BYTES (4 * 128 * TS * 4)   // 4 arrays x 128 rows x 36 u32

__device__ __forceinline__ unsigned f2tf32(float x) {
    unsigned r;
    asm("cvt.rna.tf32.f32 %0, %1;" : "=r"(r) : "f"(x));
    return r;
}

__device__ __forceinline__ void mma_tf32(float d[4], const unsigned a[4],
                                         const unsigned b[2]) {
    asm volatile(
        "mma.sync.aligned.m16n8k8.row.col.f32.tf32.tf32.f32 "
        "{%0,%1,%2,%3},{%4,%5,%6,%7},{%8,%9},{%0,%1,%2,%3};"
        : "+f"(d[0]), "+f"(d[1]), "+f"(d[2]), "+f"(d[3])
        : "r"(a[0]), "r"(a[1]), "r"(a[2]), "r"(a[3]), "r"(b[0]), "r"(b[1]));
}

__global__ __launch_bounds__(256, 2) void sgemm_tf32x3_bias(
    const float* __restrict__ A, const float* __restrict__ Bm,
    const float* __restrict__ bias, float* __restrict__ C)
{
    const int K = Hdim, N = Vsz;
    extern __shared__ unsigned smu[];
    unsigned* As_h = smu;                    // [128][TS]
    unsigned* As_l = As_h + 128 * TS;
    unsigned* Bs_h = As_l + 128 * TS;
    unsigned* Bs_l = Bs_h + 128 * TS;

    int tid = threadIdx.x;
    int lane = tid & 31, wrp = tid >> 5;
    int wm = wrp & 1, wn = wrp >> 1;         // 2 m-warps x 4 n-warps
    int r = lane >> 2, cq = lane & 3;
    int m0 = blockIdx.x * 128;
    int n0 = blockIdx.y * 128;

    float acc[4][4][4];
#pragma unroll
    for (int i = 0; i < 4; i++)
#pragma unroll
        for (int j = 0; j < 4; j++)
#pragma unroll
            for (int q = 0; q < 4; q++) acc[i][j][q] = 0.f;

    for (int kc = 0; kc < K; kc += 32) {
        __syncthreads();
        // stage A and B tiles: 128 rows x 32 k each, split hi/lo
#pragma unroll
        for (int q = 0; q < 4; q++) {
            int cell = tid + q * 256;          // 0..1023
            int mrow = cell >> 3, k4 = (cell & 7) * 4;
            float4 va = *(const float4*)&A[(size_t)(m0 + mrow) * K + kc + k4];
            float4 vb = *(const float4*)&Bm[(size_t)(n0 + mrow) * K + kc + k4];
            unsigned ah0 = f2tf32(va.x), ah1 = f2tf32(va.y),
                     ah2 = f2tf32(va.z), ah3 = f2tf32(va.w);
            unsigned al0 = f2tf32(va.x - __uint_as_float(ah0));
            unsigned al1 = f2tf32(va.y - __uint_as_float(ah1));
            unsigned al2 = f2tf32(va.z - __uint_as_float(ah2));
            unsigned al3 = f2tf32(va.w - __uint_as_float(ah3));
            unsigned bh0 = f2tf32(vb.x), bh1 = f2tf32(vb.y),
                     bh2 = f2tf32(vb.z), bh3 = f2tf32(vb.w);
            unsigned bl0 = f2tf32(vb.x - __uint_as_float(bh0));
            unsigned bl1 = f2tf32(vb.y - __uint_as_float(bh1));
            unsigned bl2 = f2tf32(vb.z - __uint_as_float(bh2));
            unsigned bl3 = f2tf32(vb.w - __uint_as_float(bh3));
            int sa = mrow * TS + k4;
            *(uint4*)&As_h[sa] = make_uint4(ah0, ah1, ah2, ah3);
            *(uint4*)&As_l[sa] = make_uint4(al0, al1, al2, al3);
            *(uint4*)&Bs_h[sa] = make_uint4(bh0, bh1, bh2, bh3);
            *(uint4*)&Bs_l[sa] = make_uint4(bl0, bl1, bl2, bl3);
        }
        __syncthreads();

#pragma unroll
        for (int kk = 0; kk < 32; kk += 8) {
            unsigned ah[4][4], al[4][4], bh[4][2], bl[4][2];
#pragma unroll
            for (int mf = 0; mf < 4; mf++) {
                int base = (wm * 64 + mf * 16 + r) * TS + kk + cq;
                ah[mf][0] = As_h[base];
                ah[mf][1] = As_h[base + 8 * TS];
                ah[mf][2] = As_h[base + 4];
                ah[mf][3] = As_h[base + 8 * TS + 4];
                al[mf][0] = As_l[base];
                al[mf][1] = As_l[base + 8 * TS];
                al[mf][2] = As_l[base + 4];
                al[mf][3] = As_l[base + 8 * TS + 4];
            }
#pragma unroll
            for (int nf = 0; nf < 4; nf++) {
                int base = (wn * 32 + nf * 8 + r) * TS + kk + cq;
                bh[nf][0] = Bs_h[base];
                bh[nf][1] = Bs_h[base + 4];
                bl[nf][0] = Bs_l[base];
                bl[nf][1] = Bs_l[base + 4];
            }
            // term 1: Ah*Bh ; term 2: Al*Bh ; term 3: Ah*Bl
#pragma unroll
            for (int mf = 0; mf < 4; mf++)
#pragma unroll
                for (int nf = 0; nf < 4; nf++)
                    mma_tf32(acc[mf][nf], ah[mf], bh[nf]);
#pragma unroll
            for (int mf = 0; mf < 4; mf++)
#pragma unroll
                for (int nf = 0; nf < 4; nf++)
                    mma_tf32(acc[mf][nf], al[mf], bh[nf]);
#pragma unroll
            for (int mf = 0; mf < 4; mf++)
#pragma unroll
                for (int nf = 0; nf < 4; nf++)
                    mma_tf32(acc[mf][nf], ah[mf], bl[nf]);
        }
    }

    // epilogue: c0,c1 -> (row, 2c),(row,2c+1); c2,c3 -> row+8
#pragma unroll
    for (int nf = 0; nf < 4; nf++) {
        int col = n0 + wn * 32 + nf * 8 + 2 * cq;
        float bv0 = bias[col], bv1 = bias[col + 1];
#pragma unroll
        for (int mf = 0; mf < 4; mf++) {
            int row = m0 + wm * 64 + mf * 16 + r;
            float2 v0 = make_float2(acc[mf][nf][0] + bv0, acc[mf][nf][1] + bv1);
            float2 v1 = make_float2(acc[mf][nf][2] + bv0, acc[mf][nf][3] + bv1);
            *(float2*)&C[(size_t)row * N + col] = v0;
            *(float2*)&C[(size_t)(row + 8) * N + col] = v1;
        }
    }
}

// ---------------- host ----------------
extern "C" void kernel_launch(void* const* d_in, const int* in_sizes, int n_in,
                              void* d_out, int out_size) {
    (void)in_sizes; (void)out_size;
    const int* seq = (const int*)d_in[0];
    int o = n_in - 14;
    const float* emb  = (const float*)d_in[o + 0];
    const float* fc_b = (const float*)d_in[o + 1];
    const float* m1w  = (const float*)d_in[o + 2];
    const float* m1b  = (const float*)d_in[o + 3];
    const float* w1ih = (const float*)d_in[o + 4];
    const float* w1hh = (const float*)d_in[o + 5];
    const float* b1ih = (const float*)d_in[o + 6];
    const float* b1hh = (const float*)d_in[o + 7];
    const float* m2w  = (const float*)d_in[o + 8];
    const float* m2b  = (const float*)d_in[o + 9];
    const float* w2ih = (const float*)d_in[o + 10];
    const float* w2hh = (const float*)d_in[o + 11];
    const float* b2ih = (const float*)d_in[o + 12];
    const float* b2hh = (const float*)d_in[o + 13];

    float* outp = (float*)d_out;                          // [B][T][V]
    float* hidp = outp + (size_t)Bsz * Tlen * Vsz;        // [B][T][H]

    cudaFuncSetAttribute(mog_lstm_kernel,
                         cudaFuncAttributeMaxDynamicSharedMemorySize, SMEM_BYTES);
    cudaFuncSetAttribute(sgemm_tf32x3_bias,
                         cudaFuncAttributeMaxDynamicSharedMemorySize, SG_SMEM_BYTES);

    mog_lstm_kernel<<<NB, NT, SMEM_BYTES>>>(seq, emb,
                                m1w, m1b, w1ih, w1hh, b1ih, b1hh,
                                m2w, m2b, w2ih, w2hh, b2ih, b2hh,
                                hidp);

    sgemm_tf32x3_bias<<<dim3((Bsz * Tlen) / 128, Vsz / 128), 256, SG_SMEM_BYTES>>>(
        hidp, emb, fc_b, outp);
}

// round 8
// speedup vs baseline: 1.6973x; 1.0734x over previous
#include <cuda_runtime.h>
#include <cuda_bf16.h>
#include <math.h>
#include <stdint.h>

#define Bsz 32
#define Tlen 128
#define Hdim 1024
#define Vsz 32000
#define NB 128
#define NT 512

// ---------------- recurrence smem layout (floats) ----------------
#define WS_STRIDE 36
#define OFF_WS 0
#define OFF_XS (256 * 36)
#define OFF_P  (OFF_XS + 256 * 32)
#define OFF_RED (OFF_P + 16 * 32 * 32)
#define SMEM_FLOATS (OFF_RED + 32 * 32)
#define SMEM_BYTES (SMEM_FLOATS * 4)

// ---------------- device scratch ----------------
__device__ float g_XT[Tlen * Hdim * Bsz];
__device__ float g_h1a[Hdim * Bsz], g_h1b[Hdim * Bsz];
__device__ float g_h2a[Hdim * Bsz], g_h2b[Hdim * Bsz];
__device__ float g_c1[Hdim * Bsz],  g_c2[Hdim * Bsz];
__device__ float g_x2[Hdim * Bsz];
__device__ float g_P[4 * Hdim * Bsz];
__device__ int g_ticket[32];
__device__ unsigned g_bar_count;
__device__ volatile unsigned g_bar_sense;

// bf16 hi/lo splits for logits GEMM
__device__ __nv_bfloat16 g_embh[(size_t)Vsz * Hdim];
__device__ __nv_bfloat16 g_embl[(size_t)Vsz * Hdim];
__device__ __nv_bfloat16 g_hidh[(size_t)Bsz * Tlen * Hdim];
__device__ __nv_bfloat16 g_hidl[(size_t)Bsz * Tlen * Hdim];

// ---------------- grid-wide barrier ----------------
__device__ __forceinline__ void grid_barrier(unsigned& sense) {
    __threadfence();
    __syncthreads();
    if (threadIdx.x == 0) {
        unsigned s = sense ^ 1u;
        if (atomicAdd(&g_bar_count, 1u) == NB - 1u) {
            g_bar_count = 0u;
            __threadfence();
            g_bar_sense = s;
        } else {
            while (g_bar_sense != s) __nanosleep(32);
        }
    }
    __syncthreads();
    __threadfence();
    sense ^= 1u;
}

// ---------------- 16-k MAC: thread computes 4j x 8b ----------------
__device__ __forceinline__ void mac16(const float* __restrict__ WsT,
                                      const float* __restrict__ Xs,
                                      int ks, int jq, int bg, float acc[4][8])
{
#pragma unroll 4
    for (int kk = 0; kk < 16; kk++) {
        int k = ks + kk;
        float4 w4 = *(const float4*)&WsT[k * WS_STRIDE + jq * 4];
        float4 xa = *(const float4*)&Xs[k * 32 + bg * 8];
        float4 xb = *(const float4*)&Xs[k * 32 + bg * 8 + 4];
        float wv[4] = {w4.x, w4.y, w4.z, w4.w};
        float xv[8] = {xa.x, xa.y, xa.z, xa.w, xb.x, xb.y, xb.z, xb.w};
#pragma unroll
        for (int a = 0; a < 4; a++)
#pragma unroll
            for (int b = 0; b < 8; b++)
                acc[a][b] = fmaf(wv[a], xv[b], acc[a][b]);
    }
}

// ---------------- mogrify stage ----------------
__device__ void mog_stage(const float* __restrict__ Wm, const float* __restrict__ bias,
                          const float* __restrict__ src, float* __restrict__ dst,
                          int mog_epoch, float* sm, unsigned& sense)
{
    float* WsT = sm + OFF_WS;
    float* Xs  = sm + OFF_XS;
    float* P   = sm + OFF_P;

    int tid = threadIdx.x, lane = tid & 31, wid = tid >> 5;
    int jq = lane >> 2, bg = lane & 3;
    int jgrp = blockIdx.x >> 2, ky = blockIdx.x & 3;
    int j0 = jgrp * 32, kb = ky * 256;

#pragma unroll
    for (int i = 0; i < 4; i++) {
        int idx = tid + i * NT;
        int k = idx & 255, j4 = idx >> 8;
        const float* wr = Wm + (size_t)(j0 + j4 * 4) * Hdim + kb + k;
        float4 v;
        v.x = wr[0];
        v.y = wr[Hdim];
        v.z = wr[2 * Hdim];
        v.w = wr[3 * Hdim];
        *(float4*)&WsT[k * WS_STRIDE + j4 * 4] = v;
    }
#pragma unroll
    for (int i = 0; i < 4; i++) {
        int idx = tid + i * NT;
        int k = idx >> 3, b4 = idx & 7;
        *(float4*)&Xs[k * 32 + b4 * 4] =
            *(const float4*)&src[(size_t)(kb + k) * Bsz + b4 * 4];
    }
    __syncthreads();

    float acc[4][8];
#pragma unroll
    for (int a = 0; a < 4; a++)
#pragma unroll
        for (int b = 0; b < 8; b++) acc[a][b] = 0.f;

    mac16(WsT, Xs, wid * 16, jq, bg, acc);

#pragma unroll
    for (int jj = 0; jj < 4; jj++) {
        float* pp = &P[wid * 1024 + (jq * 4 + jj) * 32 + bg * 8];
        *(float4*)pp       = make_float4(acc[jj][0], acc[jj][1], acc[jj][2], acc[jj][3]);
        *(float4*)(pp + 4) = make_float4(acc[jj][4], acc[jj][5], acc[jj][6], acc[jj][7]);
    }
    __syncthreads();

#pragma unroll
    for (int i = 0; i < 2; i++) {
        int cell = tid + i * NT;
        float s = 0.f;
#pragma unroll
        for (int w = 0; w < 16; w++) s += P[w * 1024 + cell];
        g_P[(size_t)ky * (Hdim * Bsz) + (size_t)(j0 + (cell >> 5)) * Bsz + (cell & 31)] = s;
    }

    __threadfence();
    __syncthreads();
    if (tid == 0) {
        atomicAdd(&g_ticket[jgrp], 1);
        int target = 4 * mog_epoch;
        while (*(volatile int*)&g_ticket[jgrp] < target) __nanosleep(32);
    }
    __syncthreads();
    __threadfence();

    if (tid < 256) {
        int e = ky * 8 + (tid >> 5);
        int b = tid & 31;
        int j = j0 + e;
        size_t o = (size_t)j * Bsz + b;
        const size_t S = (size_t)Hdim * Bsz;
        float s = g_P[o] + g_P[S + o] + g_P[2 * S + o] + g_P[3 * S + o] + bias[j];
        dst[o] *= 2.f / (1.f + __expf(-s));
    }
    grid_barrier(sense);
}

// ---------------- LSTM gate stage ----------------
__device__ void gate_stage(const float* __restrict__ Wih, const float* __restrict__ Whh,
                           const float* __restrict__ bih, const float* __restrict__ bhh,
                           const float* __restrict__ xsrc, const float* __restrict__ hsrc,
                           float* __restrict__ cSt, float* __restrict__ hDst,
                           float* __restrict__ x2copy, float* __restrict__ hidOut, int t,
                           float* sm, unsigned& sense)
{
    float* WsT = sm + OFF_WS;
    float* Xs  = sm + OFF_XS;
    float* P   = sm + OFF_P;
    float* Red = sm + OFF_RED;

    int tid = threadIdx.x, lane = tid & 31, wid = tid >> 5;
    int jq = lane >> 2, bg = lane & 3;
    int j0u = blockIdx.x * 8;

    float acc[4][8];
#pragma unroll
    for (int a = 0; a < 4; a++)
#pragma unroll
        for (int b = 0; b < 8; b++) acc[a][b] = 0.f;

    for (int c = 0; c < 8; c++) {
        const float* Wm = (c < 4) ? Wih : Whh;
        const float* S  = (c < 4) ? xsrc : hsrc;
        int cbase = (c & 3) * 256;
        __syncthreads();
#pragma unroll
        for (int i = 0; i < 4; i++) {
            int idx = tid + i * NT;
            int k = idx & 255, j4 = idx >> 8;
            float4 v;
            {
                int r0 = j4 * 4;
                v.x = Wm[(size_t)((r0 >> 3) * Hdim + j0u + (r0 & 7)) * Hdim + cbase + k];
                int r1 = j4 * 4 + 1;
                v.y = Wm[(size_t)((r1 >> 3) * Hdim + j0u + (r1 & 7)) * Hdim + cbase + k];
                int r2 = j4 * 4 + 2;
                v.z = Wm[(size_t)((r2 >> 3) * Hdim + j0u + (r2 & 7)) * Hdim + cbase + k];
                int r3 = j4 * 4 + 3;
                v.w = Wm[(size_t)((r3 >> 3) * Hdim + j0u + (r3 & 7)) * Hdim + cbase + k];
            }
            *(float4*)&WsT[k * WS_STRIDE + j4 * 4] = v;
        }
#pragma unroll
        for (int i = 0; i < 4; i++) {
            int idx = tid + i * NT;
            int k = idx >> 3, b4 = idx & 7;
            *(float4*)&Xs[k * 32 + b4 * 4] =
                *(const float4*)&S[(size_t)(cbase + k) * Bsz + b4 * 4];
        }
        __syncthreads();
        mac16(WsT, Xs, wid * 16, jq, bg, acc);
    }

#pragma unroll
    for (int jj = 0; jj < 4; jj++) {
        float* pp = &P[wid * 1024 + (jq * 4 + jj) * 32 + bg * 8];
        *(float4*)pp       = make_float4(acc[jj][0], acc[jj][1], acc[jj][2], acc[jj][3]);
        *(float4*)(pp + 4) = make_float4(acc[jj][4], acc[jj][5], acc[jj][6], acc[jj][7]);
    }
    __syncthreads();
#pragma unroll
    for (int i = 0; i < 2; i++) {
        int cell = tid + i * NT;
        float s = 0.f;
#pragma unroll
        for (int w = 0; w < 16; w++) s += P[w * 1024 + cell];
        Red[cell] = s;
    }
    __syncthreads();

    if (tid < 256) {
        int u = tid >> 5, b = tid & 31;
        int j = j0u + u;
        float gi = Red[(u) * 32 + b]      + bih[j]            + bhh[j];
        float gf = Red[(8 + u) * 32 + b]  + bih[Hdim + j]     + bhh[Hdim + j];
        float gg = Red[(16 + u) * 32 + b] + bih[2 * Hdim + j] + bhh[2 * Hdim + j];
        float go = Red[(24 + u) * 32 + b] + bih[3 * Hdim + j] + bhh[3 * Hdim + j];

        float si = 1.f / (1.f + __expf(-gi));
        float sf = 1.f / (1.f + __expf(-gf));
        float tg = tanhf(gg);
        float so = 1.f / (1.f + __expf(-go));

        size_t g = (size_t)j * Bsz + b;
        float cc = sf * cSt[g] + si * tg;
        float h = so * tanhf(cc);
        cSt[g] = cc;
        hDst[g] = h;
        if (x2copy) x2copy[g] = h;
        if (hidOut) hidOut[(size_t)b * Tlen * Hdim + (size_t)t * Hdim + j] = h;
    }
    grid_barrier(sense);
}

// ---------------- persistent recurrence kernel ----------------
__global__ __launch_bounds__(NT, 1) void mog_lstm_kernel(
    const int* __restrict__ seq, const float* __restrict__ emb,
    const float* __restrict__ m1w, const float* __restrict__ m1b,
    const float* __restrict__ w1ih, const float* __restrict__ w1hh,
    const float* __restrict__ b1ih, const float* __restrict__ b1hh,
    const float* __restrict__ m2w, const float* __restrict__ m2b,
    const float* __restrict__ w2ih, const float* __restrict__ w2hh,
    const float* __restrict__ b2ih, const float* __restrict__ b2hh,
    float* __restrict__ hidp)
{
    extern __shared__ float sm[];
    int tid = threadIdx.x;
    int bid = blockIdx.x;
    unsigned sense = 0;

    for (int g = bid * NT + tid; g < Hdim * Bsz; g += NB * NT) {
        g_h1a[g] = 0.f; g_h1b[g] = 0.f; g_h2a[g] = 0.f; g_h2b[g] = 0.f;
        g_c1[g] = 0.f;  g_c2[g] = 0.f;
    }
    {
        int t = bid;
        for (int idx = tid; idx < Hdim * Bsz; idx += NT) {
            int b = idx & 31;
            int k = idx >> 5;
            int id = seq[b * Tlen + t];
            g_XT[(size_t)t * Hdim * Bsz + (size_t)k * Bsz + b] =
                emb[(size_t)id * Hdim + k];
        }
    }
    grid_barrier(sense);

    int mog_epoch = 0;
    for (int t = 0; t < Tlen; t++) {
        float* xt  = g_XT + (size_t)t * Hdim * Bsz;
        float* h1s = (t & 1) ? g_h1b : g_h1a;
        float* h1d = (t & 1) ? g_h1a : g_h1b;
        float* h2s = (t & 1) ? g_h2b : g_h2a;
        float* h2d = (t & 1) ? g_h2a : g_h2b;

        for (int i = 0; i < 5; i++) {
            mog_epoch++;
            const float* src = (i & 1) ? (const float*)xt : (const float*)h1s;
            float* dst = (i & 1) ? h1s : xt;
            mog_stage(m1w + (size_t)i * Hdim * Hdim, m1b + i * Hdim,
                      src, dst, mog_epoch, sm, sense);
        }
        gate_stage(w1ih, w1hh, b1ih, b1hh, xt, h1s, g_c1, h1d,
                   g_x2, nullptr, t, sm, sense);

        for (int i = 0; i < 5; i++) {
            mog_epoch++;
            const float* src = (i & 1) ? (const float*)g_x2 : (const float*)h2s;
            float* dst = (i & 1) ? h2s : g_x2;
            mog_stage(m2w + (size_t)i * Hdim * Hdim, m2b + i * Hdim,
                      src, dst, mog_epoch, sm, sense);
        }
        gate_stage(w2ih, w2hh, b2ih, b2hh, g_x2, h2s, g_c2, h2d,
                   nullptr, hidp, t, sm, sense);
    }
    grid_barrier(sense);

    if (bid < 32 && tid == 0) g_ticket[bid] = 0;
}

// ================= bf16 hi/lo split =================
__global__ void split_bf16_kernel(const float* __restrict__ src,
                                  __nv_bfloat16* __restrict__ hi,
                                  __nv_bfloat16* __restrict__ lo, size_t n4)
{
    for (size_t i = blockIdx.x * blockDim.x + threadIdx.x; i < n4;
         i += (size_t)gridDim.x * blockDim.x) {
        float4 v = *(const float4*)(src + i * 4);
        __nv_bfloat16 h0 = __float2bfloat16_rn(v.x);
        __nv_bfloat16 h1 = __float2bfloat16_rn(v.y);
        __nv_bfloat16 h2 = __float2bfloat16_rn(v.z);
        __nv_bfloat16 h3 = __float2bfloat16_rn(v.w);
        __nv_bfloat16 l0 = __float2bfloat16_rn(v.x - __bfloat162float(h0));
        __nv_bfloat16 l1 = __float2bfloat16_rn(v.y - __bfloat162float(h1));
        __nv_bfloat16 l2 = __float2bfloat16_rn(v.z - __bfloat162float(h2));
        __nv_bfloat16 l3 = __float2bfloat16_rn(v.w - __bfloat162float(h3));
        __nv_bfloat162* hp = (__nv_bfloat162*)(hi + i * 4);
        __nv_bfloat162* lp = (__nv_bfloat162*)(lo + i * 4);
        hp[0] = __nv_bfloat162(h0, h1);
        hp[1] = __nv_bfloat162(h2, h3);
        lp[0] = __nv_bfloat162(l0, l1);
        lp[1] = __nv_bfloat162(l2, l3);
    }
}

// ================= bf16x3 legacy-mma logits GEMM =================
// C[m][n] = sum_k A[m][k]*B[n][k] + bias[n]
// mma.sync.m16n8k16 bf16, A .row, B .col (emb rows are k-contiguous).
// Error compensation: acc += Ah*Bh + Al*Bh + Ah*Bl.

#define GTS 72                                  // smem stride (bf16 elems)
#define G_SMEM_BYTES (4 * 128 * GTS * 2)        // 73728

__device__ __forceinline__ void mma_bf16(float d[4], const uint32_t a[4],
                                         const uint32_t b[2]) {
    asm volatile(
        "mma.sync.aligned.m16n8k16.row.col.f32.bf16.bf16.f32 "
        "{%0,%1,%2,%3},{%4,%5,%6,%7},{%8,%9},{%0,%1,%2,%3};"
        : "+f"(d[0]), "+f"(d[1]), "+f"(d[2]), "+f"(d[3])
        : "r"(a[0]), "r"(a[1]), "r"(a[2]), "r"(a[3]), "r"(b[0]), "r"(b[1]));
}

__global__ __launch_bounds__(256, 2) void gemm_bf16x3_bias(
    const float* __restrict__ bias, float* __restrict__ C)
{
    extern __shared__ __nv_bfloat16 gs[];
    __nv_bfloat16* Ahs = gs;
    __nv_bfloat16* Als = Ahs + 128 * GTS;
    __nv_bfloat16* Bhs = Als + 128 * GTS;
    __nv_bfloat16* Bls = Bhs + 128 * GTS;

    int tid = threadIdx.x;
    int lane = tid & 31, wrp = tid >> 5;
    int wm = wrp & 1, wn = wrp >> 1;          // 2 m-warps x 4 n-warps
    int gr = lane >> 2, tig = lane & 3;
    int m0 = blockIdx.x * 128;
    int n0 = blockIdx.y * 128;

    const __nv_bfloat16* Ahg = g_hidh + (size_t)m0 * Hdim;
    const __nv_bfloat16* Alg = g_hidl + (size_t)m0 * Hdim;
    const __nv_bfloat16* Bhg = g_embh + (size_t)n0 * Hdim;
    const __nv_bfloat16* Blg = g_embl + (size_t)n0 * Hdim;

    float acc[4][4][4];
#pragma unroll
    for (int i = 0; i < 4; i++)
#pragma unroll
        for (int j = 0; j < 4; j++)
#pragma unroll
            for (int q = 0; q < 4; q++) acc[i][j][q] = 0.f;

    for (int kc = 0; kc < Hdim; kc += 64) {
        __syncthreads();
#pragma unroll
        for (int i = 0; i < 4; i++) {
            int idx = tid + i * 256;            // 0..1023
            int r = idx >> 3, u = idx & 7;      // row, 8-elem group
            int so = r * GTS + u * 8;
            size_t go = (size_t)r * Hdim + kc + u * 8;
            *(uint4*)&Ahs[so] = *(const uint4*)&Ahg[go];
            *(uint4*)&Als[so] = *(const uint4*)&Alg[go];
            *(uint4*)&Bhs[so] = *(const uint4*)&Bhg[go];
            *(uint4*)&Bls[so] = *(const uint4*)&Blg[go];
        }
        __syncthreads();

#pragma unroll
        for (int ks = 0; ks < 4; ks++) {
            int kb = ks * 16;
            uint32_t ah[4][4], al[4][4], bh[4][2], bl[4][2];
#pragma unroll
            for (int mf = 0; mf < 4; mf++) {
                int base = (wm * 64 + mf * 16 + gr) * GTS + kb + 2 * tig;
                ah[mf][0] = *(const uint32_t*)&Ahs[base];
                ah[mf][1] = *(const uint32_t*)&Ahs[base + 8 * GTS];
                ah[mf][2] = *(const uint32_t*)&Ahs[base + 8];
                ah[mf][3] = *(const uint32_t*)&Ahs[base + 8 * GTS + 8];
                al[mf][0] = *(const uint32_t*)&Als[base];
                al[mf][1] = *(const uint32_t*)&Als[base + 8 * GTS];
                al[mf][2] = *(const uint32_t*)&Als[base + 8];
                al[mf][3] = *(const uint32_t*)&Als[base + 8 * GTS + 8];
            }
#pragma unroll
            for (int nf = 0; nf < 4; nf++) {
                int base = (wn * 32 + nf * 8 + gr) * GTS + kb + 2 * tig;
                bh[nf][0] = *(const uint32_t*)&Bhs[base];
                bh[nf][1] = *(const uint32_t*)&Bhs[base + 8];
                bl[nf][0] = *(const uint32_t*)&Bls[base];
                bl[nf][1] = *(const uint32_t*)&Bls[base + 8];
            }
#pragma unroll
            for (int mf = 0; mf < 4; mf++)
#pragma unroll
                for (int nf = 0; nf < 4; nf++)
                    mma_bf16(acc[mf][nf], ah[mf], bh[nf]);
#pragma unroll
            for (int mf = 0; mf < 4; mf++)
#pragma unroll
                for (int nf = 0; nf < 4; nf++)
                    mma_bf16(acc[mf][nf], al[mf], bh[nf]);
#pragma unroll
            for (int mf = 0; mf < 4; mf++)
#pragma unroll
                for (int nf = 0; nf < 4; nf++)
                    mma_bf16(acc[mf][nf], ah[mf], bl[nf]);
        }
    }

    // epilogue: c0,c1 -> (row, 2tig),(row, 2tig+1); c2,c3 -> row+8
#pragma unroll
    for (int nf = 0; nf < 4; nf++) {
        int col = n0 + wn * 32 + nf * 8 + 2 * tig;
        float bv0 = bias[col], bv1 = bias[col + 1];
#pragma unroll
        for (int mf = 0; mf < 4; mf++) {
            int row = m0 + wm * 64 + mf * 16 + gr;
            float2 v0 = make_float2(acc[mf][nf][0] + bv0, acc[mf][nf][1] + bv1);
            float2 v1 = make_float2(acc[mf][nf][2] + bv0, acc[mf][nf][3] + bv1);
            *(float2*)&C[(size_t)row * Vsz + col] = v0;
            *(float2*)&C[(size_t)(row + 8) * Vsz + col] = v1;
        }
    }
}

// ---------------- host ----------------
extern "C" void kernel_launch(void* const* d_in, const int* in_sizes, int n_in,
                              void* d_out, int out_size) {
    (void)in_sizes; (void)out_size;
    const int* seq = (const int*)d_in[0];
    int o = n_in - 14;
    const float* emb  = (const float*)d_in[o + 0];
    const float* fc_b = (const float*)d_in[o + 1];
    const float* m1w  = (const float*)d_in[o + 2];
    const float* m1b  = (const float*)d_in[o + 3];
    const float* w1ih = (const float*)d_in[o + 4];
    const float* w1hh = (const float*)d_in[o + 5];
    const float* b1ih = (const float*)d_in[o + 6];
    const float* b1hh = (const float*)d_in[o + 7];
    const float* m2w  = (const float*)d_in[o + 8];
    const float* m2b  = (const float*)d_in[o + 9];
    const float* w2ih = (const float*)d_in[o + 10];
    const float* w2hh = (const float*)d_in[o + 11];
    const float* b2ih = (const float*)d_in[o + 12];
    const float* b2hh = (const float*)d_in[o + 13];

    float* outp = (float*)d_out;                          // [B][T][V]
    float* hidp = outp + (size_t)Bsz * Tlen * Vsz;        // [B][T][H]

    __nv_bfloat16 *embh, *embl, *hidh, *hidl;
    cudaGetSymbolAddress((void**)&embh, g_embh);
    cudaGetSymbolAddress((void**)&embl, g_embl);
    cudaGetSymbolAddress((void**)&hidh, g_hidh);
    cudaGetSymbolAddress((void**)&hidl, g_hidl);

    cudaFuncSetAttribute(mog_lstm_kernel,
                         cudaFuncAttributeMaxDynamicSharedMemorySize, SMEM_BYTES);
    cudaFuncSetAttribute(gemm_bf16x3_bias,
                         cudaFuncAttributeMaxDynamicSharedMemorySize, G_SMEM_BYTES);

    // split embedding (independent of recurrence result)
    split_bf16_kernel<<<2048, 256>>>(emb, embh, embl, (size_t)Vsz * Hdim / 4);

    mog_lstm_kernel<<<NB, NT, SMEM_BYTES>>>(seq, emb,
                                m1w, m1b, w1ih, w1hh, b1ih, b1hh,
                                m2w, m2b, w2ih, w2hh, b2ih, b2hh,
                                hidp);

    // split hidden states produced by the recurrence
    split_bf16_kernel<<<1024, 256>>>(hidp, hidh, hidl, (size_t)Bsz * Tlen * Hdim / 4);

    gemm_bf16x3_bias<<<dim3((Bsz * Tlen) / 128, Vsz / 128), 256, G_SMEM_BYTES>>>(fc_b, outp);
}

// round 9
// speedup vs baseline: 1.9753x; 1.1638x over previous
#include <cuda_runtime.h>
#include <cuda_bf16.h>
#include <math.h>
#include <stdint.h>

#define Bsz 32
#define Tlen 128
#define Hdim 1024
#define Vsz 32000
#define NB 128
#define NT 512

// ---------------- recurrence smem layout (bytes) ----------------
#define RTS 264                     // bf16 row stride (256 + 8 pad)
#define OFF_WH 0                    // W hi: 32 x 264 bf16 = 16896 B
#define OFF_WL 16896
#define OFF_XH 33792                // x hi: 32 x 264 bf16
#define OFF_XL 50688
#define OFF_PP 67584                // partials: 16 x 1024 floats = 65536 B
#define OFF_RD 133120               // reduced: 1024 floats
#define R_SMEM_BYTES 137216

// ---------------- device scratch ----------------
__device__ float g_XT[Tlen * Bsz * Hdim];        // [t][b][k]
__device__ float g_h1a[Bsz * Hdim], g_h1b[Bsz * Hdim];
__device__ float g_h2a[Bsz * Hdim], g_h2b[Bsz * Hdim];
__device__ float g_c1[Bsz * Hdim],  g_c2[Bsz * Hdim];
__device__ float g_x2[Bsz * Hdim];
__device__ float g_P[4 * Hdim * Bsz];            // mogrify cross-block partials [ky][j][b]
__device__ int g_ticket[32];
__device__ unsigned g_bar_count;
__device__ volatile unsigned g_bar_sense;

// bf16 hi/lo weight splits (one big arena)
// layout: m1w(5M) | m2w(5M) | w1ih(4M) | w1hh(4M) | w2ih(4M) | w2hh(4M)
#define WOFF_M1   0
#define WOFF_M2   5242880
#define WOFF_G1IH 10485760
#define WOFF_G1HH 14680064
#define WOFF_G2IH 18874368
#define WOFF_G2HH 23068672
#define WTOTAL    27262976
__device__ __nv_bfloat16 g_wh[WTOTAL];
__device__ __nv_bfloat16 g_wl[WTOTAL];

// bf16 hi/lo splits for logits GEMM
__device__ __nv_bfloat16 g_embh[(size_t)Vsz * Hdim];
__device__ __nv_bfloat16 g_embl[(size_t)Vsz * Hdim];
__device__ __nv_bfloat16 g_hidh[(size_t)Bsz * Tlen * Hdim];
__device__ __nv_bfloat16 g_hidl[(size_t)Bsz * Tlen * Hdim];

// ---------------- grid-wide barrier (sense reversing, replay-safe) ----------------
__device__ __forceinline__ void grid_barrier(unsigned& sense) {
    __threadfence();
    __syncthreads();
    if (threadIdx.x == 0) {
        unsigned s = sense ^ 1u;
        if (atomicAdd(&g_bar_count, 1u) == NB - 1u) {
            g_bar_count = 0u;
            __threadfence();
            g_bar_sense = s;
        } else {
            while (g_bar_sense != s) __nanosleep(32);
        }
    }
    __syncthreads();
    __threadfence();
    sense ^= 1u;
}

// ---------------- mma helper (validated fragment layout) ----------------
__device__ __forceinline__ void mma_bf16(float d[4], const uint32_t a[4],
                                         const uint32_t b[2]) {
    asm volatile(
        "mma.sync.aligned.m16n8k16.row.col.f32.bf16.bf16.f32 "
        "{%0,%1,%2,%3},{%4,%5,%6,%7},{%8,%9},{%0,%1,%2,%3};"
        : "+f"(d[0]), "+f"(d[1]), "+f"(d[2]), "+f"(d[3])
        : "r"(a[0]), "r"(a[1]), "r"(a[2]), "r"(a[3]), "r"(b[0]), "r"(b[1]));
}

__device__ __forceinline__ uint32_t pack_bf2(float a, float b) {
    __nv_bfloat162 t(__float2bfloat16_rn(a), __float2bfloat16_rn(b));
    return *(uint32_t*)&t;
}

// stage x chunk (fp32 [b][k] slice kb..kb+255) into smem bf16 hi/lo
__device__ __forceinline__ void stage_x(const float* __restrict__ src, int kb,
                                        __nv_bfloat16* XhS, __nv_bfloat16* XlS)
{
    int tid = threadIdx.x;
#pragma unroll
    for (int i = 0; i < 4; i++) {
        int idx = tid + i * NT;          // 0..2047 float4 cells
        int b = idx >> 6, q = idx & 63;
        float4 v = *(const float4*)&src[(size_t)b * Hdim + kb + q * 4];
        float hx = __bfloat162float(__float2bfloat16_rn(v.x));
        float hy = __bfloat162float(__float2bfloat16_rn(v.y));
        float hz = __bfloat162float(__float2bfloat16_rn(v.z));
        float hw = __bfloat162float(__float2bfloat16_rn(v.w));
        uint2 uh, ul;
        uh.x = pack_bf2(v.x, v.y);
        uh.y = pack_bf2(v.z, v.w);
        ul.x = pack_bf2(v.x - hx, v.y - hy);
        ul.y = pack_bf2(v.z - hz, v.w - hw);
        *(uint2*)&XhS[b * RTS + q * 4] = uh;
        *(uint2*)&XlS[b * RTS + q * 4] = ul;
    }
}

// warp fragment compute: 2 m-tiles x 4 n-tiles, 3 compensation terms
__device__ __forceinline__ void frag_mma(const __nv_bfloat16* WhS, const __nv_bfloat16* WlS,
                                         const __nv_bfloat16* XhS, const __nv_bfloat16* XlS,
                                         int kw, int gr, int tig, float acc[2][4][4])
{
    uint32_t ah[2][4], al[2][4], bh[4][2], bl[4][2];
#pragma unroll
    for (int mf = 0; mf < 2; mf++) {
        int base = (mf * 16 + gr) * RTS + kw + 2 * tig;
        ah[mf][0] = *(const uint32_t*)&WhS[base];
        ah[mf][1] = *(const uint32_t*)&WhS[base + 8 * RTS];
        ah[mf][2] = *(const uint32_t*)&WhS[base + 8];
        ah[mf][3] = *(const uint32_t*)&WhS[base + 8 * RTS + 8];
        al[mf][0] = *(const uint32_t*)&WlS[base];
        al[mf][1] = *(const uint32_t*)&WlS[base + 8 * RTS];
        al[mf][2] = *(const uint32_t*)&WlS[base + 8];
        al[mf][3] = *(const uint32_t*)&WlS[base + 8 * RTS + 8];
    }
#pragma unroll
    for (int nf = 0; nf < 4; nf++) {
        int base = (nf * 8 + gr) * RTS + kw + 2 * tig;
        bh[nf][0] = *(const uint32_t*)&XhS[base];
        bh[nf][1] = *(const uint32_t*)&XhS[base + 8];
        bl[nf][0] = *(const uint32_t*)&XlS[base];
        bl[nf][1] = *(const uint32_t*)&XlS[base + 8];
    }
#pragma unroll
    for (int mf = 0; mf < 2; mf++)
#pragma unroll
        for (int nf = 0; nf < 4; nf++) {
            mma_bf16(acc[mf][nf], ah[mf], bh[nf]);
            mma_bf16(acc[mf][nf], al[mf], bh[nf]);
            mma_bf16(acc[mf][nf], ah[mf], bl[nf]);
        }
}

// write per-warp fragment partials into P[w][j][b]
__device__ __forceinline__ void write_partials(float* P, int w, int gr, int tig,
                                               float acc[2][4][4])
{
#pragma unroll
    for (int mf = 0; mf < 2; mf++)
#pragma unroll
        for (int nf = 0; nf < 4; nf++) {
            int cc = nf * 8 + 2 * tig;
            *(float2*)&P[w * 1024 + (mf * 16 + gr) * 32 + cc] =
                make_float2(acc[mf][nf][0], acc[mf][nf][1]);
            *(float2*)&P[w * 1024 + (mf * 16 + gr + 8) * 32 + cc] =
                make_float2(acc[mf][nf][2], acc[mf][nf][3]);
        }
}

// ---------------- mogrify stage: dst *= 2*sigmoid(W @ src + bias) ----------------
// block = (j-group of 32 rows) x (k-slice of 256)
__device__ void mog_stage(const __nv_bfloat16* __restrict__ Wh,
                          const __nv_bfloat16* __restrict__ Wl,
                          const float* __restrict__ bias,
                          const float* __restrict__ src, float* __restrict__ dst,
                          int mog_epoch, char* sm, unsigned& sense)
{
    __nv_bfloat16* WhS = (__nv_bfloat16*)(sm + OFF_WH);
    __nv_bfloat16* WlS = (__nv_bfloat16*)(sm + OFF_WL);
    __nv_bfloat16* XhS = (__nv_bfloat16*)(sm + OFF_XH);
    __nv_bfloat16* XlS = (__nv_bfloat16*)(sm + OFF_XL);
    float* P = (float*)(sm + OFF_PP);

    int tid = threadIdx.x, lane = tid & 31, w = tid >> 5;
    int gr = lane >> 2, tig = lane & 3;
    int jgrp = blockIdx.x >> 2, ky = blockIdx.x & 3;
    int j0 = jgrp * 32, kb = ky * 256;

    // stage W hi/lo: 32 rows x 256 k
#pragma unroll
    for (int i = 0; i < 2; i++) {
        int idx = tid + i * NT;
        int r = idx >> 5, u4 = idx & 31;
        size_t go = (size_t)(j0 + r) * Hdim + kb + u4 * 8;
        *(uint4*)&WhS[r * RTS + u4 * 8] = *(const uint4*)&Wh[go];
        *(uint4*)&WlS[r * RTS + u4 * 8] = *(const uint4*)&Wl[go];
    }
    stage_x(src, kb, XhS, XlS);
    __syncthreads();

    float acc[2][4][4];
#pragma unroll
    for (int a = 0; a < 2; a++)
#pragma unroll
        for (int b = 0; b < 4; b++)
#pragma unroll
            for (int q = 0; q < 4; q++) acc[a][b][q] = 0.f;

    frag_mma(WhS, WlS, XhS, XlS, w * 16, gr, tig, acc);
    write_partials(P, w, gr, tig, acc);
    __syncthreads();

    // 16-warp reduce -> g_P[ky]
#pragma unroll
    for (int i = 0; i < 2; i++) {
        int cell = tid + i * NT;     // [jloc][b]
        float s = 0.f;
#pragma unroll
        for (int ww = 0; ww < 16; ww++) s += P[ww * 1024 + cell];
        g_P[(size_t)ky * (Hdim * Bsz) + (size_t)(j0 + (cell >> 5)) * 32 + (cell & 31)] = s;
    }

    // 4-block sub-barrier among the k-slices of this j-group
    __threadfence();
    __syncthreads();
    if (tid == 0) {
        atomicAdd(&g_ticket[jgrp], 1);
        int target = 4 * mog_epoch;
        while (*(volatile int*)&g_ticket[jgrp] < target) __nanosleep(32);
    }
    __syncthreads();
    __threadfence();

    // distributed finalize: this block owns rows j0 + ky*8 .. +7
    if (tid < 256) {
        int jl = tid & 7, b = tid >> 3;
        int j = j0 + ky * 8 + jl;
        size_t po = (size_t)j * 32 + b;
        const size_t S = (size_t)Hdim * Bsz;
        float s = g_P[po] + g_P[S + po] + g_P[2 * S + po] + g_P[3 * S + po] + bias[j];
        dst[(size_t)b * Hdim + j] *= 2.f / (1.f + __expf(-s));
    }
    grid_barrier(sense);
}

// ---------------- LSTM gate stage: block owns 8 units x 4 gates, full K ----------------
__device__ void gate_stage(const __nv_bfloat16* __restrict__ Wih_h,
                           const __nv_bfloat16* __restrict__ Wih_l,
                           const __nv_bfloat16* __restrict__ Whh_h,
                           const __nv_bfloat16* __restrict__ Whh_l,
                           const float* __restrict__ bih, const float* __restrict__ bhh,
                           const float* __restrict__ xsrc, const float* __restrict__ hsrc,
                           float* __restrict__ cSt, float* __restrict__ hDst,
                           float* __restrict__ x2copy, float* __restrict__ hidOut, int t,
                           char* sm, unsigned& sense)
{
    __nv_bfloat16* WhS = (__nv_bfloat16*)(sm + OFF_WH);
    __nv_bfloat16* WlS = (__nv_bfloat16*)(sm + OFF_WL);
    __nv_bfloat16* XhS = (__nv_bfloat16*)(sm + OFF_XH);
    __nv_bfloat16* XlS = (__nv_bfloat16*)(sm + OFF_XL);
    float* P   = (float*)(sm + OFF_PP);
    float* Red = (float*)(sm + OFF_RD);

    int tid = threadIdx.x, lane = tid & 31, w = tid >> 5;
    int gr = lane >> 2, tig = lane & 3;
    int j0u = blockIdx.x * 8;

    float acc[2][4][4];
#pragma unroll
    for (int a = 0; a < 2; a++)
#pragma unroll
        for (int b = 0; b < 4; b++)
#pragma unroll
            for (int q = 0; q < 4; q++) acc[a][b][q] = 0.f;

    for (int c = 0; c < 8; c++) {
        const __nv_bfloat16* Wmh = (c < 4) ? Wih_h : Whh_h;
        const __nv_bfloat16* Wml = (c < 4) ? Wih_l : Whh_l;
        const float* S = (c < 4) ? xsrc : hsrc;
        int cbase = (c & 3) * 256;
        __syncthreads();     // previous chunk fragment reads complete
        // stage W: local rows r -> global row (r>>3)*Hdim + j0u + (r&7)
#pragma unroll
        for (int i = 0; i < 2; i++) {
            int idx = tid + i * NT;
            int r = idx >> 5, u4 = idx & 31;
            int grow = (r >> 3) * Hdim + j0u + (r & 7);
            size_t go = (size_t)grow * Hdim + cbase + u4 * 8;
            *(uint4*)&WhS[r * RTS + u4 * 8] = *(const uint4*)&Wmh[go];
            *(uint4*)&WlS[r * RTS + u4 * 8] = *(const uint4*)&Wml[go];
        }
        stage_x(S, cbase, XhS, XlS);
        __syncthreads();
        frag_mma(WhS, WlS, XhS, XlS, w * 16, gr, tig, acc);
    }

    write_partials(P, w, gr, tig, acc);
    __syncthreads();
#pragma unroll
    for (int i = 0; i < 2; i++) {
        int cell = tid + i * NT;
        float s = 0.f;
#pragma unroll
        for (int ww = 0; ww < 16; ww++) s += P[ww * 1024 + cell];
        Red[cell] = s;
    }
    __syncthreads();

    // fused LSTM pointwise: thread -> (unit u, batch b)
    if (tid < 256) {
        int u = tid & 7, b = tid >> 3;
        int j = j0u + u;
        float gi = Red[(u) * 32 + b]      + bih[j]            + bhh[j];
        float gf = Red[(8 + u) * 32 + b]  + bih[Hdim + j]     + bhh[Hdim + j];
        float gg = Red[(16 + u) * 32 + b] + bih[2 * Hdim + j] + bhh[2 * Hdim + j];
        float go = Red[(24 + u) * 32 + b] + bih[3 * Hdim + j] + bhh[3 * Hdim + j];

        float si = 1.f / (1.f + __expf(-gi));
        float sf = 1.f / (1.f + __expf(-gf));
        float tg = tanhf(gg);
        float so = 1.f / (1.f + __expf(-go));

        size_t g = (size_t)b * Hdim + j;
        float cc = sf * cSt[g] + si * tg;
        float h = so * tanhf(cc);
        cSt[g] = cc;
        hDst[g] = h;
        if (x2copy) x2copy[g] = h;
        if (hidOut) hidOut[(size_t)b * Tlen * Hdim + (size_t)t * Hdim + j] = h;
    }
    grid_barrier(sense);
}

// ---------------- persistent recurrence kernel ----------------
__global__ __launch_bounds__(NT, 1) void mog_lstm_kernel(
    const int* __restrict__ seq, const float* __restrict__ emb,
    const float* __restrict__ m1b, const float* __restrict__ b1ih,
    const float* __restrict__ b1hh, const float* __restrict__ m2b,
    const float* __restrict__ b2ih, const float* __restrict__ b2hh,
    float* __restrict__ hidp)
{
    extern __shared__ char sm[];
    int tid = threadIdx.x;
    int bid = blockIdx.x;
    unsigned sense = 0;

    for (int g = bid * NT + tid; g < Bsz * Hdim; g += NB * NT) {
        g_h1a[g] = 0.f; g_h1b[g] = 0.f; g_h2a[g] = 0.f; g_h2b[g] = 0.f;
        g_c1[g] = 0.f;  g_c2[g] = 0.f;
    }
    {
        int t = bid;   // embedding gather: XT[t][b][k]
        for (int idx = tid; idx < Bsz * Hdim; idx += NT) {
            int b = idx >> 10, k = idx & 1023;
            int id = seq[b * Tlen + t];
            g_XT[((size_t)t * Bsz + b) * Hdim + k] = emb[(size_t)id * Hdim + k];
        }
    }
    grid_barrier(sense);

    int mog_epoch = 0;
    for (int t = 0; t < Tlen; t++) {
        float* xt  = g_XT + (size_t)t * Bsz * Hdim;
        float* h1s = (t & 1) ? g_h1b : g_h1a;
        float* h1d = (t & 1) ? g_h1a : g_h1b;
        float* h2s = (t & 1) ? g_h2b : g_h2a;
        float* h2d = (t & 1) ? g_h2a : g_h2b;

        for (int i = 0; i < 5; i++) {
            mog_epoch++;
            const float* src = (i & 1) ? (const float*)xt : (const float*)h1s;
            float* dst = (i & 1) ? h1s : xt;
            mog_stage(g_wh + WOFF_M1 + (size_t)i * Hdim * Hdim,
                      g_wl + WOFF_M1 + (size_t)i * Hdim * Hdim,
                      m1b + i * Hdim, src, dst, mog_epoch, sm, sense);
        }
        gate_stage(g_wh + WOFF_G1IH, g_wl + WOFF_G1IH,
                   g_wh + WOFF_G1HH, g_wl + WOFF_G1HH,
                   b1ih, b1hh, xt, h1s, g_c1, h1d, g_x2, nullptr, t, sm, sense);

        for (int i = 0; i < 5; i++) {
            mog_epoch++;
            const float* src = (i & 1) ? (const float*)g_x2 : (const float*)h2s;
            float* dst = (i & 1) ? h2s : g_x2;
            mog_stage(g_wh + WOFF_M2 + (size_t)i * Hdim * Hdim,
                      g_wl + WOFF_M2 + (size_t)i * Hdim * Hdim,
                      m2b + i * Hdim, src, dst, mog_epoch, sm, sense);
        }
        gate_stage(g_wh + WOFF_G2IH, g_wl + WOFF_G2IH,
                   g_wh + WOFF_G2HH, g_wl + WOFF_G2HH,
                   b2ih, b2hh, g_x2, h2s, g_c2, h2d, nullptr, hidp, t, sm, sense);
    }
    grid_barrier(sense);   // even barrier count: sense restored for replay

    if (bid < 32 && tid == 0) g_ticket[bid] = 0;
}

// ================= bf16 hi/lo split =================
__global__ void split_bf16_kernel(const float* __restrict__ src,
                                  __nv_bfloat16* __restrict__ hi,
                                  __nv_bfloat16* __restrict__ lo, size_t n4)
{
    for (size_t i = blockIdx.x * blockDim.x + threadIdx.x; i < n4;
         i += (size_t)gridDim.x * blockDim.x) {
        float4 v = *(const float4*)(src + i * 4);
        __nv_bfloat16 h0 = __float2bfloat16_rn(v.x);
        __nv_bfloat16 h1 = __float2bfloat16_rn(v.y);
        __nv_bfloat16 h2 = __float2bfloat16_rn(v.z);
        __nv_bfloat16 h3 = __float2bfloat16_rn(v.w);
        __nv_bfloat16 l0 = __float2bfloat16_rn(v.x - __bfloat162float(h0));
        __nv_bfloat16 l1 = __float2bfloat16_rn(v.y - __bfloat162float(h1));
        __nv_bfloat16 l2 = __float2bfloat16_rn(v.z - __bfloat162float(h2));
        __nv_bfloat16 l3 = __float2bfloat16_rn(v.w - __bfloat162float(h3));
        __nv_bfloat162* hp = (__nv_bfloat162*)(hi + i * 4);
        __nv_bfloat162* lp = (__nv_bfloat162*)(lo + i * 4);
        hp[0] = __nv_bfloat162(h0, h1);
        hp[1] = __nv_bfloat162(h2, h3);
        lp[0] = __nv_bfloat162(l0, l1);
        lp[1] = __nv_bfloat162(l2, l3);
    }
}

// ================= bf16x3 legacy-mma logits GEMM (unchanged from R8) =================
#define GTS 72
#define G_SMEM_BYTES (4 * 128 * GTS * 2)

__global__ __launch_bounds__(256, 2) void gemm_bf16x3_bias(
    const float* __restrict__ bias, float* __restrict__ C)
{
    extern __shared__ __nv_bfloat16 gs[];
    __nv_bfloat16* Ahs = gs;
    __nv_bfloat16* Als = Ahs + 128 * GTS;
    __nv_bfloat16* Bhs = Als + 128 * GTS;
    __nv_bfloat16* Bls = Bhs + 128 * GTS;

    int tid = threadIdx.x;
    int lane = tid & 31, wrp = tid >> 5;
    int wm = wrp & 1, wn = wrp >> 1;
    int gr = lane >> 2, tig = lane & 3;
    int m0 = blockIdx.x * 128;
    int n0 = blockIdx.y * 128;

    const __nv_bfloat16* Ahg = g_hidh + (size_t)m0 * Hdim;
    const __nv_bfloat16* Alg = g_hidl + (size_t)m0 * Hdim;
    const __nv_bfloat16* Bhg = g_embh + (size_t)n0 * Hdim;
    const __nv_bfloat16* Blg = g_embl + (size_t)n0 * Hdim;

    float acc[4][4][4];
#pragma unroll
    for (int i = 0; i < 4; i++)
#pragma unroll
        for (int j = 0; j < 4; j++)
#pragma unroll
            for (int q = 0; q < 4; q++) acc[i][j][q] = 0.f;

    for (int kc = 0; kc < Hdim; kc += 64) {
        __syncthreads();
#pragma unroll
        for (int i = 0; i < 4; i++) {
            int idx = tid + i * 256;
            int r = idx >> 3, u = idx & 7;
            int so = r * GTS + u * 8;
            size_t go = (size_t)r * Hdim + kc + u * 8;
            *(uint4*)&Ahs[so] = *(const uint4*)&Ahg[go];
            *(uint4*)&Als[so] = *(const uint4*)&Alg[go];
            *(uint4*)&Bhs[so] = *(const uint4*)&Bhg[go];
            *(uint4*)&Bls[so] = *(const uint4*)&Blg[go];
        }
        __syncthreads();

#pragma unroll
        for (int ks = 0; ks < 4; ks++) {
            int kb = ks * 16;
            uint32_t ah[4][4], al[4][4], bh[4][2], bl[4][2];
#pragma unroll
            for (int mf = 0; mf < 4; mf++) {
                int base = (wm * 64 + mf * 16 + gr) * GTS + kb + 2 * tig;
                ah[mf][0] = *(const uint32_t*)&Ahs[base];
                ah[mf][1] = *(const uint32_t*)&Ahs[base + 8 * GTS];
                ah[mf][2] = *(const uint32_t*)&Ahs[base + 8];
                ah[mf][3] = *(const uint32_t*)&Ahs[base + 8 * GTS + 8];
                al[mf][0] = *(const uint32_t*)&Als[base];
                al[mf][1] = *(const uint32_t*)&Als[base + 8 * GTS];
                al[mf][2] = *(const uint32_t*)&Als[base + 8];
                al[mf][3] = *(const uint32_t*)&Als[base + 8 * GTS + 8];
            }
#pragma unroll
            for (int nf = 0; nf < 4; nf++) {
                int base = (wn * 32 + nf * 8 + gr) * GTS + kb + 2 * tig;
                bh[nf][0] = *(const uint32_t*)&Bhs[base];
                bh[nf][1] = *(const uint32_t*)&Bhs[base + 8];
                bl[nf][0] = *(const uint32_t*)&Bls[base];
                bl[nf][1] = *(const uint32_t*)&Bls[base + 8];
            }
#pragma unroll
            for (int mf = 0; mf < 4; mf++)
#pragma unroll
                for (int nf = 0; nf < 4; nf++) {
                    mma_bf16(acc[mf][nf], ah[mf], bh[nf]);
                    mma_bf16(acc[mf][nf], al[mf], bh[nf]);
                    mma_bf16(acc[mf][nf], ah[mf], bl[nf]);
                }
        }
    }

#pragma unroll
    for (int nf = 0; nf < 4; nf++) {
        int col = n0 + wn * 32 + nf * 8 + 2 * tig;
        float bv0 = bias[col], bv1 = bias[col + 1];
#pragma unroll
        for (int mf = 0; mf < 4; mf++) {
            int row = m0 + wm * 64 + mf * 16 + gr;
            float2 v0 = make_float2(acc[mf][nf][0] + bv0, acc[mf][nf][1] + bv1);
            float2 v1 = make_float2(acc[mf][nf][2] + bv0, acc[mf][nf][3] + bv1);
            *(float2*)&C[(size_t)row * Vsz + col] = v0;
            *(float2*)&C[(size_t)(row + 8) * Vsz + col] = v1;
        }
    }
}

// ---------------- host ----------------
extern "C" void kernel_launch(void* const* d_in, const int* in_sizes, int n_in,
                              void* d_out, int out_size) {
    (void)in_sizes; (void)out_size;
    const int* seq = (const int*)d_in[0];
    int o = n_in - 14;
    const float* emb  = (const float*)d_in[o + 0];
    const float* fc_b = (const float*)d_in[o + 1];
    const float* m1w  = (const float*)d_in[o + 2];
    const float* m1b  = (const float*)d_in[o + 3];
    const float* w1ih = (const float*)d_in[o + 4];
    const float* w1hh = (const float*)d_in[o + 5];
    const float* b1ih = (const float*)d_in[o + 6];
    const float* b1hh = (const float*)d_in[o + 7];
    const float* m2w  = (const float*)d_in[o + 8];
    const float* m2b  = (const float*)d_in[o + 9];
    const float* w2ih = (const float*)d_in[o + 10];
    const float* w2hh = (const float*)d_in[o + 11];
    const float* b2ih = (const float*)d_in[o + 12];
    const float* b2hh = (const float*)d_in[o + 13];

    float* outp = (float*)d_out;                          // [B][T][V]
    float* hidp = outp + (size_t)Bsz * Tlen * Vsz;        // [B][T][H]

    __nv_bfloat16 *embh, *embl, *hidh, *hidl, *wh, *wl;
    cudaGetSymbolAddress((void**)&embh, g_embh);
    cudaGetSymbolAddress((void**)&embl, g_embl);
    cudaGetSymbolAddress((void**)&hidh, g_hidh);
    cudaGetSymbolAddress((void**)&hidl, g_hidl);
    cudaGetSymbolAddress((void**)&wh, g_wh);
    cudaGetSymbolAddress((void**)&wl, g_wl);

    cudaFuncSetAttribute(mog_lstm_kernel,
                         cudaFuncAttributeMaxDynamicSharedMemorySize, R_SMEM_BYTES);
    cudaFuncSetAttribute(gemm_bf16x3_bias,
                         cudaFuncAttributeMaxDynamicSharedMemorySize, G_SMEM_BYTES);

    // split weights into bf16 hi/lo arena
    split_bf16_kernel<<<512, 256>>>(m1w,  wh + WOFF_M1,   wl + WOFF_M1,   (size_t)5 * Hdim * Hdim / 4);
    split_bf16_kernel<<<512, 256>>>(m2w,  wh + WOFF_M2,   wl + WOFF_M2,   (size_t)5 * Hdim * Hdim / 4);
    split_bf16_kernel<<<512, 256>>>(w1ih, wh + WOFF_G1IH, wl + WOFF_G1IH, (size_t)4 * Hdim * Hdim / 4);
    split_bf16_kernel<<<512, 256>>>(w1hh, wh + WOFF_G1HH, wl + WOFF_G1HH, (size_t)4 * Hdim * Hdim / 4);
    split_bf16_kernel<<<512, 256>>>(w2ih, wh + WOFF_G2IH, wl + WOFF_G2IH, (size_t)4 * Hdim * Hdim / 4);
    split_bf16_kernel<<<512, 256>>>(w2hh, wh + WOFF_G2HH, wl + WOFF_G2HH, (size_t)4 * Hdim * Hdim / 4);

    // split embedding (independent of recurrence result)
    split_bf16_kernel<<<2048, 256>>>(emb, embh, embl, (size_t)Vsz * Hdim / 4);

    mog_lstm_kernel<<<NB, NT, R_SMEM_BYTES>>>(seq, emb,
                                              m1b, b1ih, b1hh, m2b, b2ih, b2hh, hidp);

    // split hidden states produced by the recurrence
    split_bf16_kernel<<<1024, 256>>>(hidp, hidh, hidl, (size_t)Bsz * Tlen * Hdim / 4);

    gemm_bf16x3_bias<<<dim3((Bsz * Tlen) / 128, Vsz / 128), 256, G_SMEM_BYTES>>>(fc_b, outp);
}

// round 11
// speedup vs baseline: 1.9933x; 1.0091x over previous
#include <cuda_runtime.h>
#include <cuda_bf16.h>
#include <math.h>
#include <stdint.h>

#define Bsz 32
#define Tlen 128
#define Hdim 1024
#define Vsz 32000
#define NB 128
#define NT 512

// ---------------- recurrence smem layout (byte offsets) ----------------
#define RTS  264                    // bf16 elems per row (256 + 8 pad)
#define RTSB (RTS * 2)              // 528 bytes per row
#define SW_WH(b) ((b) * 33792)
#define SW_WL(b) ((b) * 33792 + 16896)
#define SX_H(b) (67584 + (b) * 33792)
#define SX_L(b) (67584 + (b) * 33792 + 16896)
#define SP_OFF   135168             // partials: 16 warps x 32 rows x 32 b floats
#define SRED_OFF 200704             // reduced: 1024 floats
#define R_SMEM_BYTES 204800

// ---------------- device scratch ----------------
__device__ float g_XT[Tlen * Bsz * Hdim];        // [t][b][k]
__device__ float g_h1a[Bsz * Hdim], g_h1b[Bsz * Hdim];
__device__ float g_h2a[Bsz * Hdim], g_h2b[Bsz * Hdim];
__device__ float g_c1[Bsz * Hdim],  g_c2[Bsz * Hdim];
__device__ float g_xA[Bsz * Hdim], g_xB[Bsz * Hdim];
__device__ float g_hA[Bsz * Hdim], g_hB[Bsz * Hdim];
__device__ unsigned g_bar_count;
__device__ volatile unsigned g_bar_sense;

// bf16 hi/lo weight arena
#define WOFF_M1   0
#define WOFF_M2   5242880
#define WOFF_G1IH 10485760
#define WOFF_G1HH 14680064
#define WOFF_G2IH 18874368
#define WOFF_G2HH 23068672
#define WTOTAL    27262976
__device__ __nv_bfloat16 g_wh[WTOTAL];
__device__ __nv_bfloat16 g_wl[WTOTAL];

// bf16 hi/lo splits for logits GEMM
__device__ __nv_bfloat16 g_embh[(size_t)Vsz * Hdim];
__device__ __nv_bfloat16 g_embl[(size_t)Vsz * Hdim];
__device__ __nv_bfloat16 g_hidh[(size_t)Bsz * Tlen * Hdim];
__device__ __nv_bfloat16 g_hidl[(size_t)Bsz * Tlen * Hdim];

// ---------------- grid-wide barrier (sense reversing, replay-safe) ----------------
__device__ __forceinline__ void grid_barrier(unsigned& sense) {
    __threadfence();
    __syncthreads();
    if (threadIdx.x == 0) {
        unsigned s = sense ^ 1u;
        if (atomicAdd(&g_bar_count, 1u) == NB - 1u) {
            g_bar_count = 0u;
            __threadfence();
            g_bar_sense = s;
        } else {
            while (g_bar_sense != s) __nanosleep(32);
        }
    }
    __syncthreads();
    __threadfence();
    sense ^= 1u;
}

// ---------------- helpers ----------------
__device__ __forceinline__ void mma_bf16(float d[4], const uint32_t a[4],
                                         const uint32_t b[2]) {
    asm volatile(
        "mma.sync.aligned.m16n8k16.row.col.f32.bf16.bf16.f32 "
        "{%0,%1,%2,%3},{%4,%5,%6,%7},{%8,%9},{%0,%1,%2,%3};"
        : "+f"(d[0]), "+f"(d[1]), "+f"(d[2]), "+f"(d[3])
        : "r"(a[0]), "r"(a[1]), "r"(a[2]), "r"(a[3]), "r"(b[0]), "r"(b[1]));
}

__device__ __forceinline__ void cp16(uint32_t saddr, const void* g) {
    asm volatile("cp.async.cg.shared.global [%0], [%1], 16;" :: "r"(saddr), "l"(g));
}
#define CP_COMMIT() asm volatile("cp.async.commit_group;" ::: "memory")
#define CP_WAIT0()  asm volatile("cp.async.wait_group 0;"  ::: "memory")

__device__ __forceinline__ uint32_t pack_bf2(float a, float b) {
    __nv_bfloat162 t(__float2bfloat16_rn(a), __float2bfloat16_rn(b));
    return *(uint32_t*)&t;
}

// prefetch 32b x 256k fp32 activation chunk into regs
__device__ __forceinline__ void x_prefetch(const float* __restrict__ src, int kb,
                                           float4 xr[4]) {
    int tid = threadIdx.x;
#pragma unroll
    for (int i = 0; i < 4; i++) {
        int idx = tid + i * NT;
        int b = idx >> 6, q = idx & 63;
        xr[i] = *(const float4*)&src[(size_t)b * Hdim + kb + q * 4];
    }
}
// convert regs -> smem bf16 hi/lo chunk buffer
__device__ __forceinline__ void x_store(char* sm, int buf, const float4 xr[4]) {
    int tid = threadIdx.x;
    char* XH = sm + SX_H(buf);
    char* XL = sm + SX_L(buf);
#pragma unroll
    for (int i = 0; i < 4; i++) {
        int idx = tid + i * NT;
        int b = idx >> 6, q = idx & 63;
        float4 v = xr[i];
        float hx = __bfloat162float(__float2bfloat16_rn(v.x));
        float hy = __bfloat162float(__float2bfloat16_rn(v.y));
        float hz = __bfloat162float(__float2bfloat16_rn(v.z));
        float hw = __bfloat162float(__float2bfloat16_rn(v.w));
        uint2 uh = make_uint2(pack_bf2(v.x, v.y), pack_bf2(v.z, v.w));
        uint2 ul = make_uint2(pack_bf2(v.x - hx, v.y - hy), pack_bf2(v.z - hz, v.w - hw));
        int off = b * RTSB + q * 8;
        *(uint2*)(XH + off) = uh;
        *(uint2*)(XL + off) = ul;
    }
}

// warp fragment compute over one staged chunk. MF = 1 (mog) or 2 (gate)
template <int MF>
__device__ __forceinline__ void frag_mma(char* sm, int buf, int kw, int gr, int tig,
                                         float acc[MF][4][4]) {
    const __nv_bfloat16* WhS = (const __nv_bfloat16*)(sm + SW_WH(buf));
    const __nv_bfloat16* WlS = (const __nv_bfloat16*)(sm + SW_WL(buf));
    const __nv_bfloat16* XhS = (const __nv_bfloat16*)(sm + SX_H(buf));
    const __nv_bfloat16* XlS = (const __nv_bfloat16*)(sm + SX_L(buf));

    uint32_t ah[MF][4], al[MF][4], bh[4][2], bl[4][2];
#pragma unroll
    for (int mf = 0; mf < MF; mf++) {
        int base = (mf * 16 + gr) * RTS + kw + 2 * tig;
        ah[mf][0] = *(const uint32_t*)&WhS[base];
        ah[mf][1] = *(const uint32_t*)&WhS[base + 8 * RTS];
        ah[mf][2] = *(const uint32_t*)&WhS[base + 8];
        ah[mf][3] = *(const uint32_t*)&WhS[base + 8 * RTS + 8];
        al[mf][0] = *(const uint32_t*)&WlS[base];
        al[mf][1] = *(const uint32_t*)&WlS[base + 8 * RTS];
        al[mf][2] = *(const uint32_t*)&WlS[base + 8];
        al[mf][3] = *(const uint32_t*)&WlS[base + 8 * RTS + 8];
    }
#pragma unroll
    for (int nf = 0; nf < 4; nf++) {
        int base = (nf * 8 + gr) * RTS + kw + 2 * tig;
        bh[nf][0] = *(const uint32_t*)&XhS[base];
        bh[nf][1] = *(const uint32_t*)&XhS[base + 8];
        bl[nf][0] = *(const uint32_t*)&XlS[base];
        bl[nf][1] = *(const uint32_t*)&XlS[base + 8];
    }
#pragma unroll
    for (int mf = 0; mf < MF; mf++)
#pragma unroll
        for (int nf = 0; nf < 4; nf++) {
            mma_bf16(acc[mf][nf], ah[mf], bh[nf]);
            mma_bf16(acc[mf][nf], al[mf], bh[nf]);
            mma_bf16(acc[mf][nf], ah[mf], bl[nf]);
        }
}

template <int MF>
__device__ __forceinline__ void write_partials(float* P, int w, int gr, int tig,
                                               float acc[MF][4][4]) {
#pragma unroll
    for (int mf = 0; mf < MF; mf++)
#pragma unroll
        for (int nf = 0; nf < 4; nf++) {
            int cc = nf * 8 + 2 * tig;
            *(float2*)&P[w * 1024 + (mf * 16 + gr) * 32 + cc] =
                make_float2(acc[mf][nf][0], acc[mf][nf][1]);
            *(float2*)&P[w * 1024 + (mf * 16 + gr + 8) * 32 + cc] =
                make_float2(acc[mf][nf][2], acc[mf][nf][3]);
        }
}

// ---------------- mogrify stage (full-K, 8 rows per block, non-inplace) ----------------
// dstNew[b][j] = mult[b][j] * 2*sigmoid( (W @ src)[j][b] + bias[j] )
__device__ void mog_stage(const __nv_bfloat16* __restrict__ Wh,
                          const __nv_bfloat16* __restrict__ Wl,
                          const float* __restrict__ bias,
                          const float* __restrict__ src,
                          const float* __restrict__ mult,
                          float* __restrict__ dstNew,
                          char* sm, uint32_t smb, unsigned& sense)
{
    int tid = threadIdx.x, lane = tid & 31, w = tid >> 5;
    int gr = lane >> 2, tig = lane & 3;
    int j0m = blockIdx.x * 8;
    float* P = (float*)(sm + SP_OFF);

    float acc[1][4][4];
#pragma unroll
    for (int nf = 0; nf < 4; nf++)
#pragma unroll
        for (int q = 0; q < 4; q++) acc[0][nf][q] = 0.f;

    // W staging for one chunk: 8 rows x 512 B (H) + same (L) = 512 cp16's
    int t2 = tid & 255;
    int wr = t2 >> 5, wu = t2 & 31;           // row 0..7, 16B unit 0..31
    size_t wgbase = (size_t)(j0m + wr) * Hdim + wu * 8;
    uint32_t wsoff = wr * RTSB + wu * 16;

    // stage chunk 0
    {
        if (tid < 256) cp16(smb + SW_WH(0) + wsoff, Wh + wgbase);
        else           cp16(smb + SW_WL(0) + wsoff, Wl + wgbase);
        CP_COMMIT();
        float4 xr[4];
        x_prefetch(src, 0, xr);
        CP_WAIT0();
        x_store(sm, 0, xr);
        __syncthreads();
    }

#pragma unroll
    for (int c = 0; c < 4; c++) {
        int cb = c & 1, nb = (c + 1) & 1;
        float4 xr[4];
        if (c < 3) {
            int kb = (c + 1) * 256;
            if (tid < 256) cp16(smb + SW_WH(nb) + wsoff, Wh + wgbase + kb);
            else           cp16(smb + SW_WL(nb) + wsoff, Wl + wgbase + kb);
            CP_COMMIT();
            x_prefetch(src, kb, xr);
        }
        frag_mma<1>(sm, cb, w * 16, gr, tig, acc);
        if (c < 3) {
            CP_WAIT0();
            x_store(sm, nb, xr);
        }
        __syncthreads();
    }

    write_partials<1>(P, w, gr, tig, acc);
    __syncthreads();

    // reduce rows 0..7 (256 cells) + fused finalize
    if (tid < 256) {
        float s = 0.f;
#pragma unroll
        for (int ww = 0; ww < 16; ww++) s += P[ww * 1024 + tid];
        int jl = tid >> 5, b = tid & 31;
        int j = j0m + jl;
        s += bias[j];
        size_t o = (size_t)b * Hdim + j;
        dstNew[o] = mult[o] * (2.f / (1.f + __expf(-s)));
    }
    grid_barrier(sense);
}

// ---------------- LSTM gate stage (full-K, 8 units x 4 gates per block) ----------------
__device__ void gate_stage(const __nv_bfloat16* __restrict__ WihH,
                           const __nv_bfloat16* __restrict__ WihL,
                           const __nv_bfloat16* __restrict__ WhhH,
                           const __nv_bfloat16* __restrict__ WhhL,
                           const float* __restrict__ bih, const float* __restrict__ bhh,
                           const float* __restrict__ xsrc, const float* __restrict__ hsrc,
                           float* __restrict__ cSt, float* __restrict__ hDst,
                           float* __restrict__ hidOut, int t,
                           char* sm, uint32_t smb, unsigned& sense)
{
    int tid = threadIdx.x, lane = tid & 31, w = tid >> 5;
    int gr = lane >> 2, tig = lane & 3;
    int j0u = blockIdx.x * 8;
    float* P   = (float*)(sm + SP_OFF);
    float* Red = (float*)(sm + SRED_OFF);

    float acc[2][4][4];
#pragma unroll
    for (int mf = 0; mf < 2; mf++)
#pragma unroll
        for (int nf = 0; nf < 4; nf++)
#pragma unroll
            for (int q = 0; q < 4; q++) acc[mf][nf][q] = 0.f;

    // W staging for one chunk: 32 rows x 512 B, H+L -> 4 cp16 per thread (2 iters)
    int r0 = tid >> 5 + 0;   // placeholder (recomputed in loop)
    (void)r0;

    // stage chunk 0 (wih, x)
    {
#pragma unroll
        for (int i = 0; i < 2; i++) {
            int idx = tid + i * NT;              // 0..1023
            int r = idx >> 5, u = idx & 31;      // row 0..31, unit 0..31
            int grow = (r >> 3) * Hdim + j0u + (r & 7);
            size_t go = (size_t)grow * Hdim + u * 8;
            cp16(smb + SW_WH(0) + r * RTSB + u * 16, WihH + go);
            cp16(smb + SW_WL(0) + r * RTSB + u * 16, WihL + go);
        }
        CP_COMMIT();
        float4 xr[4];
        x_prefetch(xsrc, 0, xr);
        CP_WAIT0();
        x_store(sm, 0, xr);
        __syncthreads();
    }

#pragma unroll
    for (int c = 0; c < 8; c++) {
        int cb = c & 1, nb = (c + 1) & 1;
        float4 xr[4];
        if (c < 7) {
            int cn = c + 1;
            const __nv_bfloat16* WmH = (cn < 4) ? WihH : WhhH;
            const __nv_bfloat16* WmL = (cn < 4) ? WihL : WhhL;
            const float* S = (cn < 4) ? xsrc : hsrc;
            int cbase = (cn & 3) * 256;
#pragma unroll
            for (int i = 0; i < 2; i++) {
                int idx = tid + i * NT;
                int r = idx >> 5, u = idx & 31;
                int grow = (r >> 3) * Hdim + j0u + (r & 7);
                size_t go = (size_t)grow * Hdim + cbase + u * 8;
                cp16(smb + SW_WH(nb) + r * RTSB + u * 16, WmH + go);
                cp16(smb + SW_WL(nb) + r * RTSB + u * 16, WmL + go);
            }
            CP_COMMIT();
            x_prefetch(S, cbase, xr);
        }
        frag_mma<2>(sm, cb, w * 16, gr, tig, acc);
        if (c < 7) {
            CP_WAIT0();
            x_store(sm, nb, xr);
        }
        __syncthreads();
    }

    write_partials<2>(P, w, gr, tig, acc);
    __syncthreads();
#pragma unroll
    for (int i = 0; i < 2; i++) {
        int cell = tid + i * NT;
        float s = 0.f;
#pragma unroll
        for (int ww = 0; ww < 16; ww++) s += P[ww * 1024 + cell];
        Red[cell] = s;
    }
    __syncthreads();

    if (tid < 256) {
        int uu = tid & 7, b = tid >> 3;
        int j = j0u + uu;
        float gi = Red[(uu) * 32 + b]      + bih[j]            + bhh[j];
        float gf = Red[(8 + uu) * 32 + b]  + bih[Hdim + j]     + bhh[Hdim + j];
        float gg = Red[(16 + uu) * 32 + b] + bih[2 * Hdim + j] + bhh[2 * Hdim + j];
        float go = Red[(24 + uu) * 32 + b] + bih[3 * Hdim + j] + bhh[3 * Hdim + j];

        float si = 1.f / (1.f + __expf(-gi));
        float sf = 1.f / (1.f + __expf(-gf));
        float tg = tanhf(gg);
        float so = 1.f / (1.f + __expf(-go));

        size_t g = (size_t)b * Hdim + j;
        float cc = sf * cSt[g] + si * tg;
        float h = so * tanhf(cc);
        cSt[g] = cc;
        hDst[g] = h;
        if (hidOut) hidOut[(size_t)b * Tlen * Hdim + (size_t)t * Hdim + j] = h;
    }
    grid_barrier(sense);
}

// ---------------- persistent recurrence kernel ----------------
__global__ __launch_bounds__(NT, 1) void mog_lstm_kernel(
    const int* __restrict__ seq, const float* __restrict__ emb,
    const float* __restrict__ m1b, const float* __restrict__ b1ih,
    const float* __restrict__ b1hh, const float* __restrict__ m2b,
    const float* __restrict__ b2ih, const float* __restrict__ b2hh,
    float* __restrict__ hidp)
{
    extern __shared__ char sm[];
    uint32_t smb;
    asm("{ .reg .u64 t; cvta.to.shared.u64 t, %1; cvt.u32.u64 %0, t; }"
        : "=r"(smb) : "l"(sm));
    int tid = threadIdx.x;
    int bid = blockIdx.x;
    unsigned sense = 0;

    for (int g = bid * NT + tid; g < Bsz * Hdim; g += NB * NT) {
        g_h1a[g] = 0.f; g_h1b[g] = 0.f; g_h2a[g] = 0.f; g_h2b[g] = 0.f;
        g_c1[g] = 0.f;  g_c2[g] = 0.f;
    }
    {
        int t = bid;   // embedding gather: XT[t][b][k]
        for (int idx = tid; idx < Bsz * Hdim; idx += NT) {
            int b = idx >> 10, k = idx & 1023;
            int id = seq[b * Tlen + t];
            g_XT[((size_t)t * Bsz + b) * Hdim + k] = emb[(size_t)id * Hdim + k];
        }
    }
    grid_barrier(sense);

    const size_t MW = (size_t)Hdim * Hdim;
    for (int t = 0; t < Tlen; t++) {
        const float* xt = g_XT + (size_t)t * Bsz * Hdim;
        float* h1s = (t & 1) ? g_h1b : g_h1a;
        float* h1d = (t & 1) ? g_h1a : g_h1b;
        float* h2s = (t & 1) ? g_h2b : g_h2a;
        float* h2d = (t & 1) ? g_h2a : g_h2b;

        // ---- cell 1 mogrify (non-inplace buffer rotation) ----
        mog_stage(g_wh + WOFF_M1 + 0 * MW, g_wl + WOFF_M1 + 0 * MW, m1b + 0 * Hdim,
                  h1s, xt,   g_xA, sm, smb, sense);                   // x1 = f(h0)*x0
        mog_stage(g_wh + WOFF_M1 + 1 * MW, g_wl + WOFF_M1 + 1 * MW, m1b + 1 * Hdim,
                  g_xA, h1s, g_hA, sm, smb, sense);                   // h1 = f(x1)*h0
        mog_stage(g_wh + WOFF_M1 + 2 * MW, g_wl + WOFF_M1 + 2 * MW, m1b + 2 * Hdim,
                  g_hA, g_xA, g_xB, sm, smb, sense);                  // x2 = f(h1)*x1
        mog_stage(g_wh + WOFF_M1 + 3 * MW, g_wl + WOFF_M1 + 3 * MW, m1b + 3 * Hdim,
                  g_xB, g_hA, g_hB, sm, smb, sense);                  // h2 = f(x2)*h1
        mog_stage(g_wh + WOFF_M1 + 4 * MW, g_wl + WOFF_M1 + 4 * MW, m1b + 4 * Hdim,
                  g_hB, g_xB, g_xA, sm, smb, sense);                  // x3 = f(h2)*x2
        gate_stage(g_wh + WOFF_G1IH, g_wl + WOFF_G1IH,
                   g_wh + WOFF_G1HH, g_wl + WOFF_G1HH,
                   b1ih, b1hh, g_xA, g_hB, g_c1, h1d, nullptr, t, sm, smb, sense);

        // ---- cell 2 mogrify (x0' = new h1 = h1d) ----
        mog_stage(g_wh + WOFF_M2 + 0 * MW, g_wl + WOFF_M2 + 0 * MW, m2b + 0 * Hdim,
                  h2s, h1d,  g_xA, sm, smb, sense);
        mog_stage(g_wh + WOFF_M2 + 1 * MW, g_wl + WOFF_M2 + 1 * MW, m2b + 1 * Hdim,
                  g_xA, h2s, g_hA, sm, smb, sense);
        mog_stage(g_wh + WOFF_M2 + 2 * MW, g_wl + WOFF_M2 + 2 * MW, m2b + 2 * Hdim,
                  g_hA, g_xA, g_xB, sm, smb, sense);
        mog_stage(g_wh + WOFF_M2 + 3 * MW, g_wl + WOFF_M2 + 3 * MW, m2b + 3 * Hdim,
                  g_xB, g_hA, g_hB, sm, smb, sense);
        mog_stage(g_wh + WOFF_M2 + 4 * MW, g_wl + WOFF_M2 + 4 * MW, m2b + 4 * Hdim,
                  g_hB, g_xB, g_xA, sm, smb, sense);
        gate_stage(g_wh + WOFF_G2IH, g_wl + WOFF_G2IH,
                   g_wh + WOFF_G2HH, g_wl + WOFF_G2HH,
                   b2ih, b2hh, g_xA, g_hB, g_c2, h2d, hidp, t, sm, smb, sense);
    }
    grid_barrier(sense);   // barriers: 1 + 128*12 + 1 = 1538 (even: sense restored)
}

// ================= bf16 hi/lo split =================
__global__ void split_bf16_kernel(const float* __restrict__ src,
                                  __nv_bfloat16* __restrict__ hi,
                                  __nv_bfloat16* __restrict__ lo, size_t n4)
{
    for (size_t i = blockIdx.x * blockDim.x + threadIdx.x; i < n4;
         i += (size_t)gridDim.x * blockDim.x) {
        float4 v = *(const float4*)(src + i * 4);
        __nv_bfloat16 h0 = __float2bfloat16_rn(v.x);
        __nv_bfloat16 h1 = __float2bfloat16_rn(v.y);
        __nv_bfloat16 h2 = __float2bfloat16_rn(v.z);
        __nv_bfloat16 h3 = __float2bfloat16_rn(v.w);
        __nv_bfloat16 l0 = __float2bfloat16_rn(v.x - __bfloat162float(h0));
        __nv_bfloat16 l1 = __float2bfloat16_rn(v.y - __bfloat162float(h1));
        __nv_bfloat16 l2 = __float2bfloat16_rn(v.z - __bfloat162float(h2));
        __nv_bfloat16 l3 = __float2bfloat16_rn(v.w - __bfloat162float(h3));
        __nv_bfloat162* hp = (__nv_bfloat162*)(hi + i * 4);
        __nv_bfloat162* lp = (__nv_bfloat162*)(lo + i * 4);
        hp[0] = __nv_bfloat162(h0, h1);
        hp[1] = __nv_bfloat162(h2, h3);
        lp[0] = __nv_bfloat162(l0, l1);
        lp[1] = __nv_bfloat162(l2, l3);
    }
}

// ================= bf16x3 legacy-mma logits GEMM (unchanged, passing) =================
#define GTS 72
#define G_SMEM_BYTES (4 * 128 * GTS * 2)

__global__ __launch_bounds__(256, 2) void gemm_bf16x3_bias(
    const float* __restrict__ bias, float* __restrict__ C)
{
    extern __shared__ __nv_bfloat16 gs[];
    __nv_bfloat16* Ahs = gs;
    __nv_bfloat16* Als = Ahs + 128 * GTS;
    __nv_bfloat16* Bhs = Als + 128 * GTS;
    __nv_bfloat16* Bls = Bhs + 128 * GTS;

    int tid = threadIdx.x;
    int lane = tid & 31, wrp = tid >> 5;
    int wm = wrp & 1, wn = wrp >> 1;
    int gr = lane >> 2, tig = lane & 3;
    int m0 = blockIdx.x * 128;
    int n0 = blockIdx.y * 128;

    const __nv_bfloat16* Ahg = g_hidh + (size_t)m0 * Hdim;
    const __nv_bfloat16* Alg = g_hidl + (size_t)m0 * Hdim;
    const __nv_bfloat16* Bhg = g_embh + (size_t)n0 * Hdim;
    const __nv_bfloat16* Blg = g_embl + (size_t)n0 * Hdim;

    float acc[4][4][4];
#pragma unroll
    for (int i = 0; i < 4; i++)
#pragma unroll
        for (int j = 0; j < 4; j++)
#pragma unroll
            for (int q = 0; q < 4; q++) acc[i][j][q] = 0.f;

    for (int kc = 0; kc < Hdim; kc += 64) {
        __syncthreads();
#pragma unroll
        for (int i = 0; i < 4; i++) {
            int idx = tid + i * 256;
            int r = idx >> 3, u = idx & 7;
            int so = r * GTS + u * 8;
            size_t go = (size_t)r * Hdim + kc + u * 8;
            *(uint4*)&Ahs[so] = *(const uint4*)&Ahg[go];
            *(uint4*)&Als[so] = *(const uint4*)&Alg[go];
            *(uint4*)&Bhs[so] = *(const uint4*)&Bhg[go];
            *(uint4*)&Bls[so] = *(const uint4*)&Blg[go];
        }
        __syncthreads();

#pragma unroll
        for (int ks = 0; ks < 4; ks++) {
            int kb = ks * 16;
            uint32_t ah[4][4], al[4][4], bh[4][2], bl[4][2];
#pragma unroll
            for (int mf = 0; mf < 4; mf++) {
                int base = (wm * 64 + mf * 16 + gr) * GTS + kb + 2 * tig;
                ah[mf][0] = *(const uint32_t*)&Ahs[base];
                ah[mf][1] = *(const uint32_t*)&Ahs[base + 8 * GTS];
                ah[mf][2] = *(const uint32_t*)&Ahs[base + 8];
                ah[mf][3] = *(const uint32_t*)&Ahs[base + 8 * GTS + 8];
                al[mf][0] = *(const uint32_t*)&Als[base];
                al[mf][1] = *(const uint32_t*)&Als[base + 8 * GTS];
                al[mf][2] = *(const uint32_t*)&Als[base + 8];
                al[mf][3] = *(const uint32_t*)&Als[base + 8 * GTS + 8];
            }
#pragma unroll
            for (int nf = 0; nf < 4; nf++) {
                int base = (wn * 32 + nf * 8 + gr) * GTS + kb + 2 * tig;
                bh[nf][0] = *(const uint32_t*)&Bhs[base];
                bh[nf][1] = *(const uint32_t*)&Bhs[base + 8];
                bl[nf][0] = *(const uint32_t*)&Bls[base];
                bl[nf][1] = *(const uint32_t*)&Bls[base + 8];
            }
#pragma unroll
            for (int mf = 0; mf < 4; mf++)
#pragma unroll
                for (int nf = 0; nf < 4; nf++) {
                    mma_bf16(acc[mf][nf], ah[mf], bh[nf]);
                    mma_bf16(acc[mf][nf], al[mf], bh[nf]);
                    mma_bf16(acc[mf][nf], ah[mf], bl[nf]);
                }
        }
    }

#pragma unroll
    for (int nf = 0; nf < 4; nf++) {
        int col = n0 + wn * 32 + nf * 8 + 2 * tig;
        float bv0 = bias[col], bv1 = bias[col + 1];
#pragma unroll
        for (int mf = 0; mf < 4; mf++) {
            int row = m0 + wm * 64 + mf * 16 + gr;
            float2 v0 = make_float2(acc[mf][nf][0] + bv0, acc[mf][nf][1] + bv1);
            float2 v1 = make_float2(acc[mf][nf][2] + bv0, acc[mf][nf][3] + bv1);
            *(float2*)&C[(size_t)row * Vsz + col] = v0;
            *(float2*)&C[(size_t)(row + 8) * Vsz + col] = v1;
        }
    }
}

// ---------------- host ----------------
extern "C" void kernel_launch(void* const* d_in, const int* in_sizes, int n_in,
                              void* d_out, int out_size) {
    (void)in_sizes; (void)out_size;
    const int* seq = (const int*)d_in[0];
    int o = n_in - 14;
    const float* emb  = (const float*)d_in[o + 0];
    const float* fc_b = (const float*)d_in[o + 1];
    const float* m1w  = (const float*)d_in[o + 2];
    const float* m1b  = (const float*)d_in[o + 3];
    const float* w1ih = (const float*)d_in[o + 4];
    const float* w1hh = (const float*)d_in[o + 5];
    const float* b1ih = (const float*)d_in[o + 6];
    const float* b1hh = (const float*)d_in[o + 7];
    const float* m2w  = (const float*)d_in[o + 8];
    const float* m2b  = (const float*)d_in[o + 9];
    const float* w2ih = (const float*)d_in[o + 10];
    const float* w2hh = (const float*)d_in[o + 11];
    const float* b2ih = (const float*)d_in[o + 12];
    const float* b2hh = (const float*)d_in[o + 13];

    float* outp = (float*)d_out;                          // [B][T][V]
    float* hidp = outp + (size_t)Bsz * Tlen * Vsz;        // [B][T][H]

    __nv_bfloat16 *embh, *embl, *hidh, *hidl, *wh, *wl;
    cudaGetSymbolAddress((void**)&embh, g_embh);
    cudaGetSymbolAddress((void**)&embl, g_embl);
    cudaGetSymbolAddress((void**)&hidh, g_hidh);
    cudaGetSymbolAddress((void**)&hidl, g_hidl);
    cudaGetSymbolAddress((void**)&wh, g_wh);
    cudaGetSymbolAddress((void**)&wl, g_wl);

    cudaFuncSetAttribute(mog_lstm_kernel,
                         cudaFuncAttributeMaxDynamicSharedMemorySize, R_SMEM_BYTES);
    cudaFuncSetAttribute(gemm_bf16x3_bias,
                         cudaFuncAttributeMaxDynamicSharedMemorySize, G_SMEM_BYTES);

    // split weights into bf16 hi/lo arena
    split_bf16_kernel<<<512, 256>>>(m1w,  wh + WOFF_M1,   wl + WOFF_M1,   (size_t)5 * Hdim * Hdim / 4);
    split_bf16_kernel<<<512, 256>>>(m2w,  wh + WOFF_M2,   wl + WOFF_M2,   (size_t)5 * Hdim * Hdim / 4);
    split_bf16_kernel<<<512, 256>>>(w1ih, wh + WOFF_G1IH, wl + WOFF_G1IH, (size_t)4 * Hdim * Hdim / 4);
    split_bf16_kernel<<<512, 256>>>(w1hh, wh + WOFF_G1HH, wl + WOFF_G1HH, (size_t)4 * Hdim * Hdim / 4);
    split_bf16_kernel<<<512, 256>>>(w2ih, wh + WOFF_G2IH, wl + WOFF_G2IH, (size_t)4 * Hdim * Hdim / 4);
    split_bf16_kernel<<<512, 256>>>(w2hh, wh + WOFF_G2HH, wl + WOFF_G2HH, (size_t)4 * Hdim * Hdim / 4);

    // split embedding (independent of recurrence result)
    split_bf16_kernel<<<2048, 256>>>(emb, embh, embl, (size_t)Vsz * Hdim / 4);

    mog_lstm_kernel<<<NB, NT, R_SMEM_BYTES>>>(seq, emb,
                                              m1b, b1ih, b1hh, m2b, b2ih, b2hh, hidp);

    // split hidden states produced by the recurrence
    split_bf16_kernel<<<1024, 256>>>(hidp, hidh, hidl, (size_t)Bsz * Tlen * Hdim / 4);

    gemm_bf16x3_bias<<<dim3((Bsz * Tlen) / 128, Vsz / 128), 256, G_SMEM_BYTES>>>(fc_b, outp);
}

// round 12
// speedup vs baseline: 2.1341x; 1.0706x over previous
#include <cuda_runtime.h>
#include <cuda_bf16.h>
#include <math.h>
#include <stdint.h>

#define Bsz 32
#define Tlen 128
#define Hdim 1024
#define Vsz 32000
#define NB 128
#define NT 512

// ---------------- recurrence smem layout (byte offsets) ----------------
// mog chunks: 256k, RTS1=264 bf16/row; gate chunks: 128k, RTS2=136 bf16/row
#define RTS1  264
#define RTS1B 528
#define RTS2  136
#define RTS2B 272
// W buffers: slot = 34816 B (H at +0, L at +17408)
#define SW_H(b) ((b) * 34816)
#define SW_L(b) ((b) * 34816 + 17408)
// X buffers: slot = 33792 B (H at +0, L at +16896)
#define SX_H(b) (69632 + (b) * 33792)
#define SX_L(b) (69632 + (b) * 33792 + 16896)
#define SP_OFF  137216              // partials: 8192 floats (32 KB)
#define R_SMEM_BYTES 169984

// ---------------- device scratch ----------------
__device__ float g_XT[Tlen * Bsz * Hdim];        // [t][b][k]
__device__ float g_h1a[Bsz * Hdim], g_h1b[Bsz * Hdim];
__device__ float g_h2a[Bsz * Hdim], g_h2b[Bsz * Hdim];
__device__ float g_c1[Bsz * Hdim],  g_c2[Bsz * Hdim];
// per-cell mogrify scratch (non-inplace rotation)
__device__ float g_xA1[Bsz * Hdim], g_xB1[Bsz * Hdim];
__device__ float g_hA1[Bsz * Hdim], g_hB1[Bsz * Hdim];
__device__ float g_xA2[Bsz * Hdim], g_xB2[Bsz * Hdim];
__device__ float g_hA2[Bsz * Hdim], g_hB2[Bsz * Hdim];
__device__ unsigned g_bar_count;
__device__ volatile unsigned g_bar_sense;

// bf16 hi/lo weight arena
#define WOFF_M1   0
#define WOFF_M2   5242880
#define WOFF_G1IH 10485760
#define WOFF_G1HH 14680064
#define WOFF_G2IH 18874368
#define WOFF_G2HH 23068672
#define WTOTAL    27262976
__device__ __nv_bfloat16 g_wh[WTOTAL];
__device__ __nv_bfloat16 g_wl[WTOTAL];

// bf16 hi/lo splits for logits GEMM
__device__ __nv_bfloat16 g_embh[(size_t)Vsz * Hdim];
__device__ __nv_bfloat16 g_embl[(size_t)Vsz * Hdim];
__device__ __nv_bfloat16 g_hidh[(size_t)Bsz * Tlen * Hdim];
__device__ __nv_bfloat16 g_hidl[(size_t)Bsz * Tlen * Hdim];

// ---------------- grid-wide barrier (sense reversing, replay-safe) ----------------
__device__ __forceinline__ void grid_barrier(unsigned& sense) {
    __threadfence();
    __syncthreads();
    if (threadIdx.x == 0) {
        unsigned s = sense ^ 1u;
        if (atomicAdd(&g_bar_count, 1u) == NB - 1u) {
            g_bar_count = 0u;
            __threadfence();
            g_bar_sense = s;
        } else {
            while (g_bar_sense != s) __nanosleep(32);
        }
    }
    __syncthreads();
    __threadfence();
    sense ^= 1u;
}

// ---------------- helpers ----------------
__device__ __forceinline__ void mma_bf16(float d[4], const uint32_t a[4],
                                         const uint32_t b[2]) {
    asm volatile(
        "mma.sync.aligned.m16n8k16.row.col.f32.bf16.bf16.f32 "
        "{%0,%1,%2,%3},{%4,%5,%6,%7},{%8,%9},{%0,%1,%2,%3};"
        : "+f"(d[0]), "+f"(d[1]), "+f"(d[2]), "+f"(d[3])
        : "r"(a[0]), "r"(a[1]), "r"(a[2]), "r"(a[3]), "r"(b[0]), "r"(b[1]));
}

__device__ __forceinline__ void cp16(uint32_t saddr, const void* g) {
    asm volatile("cp.async.cg.shared.global [%0], [%1], 16;" :: "r"(saddr), "l"(g));
}
#define CP_COMMIT() asm volatile("cp.async.commit_group;" ::: "memory")
#define CP_WAIT0()  asm volatile("cp.async.wait_group 0;"  ::: "memory")

__device__ __forceinline__ uint32_t pack_bf2(float a, float b) {
    __nv_bfloat162 t(__float2bfloat16_rn(a), __float2bfloat16_rn(b));
    return *(uint32_t*)&t;
}

// ---- activation staging: fp32 [b][k] slice -> smem bf16 hi/lo ----
// KCH = chunk k-width (256 mog / 128 gate); RTSBx = byte row stride
template <int KCH, int RTSBx>
__device__ __forceinline__ void x_prefetch(const float* __restrict__ src, int kb,
                                           float4* xr) {
    int tid = threadIdx.x;
    const int CELLS = Bsz * KCH / 4;      // float4 cells
#pragma unroll
    for (int i = 0; i < CELLS / NT; i++) {
        int idx = tid + i * NT;
        int b = idx / (KCH / 4), q = idx % (KCH / 4);
        xr[i] = *(const float4*)&src[(size_t)b * Hdim + kb + q * 4];
    }
}
template <int KCH, int RTSBx>
__device__ __forceinline__ void x_store(char* sm, int buf, const float4* xr) {
    int tid = threadIdx.x;
    char* XH = sm + SX_H(buf);
    char* XL = sm + SX_L(buf);
    const int CELLS = Bsz * KCH / 4;
#pragma unroll
    for (int i = 0; i < CELLS / NT; i++) {
        int idx = tid + i * NT;
        int b = idx / (KCH / 4), q = idx % (KCH / 4);
        float4 v = xr[i];
        float hx = __bfloat162float(__float2bfloat16_rn(v.x));
        float hy = __bfloat162float(__float2bfloat16_rn(v.y));
        float hz = __bfloat162float(__float2bfloat16_rn(v.z));
        float hw = __bfloat162float(__float2bfloat16_rn(v.w));
        uint2 uh = make_uint2(pack_bf2(v.x, v.y), pack_bf2(v.z, v.w));
        uint2 ul = make_uint2(pack_bf2(v.x - hx, v.y - hy), pack_bf2(v.z - hz, v.w - hw));
        int off = b * RTSBx + q * 8;
        *(uint2*)(XH + off) = uh;
        *(uint2*)(XL + off) = ul;
    }
}

// ---- m16 fragment mma over one staged chunk slice (validated layout) ----
// rowBase: W smem row of this warp's m16 tile; kw: k offset; KSTEPS k16 steps
template <int RTSx, int KSTEPS>
__device__ __forceinline__ void frag16(char* sm, int buf, int rowBase, int kw,
                                       int gr, int tig, float acc[4][4]) {
    const __nv_bfloat16* WhS = (const __nv_bfloat16*)(sm + SW_H(buf));
    const __nv_bfloat16* WlS = (const __nv_bfloat16*)(sm + SW_L(buf));
    const __nv_bfloat16* XhS = (const __nv_bfloat16*)(sm + SX_H(buf));
    const __nv_bfloat16* XlS = (const __nv_bfloat16*)(sm + SX_L(buf));
#pragma unroll
    for (int ks = 0; ks < KSTEPS; ks++) {
        int k0 = kw + ks * 16 + 2 * tig;
        uint32_t ah[4], al[4], bh[4][2], bl[4][2];
        int base = (rowBase + gr) * RTSx + k0;
        ah[0] = *(const uint32_t*)&WhS[base];
        ah[1] = *(const uint32_t*)&WhS[base + 8 * RTSx];
        ah[2] = *(const uint32_t*)&WhS[base + 8];
        ah[3] = *(const uint32_t*)&WhS[base + 8 * RTSx + 8];
        al[0] = *(const uint32_t*)&WlS[base];
        al[1] = *(const uint32_t*)&WlS[base + 8 * RTSx];
        al[2] = *(const uint32_t*)&WlS[base + 8];
        al[3] = *(const uint32_t*)&WlS[base + 8 * RTSx + 8];
#pragma unroll
        for (int nf = 0; nf < 4; nf++) {
            int xb = (nf * 8 + gr) * RTSx + k0;
            bh[nf][0] = *(const uint32_t*)&XhS[xb];
            bh[nf][1] = *(const uint32_t*)&XhS[xb + 8];
            bl[nf][0] = *(const uint32_t*)&XlS[xb];
            bl[nf][1] = *(const uint32_t*)&XlS[xb + 8];
        }
#pragma unroll
        for (int nf = 0; nf < 4; nf++) {
            mma_bf16(acc[nf], ah, bh[nf]);
            mma_bf16(acc[nf], al, bh[nf]);
            mma_bf16(acc[nf], ah, bl[nf]);
        }
    }
}

// ---------------- mogrify stage: 16 rows/block, full K, 256k chunks ----------------
// dstNew[b][j] = mult[b][j] * 2*sigmoid( (W @ src)[j][b] + bias[j] )
__device__ void mog_stage(const __nv_bfloat16* __restrict__ Wh,
                          const __nv_bfloat16* __restrict__ Wl,
                          const float* __restrict__ bias,
                          const float* __restrict__ src,
                          const float* __restrict__ mult,
                          float* __restrict__ dstNew,
                          int lb, char* sm, uint32_t smb)
{
    int tid = threadIdx.x, lane = tid & 31, w = tid >> 5;
    int gr = lane >> 2, tig = lane & 3;
    int j0 = lb * 16;
    float* P = (float*)(sm + SP_OFF);

    float acc[4][4];
#pragma unroll
    for (int nf = 0; nf < 4; nf++)
#pragma unroll
        for (int q = 0; q < 4; q++) acc[nf][q] = 0.f;

    // W staging: 16 rows x 512 B x {H,L} -> 2 cp16/thread per chunk
    int wr = tid >> 5, wu = tid & 31;            // row 0..15, 16B unit 0..31
    size_t wgbase = (size_t)(j0 + wr) * Hdim + wu * 8;
    uint32_t wsoff = wr * RTS1B + wu * 16;

    // chunk 0
    {
        cp16(smb + SW_H(0) + wsoff, Wh + wgbase);
        cp16(smb + SW_L(0) + wsoff, Wl + wgbase);
        CP_COMMIT();
        float4 xr[4];
        x_prefetch<256, RTS1B>(src, 0, xr);
        CP_WAIT0();
        x_store<256, RTS1B>(sm, 0, xr);
        __syncthreads();
    }
#pragma unroll
    for (int c = 0; c < 4; c++) {
        int cb = c & 1, nb = (c + 1) & 1;
        float4 xr[4];
        if (c < 3) {
            int kb = (c + 1) * 256;
            cp16(smb + SW_H(nb) + wsoff, Wh + wgbase + kb);
            cp16(smb + SW_L(nb) + wsoff, Wl + wgbase + kb);
            CP_COMMIT();
            x_prefetch<256, RTS1B>(src, kb, xr);
        }
        frag16<RTS1, 1>(sm, cb, 0, w * 16, gr, tig, acc);
        if (c < 3) {
            CP_WAIT0();
            x_store<256, RTS1B>(sm, nb, xr);
        }
        __syncthreads();
    }

    // per-warp partials: P[w][row 0..15][b]
#pragma unroll
    for (int nf = 0; nf < 4; nf++) {
        int cc = nf * 8 + 2 * tig;
        *(float2*)&P[w * 512 + gr * 32 + cc]       = make_float2(acc[nf][0], acc[nf][1]);
        *(float2*)&P[w * 512 + (gr + 8) * 32 + cc] = make_float2(acc[nf][2], acc[nf][3]);
    }
    __syncthreads();

    // reduce + fused finalize: 512 cells, 1/thread
    {
        float s = 0.f;
#pragma unroll
        for (int ww = 0; ww < 16; ww++) s += P[ww * 512 + tid];
        int row = tid >> 5, b = tid & 31;
        int j = j0 + row;
        s += bias[j];
        size_t o = (size_t)b * Hdim + j;
        dstNew[o] = mult[o] * (2.f / (1.f + __expf(-s)));
    }
}

// ---------------- gate stage: 64 rows (16 units x 4 gates)/block, K=2048, 128k chunks --
__device__ void gate_stage(const __nv_bfloat16* __restrict__ WihH,
                           const __nv_bfloat16* __restrict__ WihL,
                           const __nv_bfloat16* __restrict__ WhhH,
                           const __nv_bfloat16* __restrict__ WhhL,
                           const float* __restrict__ bih, const float* __restrict__ bhh,
                           const float* __restrict__ xsrc, const float* __restrict__ hsrc,
                           float* __restrict__ cSt, float* __restrict__ hDst,
                           float* __restrict__ hidOut, int t,
                           int lb, char* sm, uint32_t smb)
{
    int tid = threadIdx.x, lane = tid & 31, w = tid >> 5;
    int gr = lane >> 2, tig = lane & 3;
    int mg = w >> 2, kg = w & 3;
    int j0u = lb * 16;                       // unit base
    float* P = (float*)(sm + SP_OFF);

    float acc[4][4];
#pragma unroll
    for (int nf = 0; nf < 4; nf++)
#pragma unroll
        for (int q = 0; q < 4; q++) acc[nf][q] = 0.f;

    // W staging per chunk: 64 rows x 256 B x {H,L} -> 4 cp16/thread (2 iters)
    auto stageW = [&](int buf, const __nv_bfloat16* WmH, const __nv_bfloat16* WmL,
                      int cbase) {
#pragma unroll
        for (int i = 0; i < 2; i++) {
            int idx = tid + i * NT;          // 0..1023
            int r = idx >> 4, u = idx & 15;  // row 0..63, 16B unit 0..15
            int grow = (r >> 4) * Hdim + j0u + (r & 15);
            size_t go = (size_t)grow * Hdim + cbase + u * 8;
            cp16(smb + SW_H(buf) + r * RTS2B + u * 16, WmH + go);
            cp16(smb + SW_L(buf) + r * RTS2B + u * 16, WmL + go);
        }
    };

    // chunk 0 (wih, x)
    {
        stageW(0, WihH, WihL, 0);
        CP_COMMIT();
        float4 xr[2];
        x_prefetch<128, RTS2B>(xsrc, 0, xr);
        CP_WAIT0();
        x_store<128, RTS2B>(sm, 0, xr);
        __syncthreads();
    }
    for (int c = 0; c < 16; c++) {
        int cb = c & 1, nb = (c + 1) & 1;
        float4 xr[2];
        if (c < 15) {
            int cn = c + 1;
            const __nv_bfloat16* WmH = (cn < 8) ? WihH : WhhH;
            const __nv_bfloat16* WmL = (cn < 8) ? WihL : WhhL;
            const float* S = (cn < 8) ? xsrc : hsrc;
            int cbase = (cn & 7) * 128;
            stageW(nb, WmH, WmL, cbase);
            CP_COMMIT();
            x_prefetch<128, RTS2B>(S, cbase, xr);
        }
        frag16<RTS2, 2>(sm, cb, mg * 16, kg * 32, gr, tig, acc);
        if (c < 15) {
            CP_WAIT0();
            x_store<128, RTS2B>(sm, nb, xr);
        }
        __syncthreads();
    }

    // partials: P[kg][row 0..63][b]
#pragma unroll
    for (int nf = 0; nf < 4; nf++) {
        int cc = nf * 8 + 2 * tig;
        *(float2*)&P[kg * 2048 + (mg * 16 + gr) * 32 + cc] =
            make_float2(acc[nf][0], acc[nf][1]);
        *(float2*)&P[kg * 2048 + (mg * 16 + gr + 8) * 32 + cc] =
            make_float2(acc[nf][2], acc[nf][3]);
    }
    __syncthreads();

    // fused pointwise: thread -> (unit u, batch b)
    {
        int u = tid >> 5, b = tid & 31;
        int j = j0u + u;
        float s[4];
#pragma unroll
        for (int g = 0; g < 4; g++) {
            int row = g * 16 + u;
            float v = 0.f;
#pragma unroll
            for (int k = 0; k < 4; k++) v += P[k * 2048 + row * 32 + b];
            s[g] = v;
        }
        float gi = s[0] + bih[j]            + bhh[j];
        float gf = s[1] + bih[Hdim + j]     + bhh[Hdim + j];
        float gg = s[2] + bih[2 * Hdim + j] + bhh[2 * Hdim + j];
        float go = s[3] + bih[3 * Hdim + j] + bhh[3 * Hdim + j];

        float si = 1.f / (1.f + __expf(-gi));
        float sf = 1.f / (1.f + __expf(-gf));
        float tg = tanhf(gg);
        float so = 1.f / (1.f + __expf(-go));

        size_t g = (size_t)b * Hdim + j;
        float cc = sf * cSt[g] + si * tg;
        float h = so * tanhf(cc);
        cSt[g] = cc;
        hDst[g] = h;
        if (hidOut) hidOut[(size_t)b * Tlen * Hdim + (size_t)t * Hdim + j] = h;
    }
}

// ---------------- persistent recurrence kernel (two pipelined cell chains) ----------
__global__ __launch_bounds__(NT, 1) void mog_lstm_kernel(
    const int* __restrict__ seq, const float* __restrict__ emb,
    const float* __restrict__ m1b, const float* __restrict__ b1ih,
    const float* __restrict__ b1hh, const float* __restrict__ m2b,
    const float* __restrict__ b2ih, const float* __restrict__ b2hh,
    float* __restrict__ hidp)
{
    extern __shared__ char sm[];
    uint32_t smb;
    asm("{ .reg .u64 t; cvta.to.shared.u64 t, %1; cvt.u32.u64 %0, t; }"
        : "=r"(smb) : "l"(sm));
    int tid = threadIdx.x;
    int bid = blockIdx.x;
    int grp = bid >> 6;          // 0 = cell1 chain, 1 = cell2 chain
    int lb  = bid & 63;
    unsigned sense = 0;

    for (int g = bid * NT + tid; g < Bsz * Hdim; g += NB * NT) {
        g_h1a[g] = 0.f; g_h1b[g] = 0.f; g_h2a[g] = 0.f; g_h2b[g] = 0.f;
        g_c1[g] = 0.f;  g_c2[g] = 0.f;
    }
    {
        int t = bid;   // embedding gather: XT[t][b][k]
        for (int idx = tid; idx < Bsz * Hdim; idx += NT) {
            int b = idx >> 10, k = idx & 1023;
            int id = seq[b * Tlen + t];
            g_XT[((size_t)t * Bsz + b) * Hdim + k] = emb[(size_t)id * Hdim + k];
        }
    }
    grid_barrier(sense);                                     // 1

    const size_t MW = (size_t)Hdim * Hdim;
    for (int p = 0; p <= Tlen; p++) {                        // 129 phases x 6 barriers
        bool Aact = (grp == 0) && (p < Tlen);
        bool Bact = (grp == 1) && (p >= 1);
        int t2 = p - 1;

        // cell1 (step p) pointers
        const float* A_x = g_XT + (size_t)p * Bsz * Hdim;    // valid when Aact
        float* A_hs = (p & 1) ? g_h1b : g_h1a;               // h1 state in
        float* A_hd = (p & 1) ? g_h1a : g_h1b;               // h1 out
        // cell2 (step t2) pointers
        const float* B_x = (t2 & 1) ? g_h1a : g_h1b;         // h1d(t2) from A
        float* B_hs = (t2 & 1) ? g_h2b : g_h2a;
        float* B_hd = (t2 & 1) ? g_h2a : g_h2b;

        // mogrify rotation tables
        const float* AsS[5] = { A_hs, g_xA1, g_hA1, g_xB1, g_hB1 };
        const float* AsM[5] = { A_x,  A_hs,  g_xA1, g_hA1, g_xB1 };
        float*       AsD[5] = { g_xA1, g_hA1, g_xB1, g_hB1, g_xA1 };
        const float* BsS[5] = { B_hs, g_xA2, g_hA2, g_xB2, g_hB2 };
        const float* BsM[5] = { B_x,  B_hs,  g_xA2, g_hA2, g_xB2 };
        float*       BsD[5] = { g_xA2, g_hA2, g_xB2, g_hB2, g_xA2 };

        for (int i = 0; i < 5; i++) {
            if (Aact)
                mog_stage(g_wh + WOFF_M1 + (size_t)i * MW, g_wl + WOFF_M1 + (size_t)i * MW,
                          m1b + i * Hdim, AsS[i], AsM[i], AsD[i], lb, sm, smb);
            else if (Bact)
                mog_stage(g_wh + WOFF_M2 + (size_t)i * MW, g_wl + WOFF_M2 + (size_t)i * MW,
                          m2b + i * Hdim, BsS[i], BsM[i], BsD[i], lb, sm, smb);
            grid_barrier(sense);
        }
        if (Aact)
            gate_stage(g_wh + WOFF_G1IH, g_wl + WOFF_G1IH,
                       g_wh + WOFF_G1HH, g_wl + WOFF_G1HH,
                       b1ih, b1hh, g_xA1, g_hB1, g_c1, A_hd, nullptr, p, lb, sm, smb);
        else if (Bact)
            gate_stage(g_wh + WOFF_G2IH, g_wl + WOFF_G2IH,
                       g_wh + WOFF_G2HH, g_wl + WOFF_G2HH,
                       b2ih, b2hh, g_xA2, g_hB2, g_c2, B_hd, hidp, t2, lb, sm, smb);
        grid_barrier(sense);
    }
    grid_barrier(sense);   // total = 1 + 129*6 + 1 = 776 (even: sense restored)
}

// ================= bf16 hi/lo split =================
__global__ void split_bf16_kernel(const float* __restrict__ src,
                                  __nv_bfloat16* __restrict__ hi,
                                  __nv_bfloat16* __restrict__ lo, size_t n4)
{
    for (size_t i = blockIdx.x * blockDim.x + threadIdx.x; i < n4;
         i += (size_t)gridDim.x * blockDim.x) {
        float4 v = *(const float4*)(src + i * 4);
        __nv_bfloat16 h0 = __float2bfloat16_rn(v.x);
        __nv_bfloat16 h1 = __float2bfloat16_rn(v.y);
        __nv_bfloat16 h2 = __float2bfloat16_rn(v.z);
        __nv_bfloat16 h3 = __float2bfloat16_rn(v.w);
        __nv_bfloat16 l0 = __float2bfloat16_rn(v.x - __bfloat162float(h0));
        __nv_bfloat16 l1 = __float2bfloat16_rn(v.y - __bfloat162float(h1));
        __nv_bfloat16 l2 = __float2bfloat16_rn(v.z - __bfloat162float(h2));
        __nv_bfloat16 l3 = __float2bfloat16_rn(v.w - __bfloat162float(h3));
        __nv_bfloat162* hp = (__nv_bfloat162*)(hi + i * 4);
        __nv_bfloat162* lp = (__nv_bfloat162*)(lo + i * 4);
        hp[0] = __nv_bfloat162(h0, h1);
        hp[1] = __nv_bfloat162(h2, h3);
        lp[0] = __nv_bfloat162(l0, l1);
        lp[1] = __nv_bfloat162(l2, l3);
    }
}

// ================= bf16x3 legacy-mma logits GEMM (unchanged, passing) =================
#define GTS 72
#define G_SMEM_BYTES (4 * 128 * GTS * 2)

__global__ __launch_bounds__(256, 2) void gemm_bf16x3_bias(
    const float* __restrict__ bias, float* __restrict__ C)
{
    extern __shared__ __nv_bfloat16 gs[];
    __nv_bfloat16* Ahs = gs;
    __nv_bfloat16* Als = Ahs + 128 * GTS;
    __nv_bfloat16* Bhs = Als + 128 * GTS;
    __nv_bfloat16* Bls = Bhs + 128 * GTS;

    int tid = threadIdx.x;
    int lane = tid & 31, wrp = tid >> 5;
    int wm = wrp & 1, wn = wrp >> 1;
    int gr = lane >> 2, tig = lane & 3;
    int m0 = blockIdx.x * 128;
    int n0 = blockIdx.y * 128;

    const __nv_bfloat16* Ahg = g_hidh + (size_t)m0 * Hdim;
    const __nv_bfloat16* Alg = g_hidl + (size_t)m0 * Hdim;
    const __nv_bfloat16* Bhg = g_embh + (size_t)n0 * Hdim;
    const __nv_bfloat16* Blg = g_embl + (size_t)n0 * Hdim;

    float acc[4][4][4];
#pragma unroll
    for (int i = 0; i < 4; i++)
#pragma unroll
        for (int j = 0; j < 4; j++)
#pragma unroll
            for (int q = 0; q < 4; q++) acc[i][j][q] = 0.f;

    for (int kc = 0; kc < Hdim; kc += 64) {
        __syncthreads();
#pragma unroll
        for (int i = 0; i < 4; i++) {
            int idx = tid + i * 256;
            int r = idx >> 3, u = idx & 7;
            int so = r * GTS + u * 8;
            size_t go = (size_t)r * Hdim + kc + u * 8;
            *(uint4*)&Ahs[so] = *(const uint4*)&Ahg[go];
            *(uint4*)&Als[so] = *(const uint4*)&Alg[go];
            *(uint4*)&Bhs[so] = *(const uint4*)&Bhg[go];
            *(uint4*)&Bls[so] = *(const uint4*)&Blg[go];
        }
        __syncthreads();

#pragma unroll
        for (int ks = 0; ks < 4; ks++) {
            int kb = ks * 16;
            uint32_t ah[4][4], al[4][4], bh[4][2], bl[4][2];
#pragma unroll
            for (int mf = 0; mf < 4; mf++) {
                int base = (wm * 64 + mf * 16 + gr) * GTS + kb + 2 * tig;
                ah[mf][0] = *(const uint32_t*)&Ahs[base];
                ah[mf][1] = *(const uint32_t*)&Ahs[base + 8 * GTS];
                ah[mf][2] = *(const uint32_t*)&Ahs[base + 8];
                ah[mf][3] = *(const uint32_t*)&Ahs[base + 8 * GTS + 8];
                al[mf][0] = *(const uint32_t*)&Als[base];
                al[mf][1] = *(const uint32_t*)&Als[base + 8 * GTS];
                al[mf][2] = *(const uint32_t*)&Als[base + 8];
                al[mf][3] = *(const uint32_t*)&Als[base + 8 * GTS + 8];
            }
#pragma unroll
            for (int nf = 0; nf < 4; nf++) {
                int base = (wn * 32 + nf * 8 + gr) * GTS + kb + 2 * tig;
                bh[nf][0] = *(const uint32_t*)&Bhs[base];
                bh[nf][1] = *(const uint32_t*)&Bhs[base + 8];
                bl[nf][0] = *(const uint32_t*)&Bls[base];
                bl[nf][1] = *(const uint32_t*)&Bls[base + 8];
            }
#pragma unroll
            for (int mf = 0; mf < 4; mf++)
#pragma unroll
                for (int nf = 0; nf < 4; nf++) {
                    mma_bf16(acc[mf][nf], ah[mf], bh[nf]);
                    mma_bf16(acc[mf][nf], al[mf], bh[nf]);
                    mma_bf16(acc[mf][nf], ah[mf], bl[nf]);
                }
        }
    }

#pragma unroll
    for (int nf = 0; nf < 4; nf++) {
        int col = n0 + wn * 32 + nf * 8 + 2 * tig;
        float bv0 = bias[col], bv1 = bias[col + 1];
#pragma unroll
        for (int mf = 0; mf < 4; mf++) {
            int row = m0 + wm * 64 + mf * 16 + gr;
            float2 v0 = make_float2(acc[mf][nf][0] + bv0, acc[mf][nf][1] + bv1);
            float2 v1 = make_float2(acc[mf][nf][2] + bv0, acc[mf][nf][3] + bv1);
            *(float2*)&C[(size_t)row * Vsz + col] = v0;
            *(float2*)&C[(size_t)(row + 8) * Vsz + col] = v1;
        }
    }
}

// ---------------- host ----------------
extern "C" void kernel_launch(void* const* d_in, const int* in_sizes, int n_in,
                              void* d_out, int out_size) {
    (void)in_sizes; (void)out_size;
    const int* seq = (const int*)d_in[0];
    int o = n_in - 14;
    const float* emb  = (const float*)d_in[o + 0];
    const float* fc_b = (const float*)d_in[o + 1];
    const float* m1w  = (const float*)d_in[o + 2];
    const float* m1b  = (const float*)d_in[o + 3];
    const float* w1ih = (const float*)d_in[o + 4];
    const float* w1hh = (const float*)d_in[o + 5];
    const float* b1ih = (const float*)d_in[o + 6];
    const float* b1hh = (const float*)d_in[o + 7];
    const float* m2w  = (const float*)d_in[o + 8];
    const float* m2b  = (const float*)d_in[o + 9];
    const float* w2ih = (const float*)d_in[o + 10];
    const float* w2hh = (const float*)d_in[o + 11];
    const float* b2ih = (const float*)d_in[o + 12];
    const float* b2hh = (const float*)d_in[o + 13];

    float* outp = (float*)d_out;                          // [B][T][V]
    float* hidp = outp + (size_t)Bsz * Tlen * Vsz;        // [B][T][H]

    __nv_bfloat16 *embh, *embl, *hidh, *hidl, *wh, *wl;
    cudaGetSymbolAddress((void**)&embh, g_embh);
    cudaGetSymbolAddress((void**)&embl, g_embl);
    cudaGetSymbolAddress((void**)&hidh, g_hidh);
    cudaGetSymbolAddress((void**)&hidl, g_hidl);
    cudaGetSymbolAddress((void**)&wh, g_wh);
    cudaGetSymbolAddress((void**)&wl, g_wl);

    cudaFuncSetAttribute(mog_lstm_kernel,
                         cudaFuncAttributeMaxDynamicSharedMemorySize, R_SMEM_BYTES);
    cudaFuncSetAttribute(gemm_bf16x3_bias,
                         cudaFuncAttributeMaxDynamicSharedMemorySize, G_SMEM_BYTES);

    // split weights into bf16 hi/lo arena
    split_bf16_kernel<<<512, 256>>>(m1w,  wh + WOFF_M1,   wl + WOFF_M1,   (size_t)5 * Hdim * Hdim / 4);
    split_bf16_kernel<<<512, 256>>>(m2w,  wh + WOFF_M2,   wl + WOFF_M2,   (size_t)5 * Hdim * Hdim / 4);
    split_bf16_kernel<<<512, 256>>>(w1ih, wh + WOFF_G1IH, wl + WOFF_G1IH, (size_t)4 * Hdim * Hdim / 4);
    split_bf16_kernel<<<512, 256>>>(w1hh, wh + WOFF_G1HH, wl + WOFF_G1HH, (size_t)4 * Hdim * Hdim / 4);
    split_bf16_kernel<<<512, 256>>>(w2ih, wh + WOFF_G2IH, wl + WOFF_G2IH, (size_t)4 * Hdim * Hdim / 4);
    split_bf16_kernel<<<512, 256>>>(w2hh, wh + WOFF_G2HH, wl + WOFF_G2HH, (size_t)4 * Hdim * Hdim / 4);

    // split embedding (independent of recurrence result)
    split_bf16_kernel<<<2048, 256>>>(emb, embh, embl, (size_t)Vsz * Hdim / 4);

    mog_lstm_kernel<<<NB, NT, R_SMEM_BYTES>>>(seq, emb,
                                              m1b, b1ih, b1hh, m2b, b2ih, b2hh, hidp);

    // split hidden states produced by the recurrence
    split_bf16_kernel<<<1024, 256>>>(hidp, hidh, hidl, (size_t)Bsz * Tlen * Hdim / 4);

    gemm_bf16x3_bias<<<dim3((Bsz * Tlen) / 128, Vsz / 128), 256, G_SMEM_BYTES>>>(fc_b, outp);
}

// round 13
// speedup vs baseline: 3.0610x; 1.4343x over previous
#include <cuda_runtime.h>
#include <cuda_bf16.h>
#include <math.h>
#include <stdint.h>

#define Bsz 32
#define Tlen 128
#define Hdim 1024
#define Vsz 32000
#define NB 128
#define NT 512

// ---------------- recurrence smem layout (byte offsets) ----------------
// mog chunks: 256k (RTS1=264 bf16/row, 16 rows); gate chunks: 128k (RTS2=136, 64 rows)
#define RTS1  264
#define RTS1B 528
#define RTS2  136
#define RTS2B 272
// W buffers: 4 slots of 34816 B (H at +0, L at +17408)
#define WSLOT 34816
#define SW_H(b) ((b) * WSLOT)
#define SW_L(b) ((b) * WSLOT + 17408)
// X buffers: 2 slots of 33792 B after W region (4*34816 = 139264)
#define SX_H(b) (139264 + (b) * 33792)
#define SX_L(b) (139264 + (b) * 33792 + 16896)
// P overlays W buffer 0 (32 KB < 34816). Written only after all W reads complete.
#define SP_OFF  0
#define R_SMEM_BYTES 206848

// ---------------- device scratch ----------------
__device__ float g_XT[Tlen * Bsz * Hdim];        // [t][b][k]
__device__ float g_h1a[Bsz * Hdim], g_h1b[Bsz * Hdim];
__device__ float g_h2a[Bsz * Hdim], g_h2b[Bsz * Hdim];
__device__ float g_c1[Bsz * Hdim],  g_c2[Bsz * Hdim];
__device__ float g_xA1[Bsz * Hdim], g_xB1[Bsz * Hdim];
__device__ float g_hA1[Bsz * Hdim], g_hB1[Bsz * Hdim];
__device__ float g_xA2[Bsz * Hdim], g_xB2[Bsz * Hdim];
__device__ float g_hA2[Bsz * Hdim], g_hB2[Bsz * Hdim];
__device__ unsigned g_bar_count;
__device__ volatile unsigned g_bar_sense;

// bf16 hi/lo weight arena
#define WOFF_M1   0
#define WOFF_M2   5242880
#define WOFF_G1IH 10485760
#define WOFF_G1HH 14680064
#define WOFF_G2IH 18874368
#define WOFF_G2HH 23068672
#define WTOTAL    27262976
__device__ __nv_bfloat16 g_wh[WTOTAL];
__device__ __nv_bfloat16 g_wl[WTOTAL];

// bf16 hi/lo splits for logits GEMM
__device__ __nv_bfloat16 g_embh[(size_t)Vsz * Hdim];
__device__ __nv_bfloat16 g_embl[(size_t)Vsz * Hdim];
__device__ __nv_bfloat16 g_hidh[(size_t)Bsz * Tlen * Hdim];
__device__ __nv_bfloat16 g_hidl[(size_t)Bsz * Tlen * Hdim];

// ---------------- grid-wide barrier (sense reversing, replay-safe) ----------------
__device__ __forceinline__ void grid_barrier(unsigned& sense) {
    __threadfence();
    __syncthreads();
    if (threadIdx.x == 0) {
        unsigned s = sense ^ 1u;
        if (atomicAdd(&g_bar_count, 1u) == NB - 1u) {
            g_bar_count = 0u;
            __threadfence();
            g_bar_sense = s;
        } else {
            while (g_bar_sense != s) __nanosleep(32);
        }
    }
    __syncthreads();
    __threadfence();
    sense ^= 1u;
}

// ---------------- helpers ----------------
__device__ __forceinline__ void mma_bf16(float d[4], const uint32_t a[4],
                                         const uint32_t b[2]) {
    asm volatile(
        "mma.sync.aligned.m16n8k16.row.col.f32.bf16.bf16.f32 "
        "{%0,%1,%2,%3},{%4,%5,%6,%7},{%8,%9},{%0,%1,%2,%3};"
        : "+f"(d[0]), "+f"(d[1]), "+f"(d[2]), "+f"(d[3])
        : "r"(a[0]), "r"(a[1]), "r"(a[2]), "r"(a[3]), "r"(b[0]), "r"(b[1]));
}

__device__ __forceinline__ void cp16(uint32_t saddr, const void* g) {
    asm volatile("cp.async.cg.shared.global [%0], [%1], 16;" :: "r"(saddr), "l"(g));
}
#define CP_COMMIT() asm volatile("cp.async.commit_group;" ::: "memory")
template <int N>
__device__ __forceinline__ void cp_wait() {
    asm volatile("cp.async.wait_group %0;" :: "n"(N) : "memory");
}

__device__ __forceinline__ uint32_t pack_bf2(float a, float b) {
    __nv_bfloat162 t(__float2bfloat16_rn(a), __float2bfloat16_rn(b));
    return *(uint32_t*)&t;
}

// ---- activation staging: fp32 [b][k] slice -> smem bf16 hi/lo ----
template <int KCH, int RTSBx>
__device__ __forceinline__ void x_prefetch(const float* __restrict__ src, int kb,
                                           float4* xr) {
    int tid = threadIdx.x;
    const int CELLS = Bsz * KCH / 4;
#pragma unroll
    for (int i = 0; i < CELLS / NT; i++) {
        int idx = tid + i * NT;
        int b = idx / (KCH / 4), q = idx % (KCH / 4);
        xr[i] = *(const float4*)&src[(size_t)b * Hdim + kb + q * 4];
    }
}
template <int KCH, int RTSBx>
__device__ __forceinline__ void x_store(char* sm, int buf, const float4* xr) {
    int tid = threadIdx.x;
    char* XH = sm + SX_H(buf);
    char* XL = sm + SX_L(buf);
    const int CELLS = Bsz * KCH / 4;
#pragma unroll
    for (int i = 0; i < CELLS / NT; i++) {
        int idx = tid + i * NT;
        int b = idx / (KCH / 4), q = idx % (KCH / 4);
        float4 v = xr[i];
        float hx = __bfloat162float(__float2bfloat16_rn(v.x));
        float hy = __bfloat162float(__float2bfloat16_rn(v.y));
        float hz = __bfloat162float(__float2bfloat16_rn(v.z));
        float hw = __bfloat162float(__float2bfloat16_rn(v.w));
        uint2 uh = make_uint2(pack_bf2(v.x, v.y), pack_bf2(v.z, v.w));
        uint2 ul = make_uint2(pack_bf2(v.x - hx, v.y - hy), pack_bf2(v.z - hz, v.w - hw));
        int off = b * RTSBx + q * 8;
        *(uint2*)(XH + off) = uh;
        *(uint2*)(XL + off) = ul;
    }
}

// ---- m16 fragment mma over one staged chunk slice ----
template <int RTSx, int KSTEPS>
__device__ __forceinline__ void frag16(char* sm, int wbuf, int xbuf, int rowBase,
                                       int kw, int gr, int tig, float acc[4][4]) {
    const __nv_bfloat16* WhS = (const __nv_bfloat16*)(sm + SW_H(wbuf));
    const __nv_bfloat16* WlS = (const __nv_bfloat16*)(sm + SW_L(wbuf));
    const __nv_bfloat16* XhS = (const __nv_bfloat16*)(sm + SX_H(xbuf));
    const __nv_bfloat16* XlS = (const __nv_bfloat16*)(sm + SX_L(xbuf));
#pragma unroll
    for (int ks = 0; ks < KSTEPS; ks++) {
        int k0 = kw + ks * 16 + 2 * tig;
        uint32_t ah[4], al[4], bh[4][2], bl[4][2];
        int base = (rowBase + gr) * RTSx + k0;
        ah[0] = *(const uint32_t*)&WhS[base];
        ah[1] = *(const uint32_t*)&WhS[base + 8 * RTSx];
        ah[2] = *(const uint32_t*)&WhS[base + 8];
        ah[3] = *(const uint32_t*)&WhS[base + 8 * RTSx + 8];
        al[0] = *(const uint32_t*)&WlS[base];
        al[1] = *(const uint32_t*)&WlS[base + 8 * RTSx];
        al[2] = *(const uint32_t*)&WlS[base + 8];
        al[3] = *(const uint32_t*)&WlS[base + 8 * RTSx + 8];
#pragma unroll
        for (int nf = 0; nf < 4; nf++) {
            int xb = (nf * 8 + gr) * RTSx + k0;
            bh[nf][0] = *(const uint32_t*)&XhS[xb];
            bh[nf][1] = *(const uint32_t*)&XhS[xb + 8];
            bl[nf][0] = *(const uint32_t*)&XlS[xb];
            bl[nf][1] = *(const uint32_t*)&XlS[xb + 8];
        }
#pragma unroll
        for (int nf = 0; nf < 4; nf++) {
            mma_bf16(acc[nf], ah, bh[nf]);
            mma_bf16(acc[nf], al, bh[nf]);
            mma_bf16(acc[nf], ah, bl[nf]);
        }
    }
}

// ---------------- mogrify stage: 16 rows/block, full K, 4 chunks all in flight ------
__device__ void mog_stage(const __nv_bfloat16* __restrict__ Wh,
                          const __nv_bfloat16* __restrict__ Wl,
                          const float* __restrict__ bias,
                          const float* __restrict__ src,
                          const float* __restrict__ mult,
                          float* __restrict__ dstNew,
                          int lb, char* sm, uint32_t smb)
{
    int tid = threadIdx.x, lane = tid & 31, w = tid >> 5;
    int gr = lane >> 2, tig = lane & 3;
    int j0 = lb * 16;
    float* P = (float*)(sm + SP_OFF);

    float acc[4][4];
#pragma unroll
    for (int nf = 0; nf < 4; nf++)
#pragma unroll
        for (int q = 0; q < 4; q++) acc[nf][q] = 0.f;

    int wr = tid >> 5, wu = tid & 31;           // row 0..15, 16B unit 0..31
    size_t wgbase = (size_t)(j0 + wr) * Hdim + wu * 8;
    uint32_t wsoff = wr * RTS1B + wu * 16;

    // issue ALL 4 W chunk groups up-front (4 buffers, 4 groups in flight)
#pragma unroll
    for (int c = 0; c < 4; c++) {
        cp16(smb + SW_H(c) + wsoff, Wh + wgbase + c * 256);
        cp16(smb + SW_L(c) + wsoff, Wl + wgbase + c * 256);
        CP_COMMIT();
    }
    // X chunk 0
    {
        float4 xr[4];
        x_prefetch<256, RTS1B>(src, 0, xr);
        x_store<256, RTS1B>(sm, 0, xr);
    }

#pragma unroll
    for (int c = 0; c < 4; c++) {
        float4 xr[4];
        if (c < 3) x_prefetch<256, RTS1B>(src, (c + 1) * 256, xr);
        if (c == 0) cp_wait<3>();
        else if (c == 1) cp_wait<2>();
        else if (c == 2) cp_wait<1>();
        else cp_wait<0>();
        __syncthreads();                 // W group c visible + X stores visible
        frag16<RTS1, 1>(sm, c, c & 1, 0, w * 16, gr, tig, acc);
        if (c < 3) x_store<256, RTS1B>(sm, (c + 1) & 1, xr);
        __syncthreads();                 // protect X buf reuse / P overlay below
    }

    // per-warp partials (P overlays W buf 0; all W reads done, sync above)
#pragma unroll
    for (int nf = 0; nf < 4; nf++) {
        int cc = nf * 8 + 2 * tig;
        *(float2*)&P[w * 512 + gr * 32 + cc]       = make_float2(acc[nf][0], acc[nf][1]);
        *(float2*)&P[w * 512 + (gr + 8) * 32 + cc] = make_float2(acc[nf][2], acc[nf][3]);
    }
    __syncthreads();

    // reduce + fused finalize: 512 cells, 1/thread
    {
        float s = 0.f;
#pragma unroll
        for (int ww = 0; ww < 16; ww++) s += P[ww * 512 + tid];
        int row = tid >> 5, b = tid & 31;
        int j = j0 + row;
        s += bias[j];
        size_t o = (size_t)b * Hdim + j;
        dstNew[o] = mult[o] * (2.f / (1.f + __expf(-s)));
    }
}

// ---------------- gate stage: 64 rows/block, K=2048, 128k chunks, 3-ahead ----------
__device__ void gate_stage(const __nv_bfloat16* __restrict__ WihH,
                           const __nv_bfloat16* __restrict__ WihL,
                           const __nv_bfloat16* __restrict__ WhhH,
                           const __nv_bfloat16* __restrict__ WhhL,
                           const float* __restrict__ bih, const float* __restrict__ bhh,
                           const float* __restrict__ xsrc, const float* __restrict__ hsrc,
                           float* __restrict__ cSt, float* __restrict__ hDst,
                           float* __restrict__ hidOut, int t,
                           int lb, char* sm, uint32_t smb)
{
    int tid = threadIdx.x, lane = tid & 31, w = tid >> 5;
    int gr = lane >> 2, tig = lane & 3;
    int mg = w >> 2, kg = w & 3;
    int j0u = lb * 16;
    float* P = (float*)(sm + SP_OFF);

    float acc[4][4];
#pragma unroll
    for (int nf = 0; nf < 4; nf++)
#pragma unroll
        for (int q = 0; q < 4; q++) acc[nf][q] = 0.f;

    auto stageW = [&](int buf, int cn) {
        const __nv_bfloat16* WmH = (cn < 8) ? WihH : WhhH;
        const __nv_bfloat16* WmL = (cn < 8) ? WihL : WhhL;
        int cbase = (cn & 7) * 128;
#pragma unroll
        for (int i = 0; i < 2; i++) {
            int idx = tid + i * NT;
            int r = idx >> 4, u = idx & 15;      // row 0..63, 16B unit 0..15
            int grow = (r >> 4) * Hdim + j0u + (r & 15);
            size_t go = (size_t)grow * Hdim + cbase + u * 8;
            cp16(smb + SW_H(buf) + r * RTS2B + u * 16, WmH + go);
            cp16(smb + SW_L(buf) + r * RTS2B + u * 16, WmL + go);
        }
        CP_COMMIT();
    };

    // prologue: 3 W chunks ahead + X chunk 0
    stageW(0, 0);
    stageW(1, 1);
    stageW(2, 2);
    {
        float4 xr[2];
        x_prefetch<128, RTS2B>(xsrc, 0, xr);
        x_store<128, RTS2B>(sm, 0, xr);
    }

#pragma unroll
    for (int c = 0; c < 16; c++) {
        if (c + 3 < 16) stageW((c + 3) & 3, c + 3);
        float4 xr[2];
        if (c < 15) {
            int cn = c + 1;
            const float* S = (cn < 8) ? xsrc : hsrc;
            x_prefetch<128, RTS2B>(S, (cn & 7) * 128, xr);
        }
        // wait for W group c: groups issued after it = min(3, 15-c)
        if (c <= 12) cp_wait<3>();
        else if (c == 13) cp_wait<2>();
        else if (c == 14) cp_wait<1>();
        else cp_wait<0>();
        __syncthreads();
        frag16<RTS2, 2>(sm, c & 3, c & 1, mg * 16, kg * 32, gr, tig, acc);
        if (c < 15) x_store<128, RTS2B>(sm, (c + 1) & 1, xr);
        __syncthreads();
    }

    // partials (P overlays W buf 0; last buf-0 read was chunk 12, sync-separated)
#pragma unroll
    for (int nf = 0; nf < 4; nf++) {
        int cc = nf * 8 + 2 * tig;
        *(float2*)&P[kg * 2048 + (mg * 16 + gr) * 32 + cc] =
            make_float2(acc[nf][0], acc[nf][1]);
        *(float2*)&P[kg * 2048 + (mg * 16 + gr + 8) * 32 + cc] =
            make_float2(acc[nf][2], acc[nf][3]);
    }
    __syncthreads();

    // fused pointwise
    {
        int u = tid >> 5, b = tid & 31;
        int j = j0u + u;
        float s[4];
#pragma unroll
        for (int g = 0; g < 4; g++) {
            int row = g * 16 + u;
            float v = 0.f;
#pragma unroll
            for (int k = 0; k < 4; k++) v += P[k * 2048 + row * 32 + b];
            s[g] = v;
        }
        float gi = s[0] + bih[j]            + bhh[j];
        float gf = s[1] + bih[Hdim + j]     + bhh[Hdim + j];
        float gg = s[2] + bih[2 * Hdim + j] + bhh[2 * Hdim + j];
        float go = s[3] + bih[3 * Hdim + j] + bhh[3 * Hdim + j];

        float si = 1.f / (1.f + __expf(-gi));
        float sf = 1.f / (1.f + __expf(-gf));
        float tg = tanhf(gg);
        float so = 1.f / (1.f + __expf(-go));

        size_t g = (size_t)b * Hdim + j;
        float cc = sf * cSt[g] + si * tg;
        float h = so * tanhf(cc);
        cSt[g] = cc;
        hDst[g] = h;
        if (hidOut) hidOut[(size_t)b * Tlen * Hdim + (size_t)t * Hdim + j] = h;
    }
}

// ---------------- persistent recurrence kernel (two pipelined cell chains) ----------
__global__ __launch_bounds__(NT, 1) void mog_lstm_kernel(
    const int* __restrict__ seq, const float* __restrict__ emb,
    const float* __restrict__ m1b, const float* __restrict__ b1ih,
    const float* __restrict__ b1hh, const float* __restrict__ m2b,
    const float* __restrict__ b2ih, const float* __restrict__ b2hh,
    float* __restrict__ hidp)
{
    extern __shared__ char sm[];
    uint32_t smb;
    asm("{ .reg .u64 t; cvta.to.shared.u64 t, %1; cvt.u32.u64 %0, t; }"
        : "=r"(smb) : "l"(sm));
    int tid = threadIdx.x;
    int bid = blockIdx.x;
    int grp = bid >> 6;
    int lb  = bid & 63;
    unsigned sense = 0;

    for (int g = bid * NT + tid; g < Bsz * Hdim; g += NB * NT) {
        g_h1a[g] = 0.f; g_h1b[g] = 0.f; g_h2a[g] = 0.f; g_h2b[g] = 0.f;
        g_c1[g] = 0.f;  g_c2[g] = 0.f;
    }
    {
        int t = bid;
        for (int idx = tid; idx < Bsz * Hdim; idx += NT) {
            int b = idx >> 10, k = idx & 1023;
            int id = seq[b * Tlen + t];
            g_XT[((size_t)t * Bsz + b) * Hdim + k] = emb[(size_t)id * Hdim + k];
        }
    }
    grid_barrier(sense);

    const size_t MW = (size_t)Hdim * Hdim;
    for (int p = 0; p <= Tlen; p++) {
        bool Aact = (grp == 0) && (p < Tlen);
        bool Bact = (grp == 1) && (p >= 1);
        int t2 = p - 1;

        const float* A_x = g_XT + (size_t)p * Bsz * Hdim;
        float* A_hs = (p & 1) ? g_h1b : g_h1a;
        float* A_hd = (p & 1) ? g_h1a : g_h1b;
        const float* B_x = (t2 & 1) ? g_h1a : g_h1b;
        float* B_hs = (t2 & 1) ? g_h2b : g_h2a;
        float* B_hd = (t2 & 1) ? g_h2a : g_h2b;

        const float* AsS[5] = { A_hs, g_xA1, g_hA1, g_xB1, g_hB1 };
        const float* AsM[5] = { A_x,  A_hs,  g_xA1, g_hA1, g_xB1 };
        float*       AsD[5] = { g_xA1, g_hA1, g_xB1, g_hB1, g_xA1 };
        const float* BsS[5] = { B_hs, g_xA2, g_hA2, g_xB2, g_hB2 };
        const float* BsM[5] = { B_x,  B_hs,  g_xA2, g_hA2, g_xB2 };
        float*       BsD[5] = { g_xA2, g_hA2, g_xB2, g_hB2, g_xA2 };

        for (int i = 0; i < 5; i++) {
            if (Aact)
                mog_stage(g_wh + WOFF_M1 + (size_t)i * MW, g_wl + WOFF_M1 + (size_t)i * MW,
                          m1b + i * Hdim, AsS[i], AsM[i], AsD[i], lb, sm, smb);
            else if (Bact)
                mog_stage(g_wh + WOFF_M2 + (size_t)i * MW, g_wl + WOFF_M2 + (size_t)i * MW,
                          m2b + i * Hdim, BsS[i], BsM[i], BsD[i], lb, sm, smb);
            grid_barrier(sense);
        }
        if (Aact)
            gate_stage(g_wh + WOFF_G1IH, g_wl + WOFF_G1IH,
                       g_wh + WOFF_G1HH, g_wl + WOFF_G1HH,
                       b1ih, b1hh, g_xA1, g_hB1, g_c1, A_hd, nullptr, p, lb, sm, smb);
        else if (Bact)
            gate_stage(g_wh + WOFF_G2IH, g_wl + WOFF_G2IH,
                       g_wh + WOFF_G2HH, g_wl + WOFF_G2HH,
                       b2ih, b2hh, g_xA2, g_hB2, g_c2, B_hd, hidp, t2, lb, sm, smb);
        grid_barrier(sense);
    }
    grid_barrier(sense);   // total = 1 + 129*6 + 1 = 776 (even: sense restored)
}

// ================= bf16 hi/lo split =================
__global__ void split_bf16_kernel(const float* __restrict__ src,
                                  __nv_bfloat16* __restrict__ hi,
                                  __nv_bfloat16* __restrict__ lo, size_t n4)
{
    for (size_t i = blockIdx.x * blockDim.x + threadIdx.x; i < n4;
         i += (size_t)gridDim.x * blockDim.x) {
        float4 v = *(const float4*)(src + i * 4);
        __nv_bfloat16 h0 = __float2bfloat16_rn(v.x);
        __nv_bfloat16 h1 = __float2bfloat16_rn(v.y);
        __nv_bfloat16 h2 = __float2bfloat16_rn(v.z);
        __nv_bfloat16 h3 = __float2bfloat16_rn(v.w);
        __nv_bfloat16 l0 = __float2bfloat16_rn(v.x - __bfloat162float(h0));
        __nv_bfloat16 l1 = __float2bfloat16_rn(v.y - __bfloat162float(h1));
        __nv_bfloat16 l2 = __float2bfloat16_rn(v.z - __bfloat162float(h2));
        __nv_bfloat16 l3 = __float2bfloat16_rn(v.w - __bfloat162float(h3));
        __nv_bfloat162* hp = (__nv_bfloat162*)(hi + i * 4);
        __nv_bfloat162* lp = (__nv_bfloat162*)(lo + i * 4);
        hp[0] = __nv_bfloat162(h0, h1);
        hp[1] = __nv_bfloat162(h2, h3);
        lp[0] = __nv_bfloat162(l0, l1);
        lp[1] = __nv_bfloat162(l2, l3);
    }
}

// ================= bf16x3 legacy-mma logits GEMM (unchanged, passing) =================
#define GTS 72
#define G_SMEM_BYTES (4 * 128 * GTS * 2)

__global__ __launch_bounds__(256, 2) void gemm_bf16x3_bias(
    const float* __restrict__ bias, float* __restrict__ C)
{
    extern __shared__ __nv_bfloat16 gs[];
    __nv_bfloat16* Ahs = gs;
    __nv_bfloat16* Als = Ahs + 128 * GTS;
    __nv_bfloat16* Bhs = Als + 128 * GTS;
    __nv_bfloat16* Bls = Bhs + 128 * GTS;

    int tid = threadIdx.x;
    int lane = tid & 31, wrp = tid >> 5;
    int wm = wrp & 1, wn = wrp >> 1;
    int gr = lane >> 2, tig = lane & 3;
    int m0 = blockIdx.x * 128;
    int n0 = blockIdx.y * 128;

    const __nv_bfloat16* Ahg = g_hidh + (size_t)m0 * Hdim;
    const __nv_bfloat16* Alg = g_hidl + (size_t)m0 * Hdim;
    const __nv_bfloat16* Bhg = g_embh + (size_t)n0 * Hdim;
    const __nv_bfloat16* Blg = g_embl + (size_t)n0 * Hdim;

    float acc[4][4][4];
#pragma unroll
    for (int i = 0; i < 4; i++)
#pragma unroll
        for (int j = 0; j < 4; j++)
#pragma unroll
            for (int q = 0; q < 4; q++) acc[i][j][q] = 0.f;

    for (int kc = 0; kc < Hdim; kc += 64) {
        __syncthreads();
#pragma unroll
        for (int i = 0; i < 4; i++) {
            int idx = tid + i * 256;
            int r = idx >> 3, u = idx & 7;
            int so = r * GTS + u * 8;
            size_t go = (size_t)r * Hdim + kc + u * 8;
            *(uint4*)&Ahs[so] = *(const uint4*)&Ahg[go];
            *(uint4*)&Als[so] = *(const uint4*)&Alg[go];
            *(uint4*)&Bhs[so] = *(const uint4*)&Bhg[go];
            *(uint4*)&Bls[so] = *(const uint4*)&Blg[go];
        }
        __syncthreads();

#pragma unroll
        for (int ks = 0; ks < 4; ks++) {
            int kb = ks * 16;
            uint32_t ah[4][4], al[4][4], bh[4][2], bl[4][2];
#pragma unroll
            for (int mf = 0; mf < 4; mf++) {
                int base = (wm * 64 + mf * 16 + gr) * GTS + kb + 2 * tig;
                ah[mf][0] = *(const uint32_t*)&Ahs[base];
                ah[mf][1] = *(const uint32_t*)&Ahs[base + 8 * GTS];
                ah[mf][2] = *(const uint32_t*)&Ahs[base + 8];
                ah[mf][3] = *(const uint32_t*)&Ahs[base + 8 * GTS + 8];
                al[mf][0] = *(const uint32_t*)&Als[base];
                al[mf][1] = *(const uint32_t*)&Als[base + 8 * GTS];
                al[mf][2] = *(const uint32_t*)&Als[base + 8];
                al[mf][3] = *(const uint32_t*)&Als[base + 8 * GTS + 8];
            }
#pragma unroll
            for (int nf = 0; nf < 4; nf++) {
                int base = (wn * 32 + nf * 8 + gr) * GTS + kb + 2 * tig;
                bh[nf][0] = *(const uint32_t*)&Bhs[base];
                bh[nf][1] = *(const uint32_t*)&Bhs[base + 8];
                bl[nf][0] = *(const uint32_t*)&Bls[base];
                bl[nf][1] = *(const uint32_t*)&Bls[base + 8];
            }
#pragma unroll
            for (int mf = 0; mf < 4; mf++)
#pragma unroll
                for (int nf = 0; nf < 4; nf++) {
                    mma_bf16(acc[mf][nf], ah[mf], bh[nf]);
                    mma_bf16(acc[mf][nf], al[mf], bh[nf]);
                    mma_bf16(acc[mf][nf], ah[mf], bl[nf]);
                }
        }
    }

#pragma unroll
    for (int nf = 0; nf < 4; nf++) {
        int col = n0 + wn * 32 + nf * 8 + 2 * tig;
        float bv0 = bias[col], bv1 = bias[col + 1];
#pragma unroll
        for (int mf = 0; mf < 4; mf++) {
            int row = m0 + wm * 64 + mf * 16 + gr;
            float2 v0 = make_float2(acc[mf][nf][0] + bv0, acc[mf][nf][1] + bv1);
            float2 v1 = make_float2(acc[mf][nf][2] + bv0, acc[mf][nf][3] + bv1);
            *(float2*)&C[(size_t)row * Vsz + col] = v0;
            *(float2*)&C[(size_t)(row + 8) * Vsz + col] = v1;
        }
    }
}

// ---------------- host ----------------
extern "C" void kernel_launch(void* const* d_in, const int* in_sizes, int n_in,
                              void* d_out, int out_size) {
    (void)in_sizes; (void)out_size;
    const int* seq = (const int*)d_in[0];
    int o = n_in - 14;
    const float* emb  = (const float*)d_in[o + 0];
    const float* fc_b = (const float*)d_in[o + 1];
    const float* m1w  = (const float*)d_in[o + 2];
    const float* m1b  = (const float*)d_in[o + 3];
    const float* w1ih = (const float*)d_in[o + 4];
    const float* w1hh = (const float*)d_in[o + 5];
    const float* b1ih = (const float*)d_in[o + 6];
    const float* b1hh = (const float*)d_in[o + 7];
    const float* m2w  = (const float*)d_in[o + 8];
    const float* m2b  = (const float*)d_in[o + 9];
    const float* w2ih = (const float*)d_in[o + 10];
    const float* w2hh = (const float*)d_in[o + 11];
    const float* b2ih = (const float*)d_in[o + 12];
    const float* b2hh = (const float*)d_in[o + 13];

    float* outp = (float*)d_out;                          // [B][T][V]
    float* hidp = outp + (size_t)Bsz * Tlen * Vsz;        // [B][T][H]

    __nv_bfloat16 *embh, *embl, *hidh, *hidl, *wh, *wl;
    cudaGetSymbolAddress((void**)&embh, g_embh);
    cudaGetSymbolAddress((void**)&embl, g_embl);
    cudaGetSymbolAddress((void**)&hidh, g_hidh);
    cudaGetSymbolAddress((void**)&hidl, g_hidl);
    cudaGetSymbolAddress((void**)&wh, g_wh);
    cudaGetSymbolAddress((void**)&wl, g_wl);

    cudaFuncSetAttribute(mog_lstm_kernel,
                         cudaFuncAttributeMaxDynamicSharedMemorySize, R_SMEM_BYTES);
    cudaFuncSetAttribute(gemm_bf16x3_bias,
                         cudaFuncAttributeMaxDynamicSharedMemorySize, G_SMEM_BYTES);

    // split weights into bf16 hi/lo arena
    split_bf16_kernel<<<512, 256>>>(m1w,  wh + WOFF_M1,   wl + WOFF_M1,   (size_t)5 * Hdim * Hdim / 4);
    split_bf16_kernel<<<512, 256>>>(m2w,  wh + WOFF_M2,   wl + WOFF_M2,   (size_t)5 * Hdim * Hdim / 4);
    split_bf16_kernel<<<512, 256>>>(w1ih, wh + WOFF_G1IH, wl + WOFF_G1IH, (size_t)4 * Hdim * Hdim / 4);
    split_bf16_kernel<<<512, 256>>>(w1hh, wh + WOFF_G1HH, wl + WOFF_G1HH, (size_t)4 * Hdim * Hdim / 4);
    split_bf16_kernel<<<512, 256>>>(w2ih, wh + WOFF_G2IH, wl + WOFF_G2IH, (size_t)4 * Hdim * Hdim / 4);
    split_bf16_kernel<<<512, 256>>>(w2hh, wh + WOFF_G2HH, wl + WOFF_G2HH, (size_t)4 * Hdim * Hdim / 4);

    // split embedding (independent of recurrence result)
    split_bf16_kernel<<<2048, 256>>>(emb, embh, embl, (size_t)Vsz * Hdim / 4);

    mog_lstm_kernel<<<NB, NT, R_SMEM_BYTES>>>(seq, emb,
                                              m1b, b1ih, b1hh, m2b, b2ih, b2hh, hidp);

    // split hidden states produced by the recurrence
    split_bf16_kernel<<<1024, 256>>>(hidp, hidh, hidl, (size_t)Bsz * Tlen * Hdim / 4);

    gemm_bf16x3_bias<<<dim3((Bsz * Tlen) / 128, Vsz / 128), 256, G_SMEM_BYTES>>>(fc_b, outp);
}